// round 1
// baseline (speedup 1.0000x reference)
#include <cuda_runtime.h>
#include <cuda_bf16.h>
#include <cstddef>

// ---------------------------------------------------------------------------
// MultiHeadAttention: y = proj( causal_attention( x @ W_attn + b_attn ) )
// B=8, T=1024, C=768, H=12, hd=64
// ---------------------------------------------------------------------------

#define B_  8
#define T_  1024
#define C_  768
#define H_  12
#define HD_ 64
#define M_ROWS (B_ * T_)          // 8192
#define QKV_N  (3 * C_)           // 2304

// Scratch (device globals; no allocation allowed)
__device__ float g_q[B_ * H_ * T_ * HD_];   // [B,H,T,hd]
__device__ float g_k[B_ * H_ * T_ * HD_];
__device__ float g_v[B_ * H_ * T_ * HD_];
__device__ float g_y[M_ROWS * C_];          // attention output in [B,T,C]

// ---------------------------------------------------------------------------
// Classic 128x128x16 fp32 SGEMM, 256 threads, 8x8 register tile.
// EPI==0: C = x@W_attn + b_attn, scattered into g_q/g_k/g_v ([B,H,T,hd]).
// EPI==1: C = g_y@W_proj + b_proj -> out ([B,T,C] row-major).
// Assumes M%128==0, N%128==0, K%16==0 (true for all shapes here).
// ---------------------------------------------------------------------------
template <int EPI>
__global__ __launch_bounds__(256, 2)
void sgemm128(const float* __restrict__ A, const float* __restrict__ Bm,
              const float* __restrict__ bias, float* __restrict__ C,
              int M, int N, int K)
{
    __shared__ float As[16][128];
    __shared__ float Bs[16][128];

    const int t  = threadIdx.x;
    const int bx = blockIdx.x;     // N tile
    const int by = blockIdx.y;     // M tile
    const int tx = t & 15;
    const int ty = t >> 4;

    const float* Ap = (EPI == 1) ? (const float*)g_y : A;
    const float* Ab = Ap + (size_t)(by * 128) * K;
    const float* Bb = Bm + bx * 128;

    float acc[8][8];
#pragma unroll
    for (int i = 0; i < 8; i++)
#pragma unroll
        for (int j = 0; j < 8; j++) acc[i][j] = 0.f;

    for (int kk = 0; kk < K; kk += 16) {
#pragma unroll
        for (int i = 0; i < 2; i++) {
            int id = t + i * 256;
            // A tile load (transpose into As[k][m])
            int arow = id >> 2;
            int ac   = (id & 3) << 2;
            float4 av = *(const float4*)&Ab[(size_t)arow * K + kk + ac];
            As[ac + 0][arow] = av.x;
            As[ac + 1][arow] = av.y;
            As[ac + 2][arow] = av.z;
            As[ac + 3][arow] = av.w;
            // B tile load (direct)
            int brow = id >> 5;
            int bc   = (id & 31) << 2;
            *(float4*)&Bs[brow][bc] =
                *(const float4*)&Bb[(size_t)(kk + brow) * N + bc];
        }
        __syncthreads();

#pragma unroll
        for (int k = 0; k < 16; k++) {
            float ar[8], br[8];
            *(float4*)&ar[0] = *(float4*)&As[k][ty * 8];
            *(float4*)&ar[4] = *(float4*)&As[k][ty * 8 + 4];
            *(float4*)&br[0] = *(float4*)&Bs[k][tx * 8];
            *(float4*)&br[4] = *(float4*)&Bs[k][tx * 8 + 4];
#pragma unroll
            for (int i = 0; i < 8; i++)
#pragma unroll
                for (int j = 0; j < 8; j++)
                    acc[i][j] += ar[i] * br[j];
        }
        __syncthreads();
    }

    // Epilogue
#pragma unroll
    for (int i = 0; i < 8; i++) {
        int m = by * 128 + ty * 8 + i;
#pragma unroll
        for (int j = 0; j < 8; j++) {
            int c = bx * 128 + tx * 8 + j;
            float v = acc[i][j] + bias[c];
            if (EPI == 0) {
                int which = c / C_;
                int cc    = c - which * C_;
                int h     = cc >> 6;      // /64
                int d     = cc & 63;
                int b     = m >> 10;      // /1024
                int tt    = m & 1023;
                float* dst = (which == 0) ? g_q : ((which == 1) ? g_k : g_v);
                dst[((size_t)(b * H_ + h) * T_ + tt) * HD_ + d] = v;
            } else {
                C[(size_t)m * N + c] = v;
            }
        }
    }
}

// ---------------------------------------------------------------------------
// Flash-style causal attention. One block per (q-tile of 64 rows, b*h).
// 256 threads. Online softmax over 64-wide K/V tiles. fp32 accumulators.
// Writes O directly into g_y in [B,T,C] layout (undoing the head transpose).
// ---------------------------------------------------------------------------
#define APAD 68   // padded row stride (floats) for 64-wide tiles

__global__ __launch_bounds__(256)
void attn_kernel()
{
    extern __shared__ float sm[];
    float* Qs = sm;                       // 64 x APAD
    float* Ks = Qs + 64 * APAD;
    float* Vs = Ks + 64 * APAD;
    float* Ps = Vs + 64 * APAD;
    float* ms = Ps + 64 * APAD;           // row max
    float* ls = ms + 64;                  // row sum
    float* al = ls + 64;                  // row alpha (rescale)

    const int t  = threadIdx.x;
    const int qt = blockIdx.x;            // 0..15
    const int bh = blockIdx.y;            // 0..95
    const size_t base = (size_t)bh * T_ * HD_;
    const int q0 = qt * 64;

    // Load Q tile (64 x 64)
    for (int i = t; i < 64 * 16; i += 256) {
        int r  = i >> 4;
        int c4 = (i & 15) << 2;
        *(float4*)&Qs[r * APAD + c4] =
            *(const float4*)&g_q[base + (size_t)(q0 + r) * HD_ + c4];
    }
    if (t < 64) { ms[t] = -1e30f; ls[t] = 0.f; }

    float acc[16];
#pragma unroll
    for (int i = 0; i < 16; i++) acc[i] = 0.f;
    __syncthreads();

    const int rg = t >> 4;       // row group for S compute (4 rows)
    const int cg = t & 15;       // col group (4 cols)
    const int r  = t & 63;       // row for O update
    const int dg = (t >> 6) << 4; // 16-wide d slice

    for (int kt = 0; kt <= qt; kt++) {
        const int k0 = kt * 64;
        // Load K and V tiles
        for (int i = t; i < 64 * 16; i += 256) {
            int rr = i >> 4;
            int c4 = (i & 15) << 2;
            *(float4*)&Ks[rr * APAD + c4] =
                *(const float4*)&g_k[base + (size_t)(k0 + rr) * HD_ + c4];
            *(float4*)&Vs[rr * APAD + c4] =
                *(const float4*)&g_v[base + (size_t)(k0 + rr) * HD_ + c4];
        }
        __syncthreads();

        // S = Q K^T  (each thread: 4x4 block)
        float s[4][4];
#pragma unroll
        for (int ii = 0; ii < 4; ii++)
#pragma unroll
            for (int jj = 0; jj < 4; jj++) s[ii][jj] = 0.f;

#pragma unroll
        for (int d = 0; d < 64; d += 4) {
            float4 qv[4], kv[4];
#pragma unroll
            for (int ii = 0; ii < 4; ii++)
                qv[ii] = *(const float4*)&Qs[(rg * 4 + ii) * APAD + d];
#pragma unroll
            for (int jj = 0; jj < 4; jj++)
                kv[jj] = *(const float4*)&Ks[(cg * 4 + jj) * APAD + d];
#pragma unroll
            for (int ii = 0; ii < 4; ii++)
#pragma unroll
                for (int jj = 0; jj < 4; jj++)
                    s[ii][jj] += qv[ii].x * kv[jj].x + qv[ii].y * kv[jj].y +
                                 qv[ii].z * kv[jj].z + qv[ii].w * kv[jj].w;
        }

        // scale + causal mask + store to Ps
#pragma unroll
        for (int ii = 0; ii < 4; ii++) {
            int qi = q0 + rg * 4 + ii;
#pragma unroll
            for (int jj = 0; jj < 4; jj++) {
                int ki = k0 + cg * 4 + jj;
                float v = s[ii][jj] * 0.125f;    // 1/sqrt(64)
                if (ki > qi) v = -1e30f;
                Ps[(rg * 4 + ii) * APAD + cg * 4 + jj] = v;
            }
        }
        __syncthreads();

        // Online softmax (one thread per row)
        if (t < 64) {
            float mo = ms[t];
            float mx = mo;
            for (int j = 0; j < 64; j++) mx = fmaxf(mx, Ps[t * APAD + j]);
            float a = __expf(mo - mx);
            float sum = 0.f;
            for (int j = 0; j < 64; j++) {
                float p = __expf(Ps[t * APAD + j] - mx);
                Ps[t * APAD + j] = p;
                sum += p;
            }
            ls[t] = ls[t] * a + sum;
            ms[t] = mx;
            al[t] = a;
        }
        __syncthreads();

        // O update: acc = acc*alpha + P @ V
        float a = al[r];
#pragma unroll
        for (int i = 0; i < 16; i++) acc[i] *= a;
        for (int j = 0; j < 64; j++) {
            float p = Ps[r * APAD + j];
            const float4* vp = (const float4*)&Vs[j * APAD + dg];
            float4 v0 = vp[0], v1 = vp[1], v2 = vp[2], v3 = vp[3];
            acc[0]  += p * v0.x; acc[1]  += p * v0.y; acc[2]  += p * v0.z; acc[3]  += p * v0.w;
            acc[4]  += p * v1.x; acc[5]  += p * v1.y; acc[6]  += p * v1.z; acc[7]  += p * v1.w;
            acc[8]  += p * v2.x; acc[9]  += p * v2.y; acc[10] += p * v2.z; acc[11] += p * v2.w;
            acc[12] += p * v3.x; acc[13] += p * v3.y; acc[14] += p * v3.z; acc[15] += p * v3.w;
        }
        __syncthreads();
    }

    // Finalize and write into g_y ([B,T,C], merging heads)
    float inv = 1.0f / ls[r];
    int b = bh / H_;
    int h = bh - b * H_;
    size_t orow = ((size_t)b * T_ + q0 + r) * C_ + h * HD_ + dg;
    float4 o;
    o.x = acc[0] * inv;  o.y = acc[1] * inv;  o.z = acc[2] * inv;  o.w = acc[3] * inv;
    *(float4*)&g_y[orow + 0] = o;
    o.x = acc[4] * inv;  o.y = acc[5] * inv;  o.z = acc[6] * inv;  o.w = acc[7] * inv;
    *(float4*)&g_y[orow + 4] = o;
    o.x = acc[8] * inv;  o.y = acc[9] * inv;  o.z = acc[10] * inv; o.w = acc[11] * inv;
    *(float4*)&g_y[orow + 8] = o;
    o.x = acc[12] * inv; o.y = acc[13] * inv; o.z = acc[14] * inv; o.w = acc[15] * inv;
    *(float4*)&g_y[orow + 12] = o;
}

// ---------------------------------------------------------------------------
extern "C" void kernel_launch(void* const* d_in, const int* in_sizes, int n_in,
                              void* d_out, int out_size)
{
    (void)in_sizes; (void)n_in; (void)out_size;
    const float* x      = (const float*)d_in[0];
    const float* W_attn = (const float*)d_in[1];
    const float* b_attn = (const float*)d_in[2];
    const float* W_proj = (const float*)d_in[3];
    const float* b_proj = (const float*)d_in[4];
    float* out = (float*)d_out;

    // 1) QKV GEMM + bias + scatter to [B,H,T,hd]
    sgemm128<0><<<dim3(QKV_N / 128, M_ROWS / 128), 256>>>(
        x, W_attn, b_attn, nullptr, M_ROWS, QKV_N, C_);

    // 2) Causal flash attention -> g_y [B,T,C]
    const int ATT_SMEM = (4 * 64 * APAD + 3 * 64) * (int)sizeof(float);
    cudaFuncSetAttribute(attn_kernel,
                         cudaFuncAttributeMaxDynamicSharedMemorySize, ATT_SMEM);
    attn_kernel<<<dim3(T_ / 64, B_ * H_), 256, ATT_SMEM>>>();

    // 3) Output projection
    sgemm128<1><<<dim3(C_ / 128, M_ROWS / 128), 256>>>(
        nullptr, W_proj, b_proj, out, M_ROWS, C_, C_);
}

// round 3
// speedup vs baseline: 1.3407x; 1.3407x over previous
#include <cuda_runtime.h>
#include <cuda_bf16.h>
#include <cstdint>
#include <cstddef>

// ---------------------------------------------------------------------------
// MultiHeadAttention: y = proj( causal_attention( x @ W_attn + b_attn ) )
// B=8, T=1024, C=768, H=12, hd=64
// GEMMs on HMMA (mma.sync bf16, hi/lo split -> ~fp32 accuracy).
// Attention fp32 SIMT (round-1 proven).
// ---------------------------------------------------------------------------

#define B_  8
#define T_  1024
#define C_  768
#define H_  12
#define HD_ 64
#define M_ROWS (B_ * T_)          // 8192
#define QKV_N  (3 * C_)           // 2304
#define K_     C_                 // 768

// ---------------- device scratch (no allocation allowed) -------------------
__device__ float g_q[B_ * H_ * T_ * HD_];   // [B,H,T,hd]
__device__ float g_k[B_ * H_ * T_ * HD_];
__device__ float g_v[B_ * H_ * T_ * HD_];
__device__ float g_y[M_ROWS * C_];          // attention output [B,T,C]

__device__ __nv_bfloat16 g_xhi[M_ROWS * K_], g_xlo[M_ROWS * K_];
__device__ __nv_bfloat16 g_yhi[M_ROWS * K_], g_ylo[M_ROWS * K_];
__device__ __nv_bfloat16 g_wahi[QKV_N * K_], g_walo[QKV_N * K_];   // W_attn^T [N,K]
__device__ __nv_bfloat16 g_wphi[C_ * K_],    g_wplo[C_ * K_];      // W_proj^T [N,K]

// ---------------- small PTX helpers (sm_80-level only) ---------------------
__device__ __forceinline__ uint32_t smem_to_u32(const void* p) {
    uint32_t a;
    asm("{ .reg .u64 t; cvta.to.shared.u64 t, %1; cvt.u32.u64 %0, t; }"
        : "=r"(a) : "l"(p));
    return a;
}
__device__ __forceinline__ void ldm_x4(uint32_t* r, uint32_t addr) {
    asm volatile("ldmatrix.sync.aligned.m8n8.x4.shared.b16 {%0,%1,%2,%3}, [%4];"
                 : "=r"(r[0]), "=r"(r[1]), "=r"(r[2]), "=r"(r[3]) : "r"(addr));
}
__device__ __forceinline__ void mma16816(float* d, const uint32_t* a,
                                         uint32_t b0, uint32_t b1) {
    asm volatile(
        "mma.sync.aligned.m16n8k16.row.col.f32.bf16.bf16.f32 "
        "{%0,%1,%2,%3}, {%4,%5,%6,%7}, {%8,%9}, {%0,%1,%2,%3};"
        : "+f"(d[0]), "+f"(d[1]), "+f"(d[2]), "+f"(d[3])
        : "r"(a[0]), "r"(a[1]), "r"(a[2]), "r"(a[3]), "r"(b0), "r"(b1));
}

// ---------------------------------------------------------------------------
// Split / conversion kernels (fp32 -> bf16 hi + bf16 lo residual)
// ---------------------------------------------------------------------------
__global__ void split_x_kernel(const float* __restrict__ s) {
    int i = blockIdx.x * 256 + threadIdx.x;
    float a = s[i];
    __nv_bfloat16 h = __float2bfloat16(a);
    g_xhi[i] = h;
    g_xlo[i] = __float2bfloat16(a - __bfloat162float(h));
}
__global__ void split_y_kernel() {
    int i = blockIdx.x * 256 + threadIdx.x;
    float a = g_y[i];
    __nv_bfloat16 h = __float2bfloat16(a);
    g_yhi[i] = h;
    g_ylo[i] = __float2bfloat16(a - __bfloat162float(h));
}
// transpose [K,N] fp32 -> [N,K] bf16 hi/lo
template <int W>
__global__ void split_tr_kernel(const float* __restrict__ s, int Kd, int Nd) {
    __shared__ float t[32][33];
    int nb = blockIdx.x * 32, kb = blockIdx.y * 32;
    int tx = threadIdx.x & 31, ty = threadIdx.x >> 5;   // 32 x 8
    for (int r = ty; r < 32; r += 8)
        t[r][tx] = s[(size_t)(kb + r) * Nd + nb + tx];
    __syncthreads();
    __nv_bfloat16* hi = W ? g_wphi : g_wahi;
    __nv_bfloat16* lo = W ? g_wplo : g_walo;
    for (int r = ty; r < 32; r += 8) {
        float a = t[tx][r];
        __nv_bfloat16 h = __float2bfloat16(a);
        size_t o = (size_t)(nb + r) * Kd + kb + tx;
        hi[o] = h;
        lo[o] = __float2bfloat16(a - __bfloat162float(h));
    }
}

// ---------------------------------------------------------------------------
// HMMA bf16 hi/lo GEMM: C[M, N] = A[M,768] * W[768,N] + bias
//   A: [M,K] bf16 hi/lo     Wt: [N,K] bf16 hi/lo (pre-transposed)
// CTA tile 128x128, K-chunk 32, 8 warps in 4(m) x 2(n); warp tile 32x64.
// SMEM holds 16x16 bf16 subtiles contiguously (512B each) -> conflict-free
// ldmatrix. Register-staged double buffering.
// EPI==0: scatter q/k/v.  EPI==1: row-major out.
// ---------------------------------------------------------------------------
#define KCH    32
#define NKCH   (K_ / KCH)          // 24
#define REGION 8192                // one 128x32 bf16 tile as subtiles
#define BUFB   (4 * REGION)        // Ah, Al, Bh, Bl
#define SMEM_HG (2 * BUFB)         // 64 KB

template <int EPI>
__global__ __launch_bounds__(256)
void hgemm(const float* __restrict__ bias, float* __restrict__ Cout, int N)
{
    extern __shared__ char smem[];
    const uint32_t sb = smem_to_u32(smem);
    const int tid  = threadIdx.x;
    const int lane = tid & 31;
    const int w    = tid >> 5;
    const int mw   = w & 3;        // 0..3 -> m32
    const int nw   = w >> 2;       // 0..1 -> n64
    const int n0 = blockIdx.x * 128;
    const int m0 = blockIdx.y * 128;

    const __nv_bfloat16* Ahi = (EPI == 0) ? g_xhi : g_yhi;
    const __nv_bfloat16* Alo = (EPI == 0) ? g_xlo : g_ylo;
    const __nv_bfloat16* Bhi = (EPI == 0) ? g_wahi : g_wphi;
    const __nv_bfloat16* Blo = (EPI == 0) ? g_walo : g_wplo;

    float acc[2][8][4];
#pragma unroll
    for (int i = 0; i < 2; i++)
#pragma unroll
        for (int j = 0; j < 8; j++)
#pragma unroll
            for (int q = 0; q < 4; q++) acc[i][j][q] = 0.f;

    // per-thread global-load descriptors: 8 x uint4 per chunk
    // q -> tile (q>>1): 0=Ahi 1=Alo 2=Bhi 3=Blo ; idx = (q&1)*256+tid
    uint4 stage[8];

    auto load_chunk = [&](int c) {
        const int kk = c * KCH;
#pragma unroll
        for (int q = 0; q < 8; q++) {
            const int tile = q >> 1;
            const int idx  = ((q & 1) << 8) + tid;   // 0..511
            const int r = idx >> 2;                  // 0..127
            const int u = idx & 3;                   // col = 8u
            const __nv_bfloat16* src =
                (tile == 0) ? Ahi : (tile == 1) ? Alo : (tile == 2) ? Bhi : Blo;
            const int g0 = (tile < 2) ? m0 : n0;
            stage[q] = *(const uint4*)(src + (size_t)(g0 + r) * K_ + kk + u * 8);
        }
    };
    auto store_chunk = [&](int buf) {
#pragma unroll
        for (int q = 0; q < 8; q++) {
            const int tile = q >> 1;
            const int idx  = ((q & 1) << 8) + tid;
            const int r = idx >> 2;
            const int u = idx & 3;
            // subtile (r/16, u/2), inner (r%16, (u&1)*8)
            uint32_t off = buf * BUFB + tile * REGION +
                           (((r >> 4) << 1) + (u >> 1)) * 512 +
                           (r & 15) * 32 + (u & 1) * 16;
            *(uint4*)(smem + off) = stage[q];
        }
    };

    // ldmatrix lane addressing (within a 16x16 subtile, 512B)
    const uint32_t a_in = (lane & 15) * 32 + (lane >> 4) * 16;
    const uint32_t b_in = ((lane & 7) + (lane >> 4) * 8) * 32 + ((lane >> 3) & 1) * 16;

    auto compute_chunk = [&](int buf) {
        const uint32_t base = sb + buf * BUFB;
#pragma unroll
        for (int kc = 0; kc < 2; kc++) {
            uint32_t af[2][2][4];   // [hl][mt][4]
#pragma unroll
            for (int hl = 0; hl < 2; hl++)
#pragma unroll
                for (int mt = 0; mt < 2; mt++) {
                    uint32_t addr = base + hl * REGION +
                                    (((mw * 2 + mt) << 1) + kc) * 512 + a_in;
                    ldm_x4(af[hl][mt], addr);
                }
            uint32_t bfq[2][4][4];  // [hl][nt16][4] (two n8 tiles per x4)
#pragma unroll
            for (int hl = 0; hl < 2; hl++)
#pragma unroll
                for (int nt = 0; nt < 4; nt++) {
                    uint32_t addr = base + (2 + hl) * REGION +
                                    (((nw * 4 + nt) << 1) + kc) * 512 + b_in;
                    ldm_x4(bfq[hl][nt], addr);
                }
#pragma unroll
            for (int mt = 0; mt < 2; mt++)
#pragma unroll
                for (int nt = 0; nt < 4; nt++)
#pragma unroll
                    for (int hf = 0; hf < 2; hf++) {
                        float* d = acc[mt][nt * 2 + hf];
                        mma16816(d, af[0][mt], bfq[0][nt][hf * 2], bfq[0][nt][hf * 2 + 1]);
                        mma16816(d, af[0][mt], bfq[1][nt][hf * 2], bfq[1][nt][hf * 2 + 1]);
                        mma16816(d, af[1][mt], bfq[0][nt][hf * 2], bfq[0][nt][hf * 2 + 1]);
                    }
        }
    };

    load_chunk(0);
    store_chunk(0);
    __syncthreads();

    for (int c = 0; c < NKCH; c++) {
        if (c + 1 < NKCH) load_chunk(c + 1);
        compute_chunk(c & 1);
        if (c + 1 < NKCH) {
            store_chunk((c + 1) & 1);
            __syncthreads();
        }
    }

    // epilogue
    const int row_in = lane >> 2;
    const int col_in = (lane & 3) * 2;
#pragma unroll
    for (int mt = 0; mt < 2; mt++) {
#pragma unroll
        for (int nt = 0; nt < 8; nt++) {
            const int c = n0 + nw * 64 + nt * 8 + col_in;
            const float b0v = bias[c], b1v = bias[c + 1];
#pragma unroll
            for (int hf = 0; hf < 2; hf++) {
                const int m = m0 + mw * 32 + mt * 16 + row_in + hf * 8;
                float v0 = acc[mt][nt][hf * 2 + 0] + b0v;
                float v1 = acc[mt][nt][hf * 2 + 1] + b1v;
                if (EPI == 0) {
                    int which = c / C_;
                    int cc = c - which * C_;
                    int h = cc >> 6, d = cc & 63;
                    int b = m >> 10, tt = m & 1023;
                    float* dstg = (which == 0) ? g_q : ((which == 1) ? g_k : g_v);
                    float2* p = (float2*)&dstg[((size_t)(b * H_ + h) * T_ + tt) * HD_ + d];
                    *p = make_float2(v0, v1);
                } else {
                    *(float2*)&Cout[(size_t)m * N + c] = make_float2(v0, v1);
                }
            }
        }
    }
}

// ---------------------------------------------------------------------------
// Flash-style causal attention (fp32 SIMT, round-1 proven).
// ---------------------------------------------------------------------------
#define APAD 68

__global__ __launch_bounds__(256)
void attn_kernel()
{
    extern __shared__ char s_raw[];
    float* sm = (float*)s_raw;
    float* Qs = sm;
    float* Ks = Qs + 64 * APAD;
    float* Vs = Ks + 64 * APAD;
    float* Ps = Vs + 64 * APAD;
    float* ms = Ps + 64 * APAD;
    float* ls = ms + 64;
    float* al = ls + 64;

    const int t  = threadIdx.x;
    const int qt = blockIdx.x;
    const int bh = blockIdx.y;
    const size_t base = (size_t)bh * T_ * HD_;
    const int q0 = qt * 64;

    for (int i = t; i < 64 * 16; i += 256) {
        int r  = i >> 4;
        int c4 = (i & 15) << 2;
        *(float4*)&Qs[r * APAD + c4] =
            *(const float4*)&g_q[base + (size_t)(q0 + r) * HD_ + c4];
    }
    if (t < 64) { ms[t] = -1e30f; ls[t] = 0.f; }

    float acc[16];
#pragma unroll
    for (int i = 0; i < 16; i++) acc[i] = 0.f;
    __syncthreads();

    const int rg = t >> 4;
    const int cg = t & 15;
    const int r  = t & 63;
    const int dg = (t >> 6) << 4;

    for (int kt = 0; kt <= qt; kt++) {
        const int k0 = kt * 64;
        for (int i = t; i < 64 * 16; i += 256) {
            int rr = i >> 4;
            int c4 = (i & 15) << 2;
            *(float4*)&Ks[rr * APAD + c4] =
                *(const float4*)&g_k[base + (size_t)(k0 + rr) * HD_ + c4];
            *(float4*)&Vs[rr * APAD + c4] =
                *(const float4*)&g_v[base + (size_t)(k0 + rr) * HD_ + c4];
        }
        __syncthreads();

        float s[4][4];
#pragma unroll
        for (int ii = 0; ii < 4; ii++)
#pragma unroll
            for (int jj = 0; jj < 4; jj++) s[ii][jj] = 0.f;

#pragma unroll
        for (int d = 0; d < 64; d += 4) {
            float4 qv[4], kv[4];
#pragma unroll
            for (int ii = 0; ii < 4; ii++)
                qv[ii] = *(const float4*)&Qs[(rg * 4 + ii) * APAD + d];
#pragma unroll
            for (int jj = 0; jj < 4; jj++)
                kv[jj] = *(const float4*)&Ks[(cg * 4 + jj) * APAD + d];
#pragma unroll
            for (int ii = 0; ii < 4; ii++)
#pragma unroll
                for (int jj = 0; jj < 4; jj++)
                    s[ii][jj] += qv[ii].x * kv[jj].x + qv[ii].y * kv[jj].y +
                                 qv[ii].z * kv[jj].z + qv[ii].w * kv[jj].w;
        }

#pragma unroll
        for (int ii = 0; ii < 4; ii++) {
            int qi = q0 + rg * 4 + ii;
#pragma unroll
            for (int jj = 0; jj < 4; jj++) {
                int ki = k0 + cg * 4 + jj;
                float v = s[ii][jj] * 0.125f;
                if (ki > qi) v = -1e30f;
                Ps[(rg * 4 + ii) * APAD + cg * 4 + jj] = v;
            }
        }
        __syncthreads();

        if (t < 64) {
            float mo = ms[t];
            float mx = mo;
            for (int j = 0; j < 64; j++) mx = fmaxf(mx, Ps[t * APAD + j]);
            float a = __expf(mo - mx);
            float sum = 0.f;
            for (int j = 0; j < 64; j++) {
                float p = __expf(Ps[t * APAD + j] - mx);
                Ps[t * APAD + j] = p;
                sum += p;
            }
            ls[t] = ls[t] * a + sum;
            ms[t] = mx;
            al[t] = a;
        }
        __syncthreads();

        float a = al[r];
#pragma unroll
        for (int i = 0; i < 16; i++) acc[i] *= a;
        for (int j = 0; j < 64; j++) {
            float p = Ps[r * APAD + j];
            const float4* vp = (const float4*)&Vs[j * APAD + dg];
            float4 v0 = vp[0], v1 = vp[1], v2 = vp[2], v3 = vp[3];
            acc[0]  += p * v0.x; acc[1]  += p * v0.y; acc[2]  += p * v0.z; acc[3]  += p * v0.w;
            acc[4]  += p * v1.x; acc[5]  += p * v1.y; acc[6]  += p * v1.z; acc[7]  += p * v1.w;
            acc[8]  += p * v2.x; acc[9]  += p * v2.y; acc[10] += p * v2.z; acc[11] += p * v2.w;
            acc[12] += p * v3.x; acc[13] += p * v3.y; acc[14] += p * v3.z; acc[15] += p * v3.w;
        }
        __syncthreads();
    }

    float inv = 1.0f / ls[r];
    int b = bh / H_;
    int h = bh - b * H_;
    size_t orow = ((size_t)b * T_ + q0 + r) * C_ + h * HD_ + dg;
    float4 o;
    o.x = acc[0] * inv;  o.y = acc[1] * inv;  o.z = acc[2] * inv;  o.w = acc[3] * inv;
    *(float4*)&g_y[orow + 0] = o;
    o.x = acc[4] * inv;  o.y = acc[5] * inv;  o.z = acc[6] * inv;  o.w = acc[7] * inv;
    *(float4*)&g_y[orow + 4] = o;
    o.x = acc[8] * inv;  o.y = acc[9] * inv;  o.z = acc[10] * inv; o.w = acc[11] * inv;
    *(float4*)&g_y[orow + 8] = o;
    o.x = acc[12] * inv; o.y = acc[13] * inv; o.z = acc[14] * inv; o.w = acc[15] * inv;
    *(float4*)&g_y[orow + 12] = o;
}

// ---------------------------------------------------------------------------
extern "C" void kernel_launch(void* const* d_in, const int* in_sizes, int n_in,
                              void* d_out, int out_size)
{
    (void)in_sizes; (void)n_in; (void)out_size;
    const float* x      = (const float*)d_in[0];
    const float* W_attn = (const float*)d_in[1];
    const float* b_attn = (const float*)d_in[2];
    const float* W_proj = (const float*)d_in[3];
    const float* b_proj = (const float*)d_in[4];
    float* out = (float*)d_out;

    // conversions
    split_x_kernel<<<(M_ROWS * K_) / 256, 256>>>(x);
    split_tr_kernel<0><<<dim3(QKV_N / 32, K_ / 32), 256>>>(W_attn, K_, QKV_N);
    split_tr_kernel<1><<<dim3(C_ / 32, K_ / 32), 256>>>(W_proj, K_, C_);

    // 1) QKV GEMM (HMMA) + bias + scatter to [B,H,T,hd]
    cudaFuncSetAttribute(hgemm<0>,
                         cudaFuncAttributeMaxDynamicSharedMemorySize, SMEM_HG);
    hgemm<0><<<dim3(QKV_N / 128, M_ROWS / 128), 256, SMEM_HG>>>(b_attn, nullptr, QKV_N);

    // 2) causal flash attention -> g_y [B,T,C]
    const int ATT_SMEM = (4 * 64 * APAD + 3 * 64) * (int)sizeof(float);
    cudaFuncSetAttribute(attn_kernel,
                         cudaFuncAttributeMaxDynamicSharedMemorySize, ATT_SMEM);
    attn_kernel<<<dim3(T_ / 64, B_ * H_), 256, ATT_SMEM>>>();

    // 3) output projection (HMMA)
    split_y_kernel<<<(M_ROWS * K_) / 256, 256>>>();
    cudaFuncSetAttribute(hgemm<1>,
                         cudaFuncAttributeMaxDynamicSharedMemorySize, SMEM_HG);
    hgemm<1><<<dim3(C_ / 128, M_ROWS / 128), 256, SMEM_HG>>>(b_proj, out, C_);
}

// round 4
// speedup vs baseline: 2.5929x; 1.9341x over previous
#include <cuda_runtime.h>
#include <cuda_bf16.h>
#include <cstdint>
#include <cstddef>

// ---------------------------------------------------------------------------
// MultiHeadAttention: y = proj( causal_attention( x @ W_attn + b_attn ) )
// B=8, T=1024, C=768, H=12, hd=64
// Everything on HMMA (mma.sync bf16, hi/lo split -> ~fp32 accuracy).
// ---------------------------------------------------------------------------

#define B_  8
#define T_  1024
#define C_  768
#define H_  12
#define HD_ 64
#define M_ROWS (B_ * T_)          // 8192
#define QKV_N  (3 * C_)           // 2304
#define K_     C_                 // 768

// ---------------- device scratch (no allocation allowed) -------------------
__device__ __nv_bfloat16 g_qhi[B_ * H_ * T_ * HD_], g_qlo[B_ * H_ * T_ * HD_];
__device__ __nv_bfloat16 g_khi[B_ * H_ * T_ * HD_], g_klo[B_ * H_ * T_ * HD_];
__device__ __nv_bfloat16 g_vhi[B_ * H_ * T_ * HD_], g_vlo[B_ * H_ * T_ * HD_];

__device__ __nv_bfloat16 g_xhi[M_ROWS * K_], g_xlo[M_ROWS * K_];
__device__ __nv_bfloat16 g_yhi[M_ROWS * K_], g_ylo[M_ROWS * K_];   // attn out
__device__ __nv_bfloat16 g_wahi[QKV_N * K_], g_walo[QKV_N * K_];   // W_attn^T [N,K]
__device__ __nv_bfloat16 g_wphi[C_ * K_],    g_wplo[C_ * K_];      // W_proj^T [N,K]

// ---------------- small PTX helpers (sm_80-level only) ---------------------
__device__ __forceinline__ uint32_t smem_to_u32(const void* p) {
    uint32_t a;
    asm("{ .reg .u64 t; cvta.to.shared.u64 t, %1; cvt.u32.u64 %0, t; }"
        : "=r"(a) : "l"(p));
    return a;
}
__device__ __forceinline__ void ldm_x4(uint32_t* r, uint32_t addr) {
    asm volatile("ldmatrix.sync.aligned.m8n8.x4.shared.b16 {%0,%1,%2,%3}, [%4];"
                 : "=r"(r[0]), "=r"(r[1]), "=r"(r[2]), "=r"(r[3]) : "r"(addr));
}
__device__ __forceinline__ void ldm_x4_t(uint32_t* r, uint32_t addr) {
    asm volatile("ldmatrix.sync.aligned.m8n8.x4.trans.shared.b16 {%0,%1,%2,%3}, [%4];"
                 : "=r"(r[0]), "=r"(r[1]), "=r"(r[2]), "=r"(r[3]) : "r"(addr));
}
__device__ __forceinline__ void mma16816(float* d, const uint32_t* a,
                                         uint32_t b0, uint32_t b1) {
    asm volatile(
        "mma.sync.aligned.m16n8k16.row.col.f32.bf16.bf16.f32 "
        "{%0,%1,%2,%3}, {%4,%5,%6,%7}, {%8,%9}, {%0,%1,%2,%3};"
        : "+f"(d[0]), "+f"(d[1]), "+f"(d[2]), "+f"(d[3])
        : "r"(a[0]), "r"(a[1]), "r"(a[2]), "r"(a[3]), "r"(b0), "r"(b1));
}
__device__ __forceinline__ uint32_t packbf(float lo, float hi) {
    __nv_bfloat162 t;
    t.x = __float2bfloat16(lo);
    t.y = __float2bfloat16(hi);
    return *(uint32_t*)&t;
}
#define SWZ(b) ((b) ^ (((b) >> 3) & 0x70))

// ---------------------------------------------------------------------------
// Split / conversion kernels (fp32 -> bf16 hi + bf16 lo residual)
// ---------------------------------------------------------------------------
__global__ void split_x_kernel(const float* __restrict__ s) {
    int i = blockIdx.x * 256 + threadIdx.x;
    float a = s[i];
    __nv_bfloat16 h = __float2bfloat16(a);
    g_xhi[i] = h;
    g_xlo[i] = __float2bfloat16(a - __bfloat162float(h));
}
// transpose [K,N] fp32 -> [N,K] bf16 hi/lo
template <int W>
__global__ void split_tr_kernel(const float* __restrict__ s, int Kd, int Nd) {
    __shared__ float t[32][33];
    int nb = blockIdx.x * 32, kb = blockIdx.y * 32;
    int tx = threadIdx.x & 31, ty = threadIdx.x >> 5;   // 32 x 8
    for (int r = ty; r < 32; r += 8)
        t[r][tx] = s[(size_t)(kb + r) * Nd + nb + tx];
    __syncthreads();
    __nv_bfloat16* hi = W ? g_wphi : g_wahi;
    __nv_bfloat16* lo = W ? g_wplo : g_walo;
    for (int r = ty; r < 32; r += 8) {
        float a = t[tx][r];
        __nv_bfloat16 h = __float2bfloat16(a);
        size_t o = (size_t)(nb + r) * Kd + kb + tx;
        hi[o] = h;
        lo[o] = __float2bfloat16(a - __bfloat162float(h));
    }
}

// ---------------------------------------------------------------------------
// HMMA bf16 hi/lo GEMM (round-3 proven). CTA 128x128, K-chunk 32, 8 warps.
// EPI==0: write q/k/v as bf16 hi/lo [B,H,T,hd].  EPI==1: fp32 row-major out.
// ---------------------------------------------------------------------------
#define KCH    32
#define NKCH   (K_ / KCH)          // 24
#define REGION 8192
#define BUFB   (4 * REGION)
#define SMEM_HG (2 * BUFB)         // 64 KB

template <int EPI>
__global__ __launch_bounds__(256)
void hgemm(const float* __restrict__ bias, float* __restrict__ Cout, int N)
{
    extern __shared__ char smem[];
    const uint32_t sb = smem_to_u32(smem);
    const int tid  = threadIdx.x;
    const int lane = tid & 31;
    const int w    = tid >> 5;
    const int mw   = w & 3;
    const int nw   = w >> 2;
    const int n0 = blockIdx.x * 128;
    const int m0 = blockIdx.y * 128;

    const __nv_bfloat16* Ahi = (EPI == 0) ? g_xhi : g_yhi;
    const __nv_bfloat16* Alo = (EPI == 0) ? g_xlo : g_ylo;
    const __nv_bfloat16* Bhi = (EPI == 0) ? g_wahi : g_wphi;
    const __nv_bfloat16* Blo = (EPI == 0) ? g_walo : g_wplo;

    float acc[2][8][4];
#pragma unroll
    for (int i = 0; i < 2; i++)
#pragma unroll
        for (int j = 0; j < 8; j++)
#pragma unroll
            for (int q = 0; q < 4; q++) acc[i][j][q] = 0.f;

    uint4 stage[8];
    auto load_chunk = [&](int c) {
        const int kk = c * KCH;
#pragma unroll
        for (int q = 0; q < 8; q++) {
            const int tile = q >> 1;
            const int idx  = ((q & 1) << 8) + tid;
            const int r = idx >> 2;
            const int u = idx & 3;
            const __nv_bfloat16* src =
                (tile == 0) ? Ahi : (tile == 1) ? Alo : (tile == 2) ? Bhi : Blo;
            const int g0 = (tile < 2) ? m0 : n0;
            stage[q] = *(const uint4*)(src + (size_t)(g0 + r) * K_ + kk + u * 8);
        }
    };
    auto store_chunk = [&](int buf) {
#pragma unroll
        for (int q = 0; q < 8; q++) {
            const int tile = q >> 1;
            const int idx  = ((q & 1) << 8) + tid;
            const int r = idx >> 2;
            const int u = idx & 3;
            uint32_t off = buf * BUFB + tile * REGION +
                           (((r >> 4) << 1) + (u >> 1)) * 512 +
                           (r & 15) * 32 + (u & 1) * 16;
            *(uint4*)(smem + off) = stage[q];
        }
    };

    const uint32_t a_in = (lane & 15) * 32 + (lane >> 4) * 16;
    const uint32_t b_in = ((lane & 7) + (lane >> 4) * 8) * 32 + ((lane >> 3) & 1) * 16;

    auto compute_chunk = [&](int buf) {
        const uint32_t base = sb + buf * BUFB;
#pragma unroll
        for (int kc = 0; kc < 2; kc++) {
            uint32_t af[2][2][4];
#pragma unroll
            for (int hl = 0; hl < 2; hl++)
#pragma unroll
                for (int mt = 0; mt < 2; mt++) {
                    uint32_t addr = base + hl * REGION +
                                    (((mw * 2 + mt) << 1) + kc) * 512 + a_in;
                    ldm_x4(af[hl][mt], addr);
                }
            uint32_t bfq[2][4][4];
#pragma unroll
            for (int hl = 0; hl < 2; hl++)
#pragma unroll
                for (int nt = 0; nt < 4; nt++) {
                    uint32_t addr = base + (2 + hl) * REGION +
                                    (((nw * 4 + nt) << 1) + kc) * 512 + b_in;
                    ldm_x4(bfq[hl][nt], addr);
                }
#pragma unroll
            for (int mt = 0; mt < 2; mt++)
#pragma unroll
                for (int nt = 0; nt < 4; nt++)
#pragma unroll
                    for (int hf = 0; hf < 2; hf++) {
                        float* d = acc[mt][nt * 2 + hf];
                        mma16816(d, af[0][mt], bfq[0][nt][hf * 2], bfq[0][nt][hf * 2 + 1]);
                        mma16816(d, af[0][mt], bfq[1][nt][hf * 2], bfq[1][nt][hf * 2 + 1]);
                        mma16816(d, af[1][mt], bfq[0][nt][hf * 2], bfq[0][nt][hf * 2 + 1]);
                    }
        }
    };

    load_chunk(0);
    store_chunk(0);
    __syncthreads();

    for (int c = 0; c < NKCH; c++) {
        if (c + 1 < NKCH) load_chunk(c + 1);
        compute_chunk(c & 1);
        if (c + 1 < NKCH) {
            store_chunk((c + 1) & 1);
            __syncthreads();
        }
    }

    const int row_in = lane >> 2;
    const int col_in = (lane & 3) * 2;
#pragma unroll
    for (int mt = 0; mt < 2; mt++) {
#pragma unroll
        for (int nt = 0; nt < 8; nt++) {
            const int c = n0 + nw * 64 + nt * 8 + col_in;
            const float b0v = bias[c], b1v = bias[c + 1];
#pragma unroll
            for (int hf = 0; hf < 2; hf++) {
                const int m = m0 + mw * 32 + mt * 16 + row_in + hf * 8;
                float v0 = acc[mt][nt][hf * 2 + 0] + b0v;
                float v1 = acc[mt][nt][hf * 2 + 1] + b1v;
                if (EPI == 0) {
                    int which = c / C_;
                    int cc = c - which * C_;
                    int h = cc >> 6, d = cc & 63;
                    int b = m >> 10, tt = m & 1023;
                    __nv_bfloat16* dh = (which == 0) ? g_qhi : ((which == 1) ? g_khi : g_vhi);
                    __nv_bfloat16* dl = (which == 0) ? g_qlo : ((which == 1) ? g_klo : g_vlo);
                    size_t o = ((size_t)(b * H_ + h) * T_ + tt) * HD_ + d;
                    float h0 = __bfloat162float(__float2bfloat16(v0));
                    float h1 = __bfloat162float(__float2bfloat16(v1));
                    *(uint32_t*)&dh[o] = packbf(v0, v1);
                    *(uint32_t*)&dl[o] = packbf(v0 - h0, v1 - h1);
                } else {
                    *(float2*)&Cout[(size_t)m * N + c] = make_float2(v0, v1);
                }
            }
        }
    }
}

// ---------------------------------------------------------------------------
// HMMA flash attention, causal. Grid (16 q-tiles, 96 bh), 128 threads (4 warps).
// Warp w owns query rows [16w, 16w+16). hi/lo 3-MMA for both S=QK^T and O=PV.
// SMEM: Kh 0 | Kl 8K | Vh 16K | Vl 24K | Qh 32K | Ql 40K  (all 64x64 bf16,
// row stride 128B, XOR-swizzled).  Output written as bf16 hi/lo to g_yhi/lo.
// ---------------------------------------------------------------------------
#define ATT_SMEM 49152

__global__ __launch_bounds__(128)
void attn_mma_kernel()
{
    extern __shared__ char smem[];
    const uint32_t sb = smem_to_u32(smem);
    const int tid = threadIdx.x, lane = tid & 31, w = tid >> 5;
    const int qt = blockIdx.x, bh = blockIdx.y;
    const int q0 = qt * 64;
    const size_t base = (size_t)bh * T_ * HD_;

    // ---- load Q tiles (hi/lo), build fragments, keep in registers ----
#pragma unroll
    for (int half = 0; half < 2; half++) {
        const __nv_bfloat16* src = half ? g_qlo : g_qhi;
        uint32_t dstb = 32768 + half * 8192;
#pragma unroll
        for (int it = 0; it < 4; it++) {
            int idx = it * 128 + tid;
            int r = idx >> 3, u = idx & 7;
            uint4 v = *(const uint4*)(src + base + (size_t)(q0 + r) * HD_ + u * 8);
            *(uint4*)(smem + dstb + SWZ(r * 128 + u * 16)) = v;
        }
    }
    __syncthreads();

    uint32_t qh[4][4], ql[4][4];
    {
        uint32_t rowb = (uint32_t)(16 * w + (lane & 7) + ((lane >> 3) & 1) * 8) * 128;
#pragma unroll
        for (int ks = 0; ks < 4; ks++) {
            uint32_t cb = ks * 32 + (lane >> 4) * 16;
            ldm_x4(qh[ks], sb + 32768 + SWZ(rowb + cb));
            ldm_x4(ql[ks], sb + 40960 + SWZ(rowb + cb));
        }
    }

    float oacc[8][4];
#pragma unroll
    for (int i = 0; i < 8; i++)
#pragma unroll
        for (int j = 0; j < 4; j++) oacc[i][j] = 0.f;
    float m_s[2] = {-1e30f, -1e30f};
    float l_s[2] = {0.f, 0.f};

    const int rlo = q0 + 16 * w + (lane >> 2);
    const int rhi = rlo + 8;

    for (int kt = 0; kt <= qt; kt++) {
        const int k0 = kt * 64;
        __syncthreads();   // all warps done reading previous K/V
        // ---- load K/V hi/lo tiles ----
#pragma unroll
        for (int tile = 0; tile < 4; tile++) {
            const __nv_bfloat16* src = (tile == 0) ? g_khi : (tile == 1) ? g_klo
                                      : (tile == 2) ? g_vhi : g_vlo;
            uint32_t dstb = tile * 8192;
#pragma unroll
            for (int it = 0; it < 4; it++) {
                int idx = it * 128 + tid;
                int r = idx >> 3, u = idx & 7;
                uint4 v = *(const uint4*)(src + base + (size_t)(k0 + r) * HD_ + u * 8);
                *(uint4*)(smem + dstb + SWZ(r * 128 + u * 16)) = v;
            }
        }
        __syncthreads();

        // ---- S = Q K^T (hi/lo 3-MMA) ----
        float sacc[8][4];
#pragma unroll
        for (int i = 0; i < 8; i++)
#pragma unroll
            for (int j = 0; j < 4; j++) sacc[i][j] = 0.f;

#pragma unroll
        for (int kt16 = 0; kt16 < 4; kt16++) {
            uint32_t rowb = (uint32_t)(kt16 * 16 + (lane & 7) + (lane >> 4) * 8) * 128;
#pragma unroll
            for (int ks = 0; ks < 4; ks++) {
                uint32_t cb = ks * 32 + ((lane >> 3) & 1) * 16;
                uint32_t kh[4], kl[4];
                ldm_x4(kh, sb + 0    + SWZ(rowb + cb));
                ldm_x4(kl, sb + 8192 + SWZ(rowb + cb));
#pragma unroll
                for (int sub = 0; sub < 2; sub++) {
                    float* d = sacc[kt16 * 2 + sub];
                    mma16816(d, qh[ks], kh[sub * 2], kh[sub * 2 + 1]);
                    mma16816(d, qh[ks], kl[sub * 2], kl[sub * 2 + 1]);
                    mma16816(d, ql[ks], kh[sub * 2], kh[sub * 2 + 1]);
                }
            }
        }

        // ---- scale + causal mask ----
#pragma unroll
        for (int nt = 0; nt < 8; nt++) {
            int cb0 = k0 + nt * 8 + (lane & 3) * 2;
#pragma unroll
            for (int j = 0; j < 4; j++) sacc[nt][j] *= 0.125f;
            if (kt == qt) {
                if (cb0 > rlo)     sacc[nt][0] = -1e30f;
                if (cb0 + 1 > rlo) sacc[nt][1] = -1e30f;
                if (cb0 > rhi)     sacc[nt][2] = -1e30f;
                if (cb0 + 1 > rhi) sacc[nt][3] = -1e30f;
            }
        }

        // ---- online softmax (register, quad shfl reductions) ----
        float tmax0 = -1e30f, tmax1 = -1e30f;
#pragma unroll
        for (int nt = 0; nt < 8; nt++) {
            tmax0 = fmaxf(tmax0, fmaxf(sacc[nt][0], sacc[nt][1]));
            tmax1 = fmaxf(tmax1, fmaxf(sacc[nt][2], sacc[nt][3]));
        }
        tmax0 = fmaxf(tmax0, __shfl_xor_sync(0xffffffff, tmax0, 1));
        tmax0 = fmaxf(tmax0, __shfl_xor_sync(0xffffffff, tmax0, 2));
        tmax1 = fmaxf(tmax1, __shfl_xor_sync(0xffffffff, tmax1, 1));
        tmax1 = fmaxf(tmax1, __shfl_xor_sync(0xffffffff, tmax1, 2));
        float nm0 = fmaxf(m_s[0], tmax0), nm1 = fmaxf(m_s[1], tmax1);
        float al0 = __expf(m_s[0] - nm0), al1 = __expf(m_s[1] - nm1);
        m_s[0] = nm0; m_s[1] = nm1;

        float rs0 = 0.f, rs1 = 0.f;
#pragma unroll
        for (int nt = 0; nt < 8; nt++) {
            sacc[nt][0] = __expf(sacc[nt][0] - nm0);
            sacc[nt][1] = __expf(sacc[nt][1] - nm0);
            sacc[nt][2] = __expf(sacc[nt][2] - nm1);
            sacc[nt][3] = __expf(sacc[nt][3] - nm1);
            rs0 += sacc[nt][0] + sacc[nt][1];
            rs1 += sacc[nt][2] + sacc[nt][3];
        }
        rs0 += __shfl_xor_sync(0xffffffff, rs0, 1);
        rs0 += __shfl_xor_sync(0xffffffff, rs0, 2);
        rs1 += __shfl_xor_sync(0xffffffff, rs1, 1);
        rs1 += __shfl_xor_sync(0xffffffff, rs1, 2);
        l_s[0] = l_s[0] * al0 + rs0;
        l_s[1] = l_s[1] * al1 + rs1;

#pragma unroll
        for (int nt = 0; nt < 8; nt++) {
            oacc[nt][0] *= al0; oacc[nt][1] *= al0;
            oacc[nt][2] *= al1; oacc[nt][3] *= al1;
        }

        // ---- P fragments (hi/lo) ----
        uint32_t ph[4][4], pl[4][4];
#pragma unroll
        for (int ks = 0; ks < 4; ks++) {
            const float* t0 = sacc[2 * ks];
            const float* t1 = sacc[2 * ks + 1];
            float h00 = __bfloat162float(__float2bfloat16(t0[0]));
            float h01 = __bfloat162float(__float2bfloat16(t0[1]));
            float h02 = __bfloat162float(__float2bfloat16(t0[2]));
            float h03 = __bfloat162float(__float2bfloat16(t0[3]));
            float h10 = __bfloat162float(__float2bfloat16(t1[0]));
            float h11 = __bfloat162float(__float2bfloat16(t1[1]));
            float h12 = __bfloat162float(__float2bfloat16(t1[2]));
            float h13 = __bfloat162float(__float2bfloat16(t1[3]));
            ph[ks][0] = packbf(t0[0], t0[1]);
            ph[ks][1] = packbf(t0[2], t0[3]);
            ph[ks][2] = packbf(t1[0], t1[1]);
            ph[ks][3] = packbf(t1[2], t1[3]);
            pl[ks][0] = packbf(t0[0] - h00, t0[1] - h01);
            pl[ks][1] = packbf(t0[2] - h02, t0[3] - h03);
            pl[ks][2] = packbf(t1[0] - h10, t1[1] - h11);
            pl[ks][3] = packbf(t1[2] - h12, t1[3] - h13);
        }

        // ---- O += P V (hi/lo 3-MMA, V via ldmatrix.trans) ----
#pragma unroll
        for (int ks = 0; ks < 4; ks++) {
            uint32_t rowb = (uint32_t)(ks * 16 + (lane & 7) + ((lane >> 3) & 1) * 8) * 128;
#pragma unroll
            for (int np = 0; np < 4; np++) {
                uint32_t cb = np * 32 + (lane >> 4) * 16;
                uint32_t vh[4], vl[4];
                ldm_x4_t(vh, sb + 16384 + SWZ(rowb + cb));
                ldm_x4_t(vl, sb + 24576 + SWZ(rowb + cb));
#pragma unroll
                for (int sub = 0; sub < 2; sub++) {
                    float* d = oacc[np * 2 + sub];
                    mma16816(d, ph[ks], vh[sub * 2], vh[sub * 2 + 1]);
                    mma16816(d, ph[ks], vl[sub * 2], vl[sub * 2 + 1]);
                    mma16816(d, pl[ks], vh[sub * 2], vh[sub * 2 + 1]);
                }
            }
        }
    }

    // ---- epilogue: y (bf16 hi/lo) into [B,T,C], merging heads ----
    float inv0 = 1.f / l_s[0], inv1 = 1.f / l_s[1];
    int b = bh / H_, h = bh - b * H_;
    const int col = h * 64 + (lane & 3) * 2;
#pragma unroll
    for (int nt = 0; nt < 8; nt++) {
        float y0 = oacc[nt][0] * inv0, y1 = oacc[nt][1] * inv0;
        float y2 = oacc[nt][2] * inv1, y3 = oacc[nt][3] * inv1;
        size_t o0 = ((size_t)b * T_ + rlo) * C_ + col + nt * 8;
        size_t o1 = ((size_t)b * T_ + rhi) * C_ + col + nt * 8;
        float h0 = __bfloat162float(__float2bfloat16(y0));
        float h1 = __bfloat162float(__float2bfloat16(y1));
        float h2 = __bfloat162float(__float2bfloat16(y2));
        float h3 = __bfloat162float(__float2bfloat16(y3));
        *(uint32_t*)&g_yhi[o0] = packbf(y0, y1);
        *(uint32_t*)&g_ylo[o0] = packbf(y0 - h0, y1 - h1);
        *(uint32_t*)&g_yhi[o1] = packbf(y2, y3);
        *(uint32_t*)&g_ylo[o1] = packbf(y2 - h2, y3 - h3);
    }
}

// ---------------------------------------------------------------------------
extern "C" void kernel_launch(void* const* d_in, const int* in_sizes, int n_in,
                              void* d_out, int out_size)
{
    (void)in_sizes; (void)n_in; (void)out_size;
    const float* x      = (const float*)d_in[0];
    const float* W_attn = (const float*)d_in[1];
    const float* b_attn = (const float*)d_in[2];
    const float* W_proj = (const float*)d_in[3];
    const float* b_proj = (const float*)d_in[4];
    float* out = (float*)d_out;

    // conversions
    split_x_kernel<<<(M_ROWS * K_) / 256, 256>>>(x);
    split_tr_kernel<0><<<dim3(QKV_N / 32, K_ / 32), 256>>>(W_attn, K_, QKV_N);
    split_tr_kernel<1><<<dim3(C_ / 32, K_ / 32), 256>>>(W_proj, K_, C_);

    // 1) QKV GEMM (HMMA) + bias -> q/k/v bf16 hi/lo [B,H,T,hd]
    cudaFuncSetAttribute(hgemm<0>,
                         cudaFuncAttributeMaxDynamicSharedMemorySize, SMEM_HG);
    hgemm<0><<<dim3(QKV_N / 128, M_ROWS / 128), 256, SMEM_HG>>>(b_attn, nullptr, QKV_N);

    // 2) causal flash attention (HMMA) -> g_yhi/g_ylo [B,T,C]
    cudaFuncSetAttribute(attn_mma_kernel,
                         cudaFuncAttributeMaxDynamicSharedMemorySize, ATT_SMEM);
    attn_mma_kernel<<<dim3(T_ / 64, B_ * H_), 128, ATT_SMEM>>>();

    // 3) output projection (HMMA)
    cudaFuncSetAttribute(hgemm<1>,
                         cudaFuncAttributeMaxDynamicSharedMemorySize, SMEM_HG);
    hgemm<1><<<dim3(C_ / 128, M_ROWS / 128), 256, SMEM_HG>>>(b_proj, out, C_);
}

// round 6
// speedup vs baseline: 3.0838x; 1.1893x over previous
#include <cuda_runtime.h>
#include <cuda_bf16.h>
#include <cstdint>
#include <cstddef>

// ---------------------------------------------------------------------------
// MultiHeadAttention: y = proj( causal_attention( x @ W_attn + b_attn ) )
// B=8, T=1024, C=768, H=12, hd=64
// Everything on HMMA (mma.sync bf16, hi/lo split -> ~fp32 accuracy).
// cp.async double-buffered pipelines throughout.
// ---------------------------------------------------------------------------

#define B_  8
#define T_  1024
#define C_  768
#define H_  12
#define HD_ 64
#define M_ROWS (B_ * T_)          // 8192
#define QKV_N  (3 * C_)           // 2304
#define K_     C_                 // 768

// ---------------- device scratch (no allocation allowed) -------------------
__device__ __nv_bfloat16 g_qhi[B_ * H_ * T_ * HD_], g_qlo[B_ * H_ * T_ * HD_];
__device__ __nv_bfloat16 g_khi[B_ * H_ * T_ * HD_], g_klo[B_ * H_ * T_ * HD_];
__device__ __nv_bfloat16 g_vhi[B_ * H_ * T_ * HD_], g_vlo[B_ * H_ * T_ * HD_];

__device__ __nv_bfloat16 g_xhi[M_ROWS * K_], g_xlo[M_ROWS * K_];
__device__ __nv_bfloat16 g_yhi[M_ROWS * K_], g_ylo[M_ROWS * K_];   // attn out
__device__ __nv_bfloat16 g_wahi[QKV_N * K_], g_walo[QKV_N * K_];   // W_attn^T [N,K]
__device__ __nv_bfloat16 g_wphi[C_ * K_],    g_wplo[C_ * K_];      // W_proj^T [N,K]

// ---------------- small PTX helpers (sm_80-level only) ---------------------
__device__ __forceinline__ uint32_t smem_to_u32(const void* p) {
    uint32_t a;
    asm("{ .reg .u64 t; cvta.to.shared.u64 t, %1; cvt.u32.u64 %0, t; }"
        : "=r"(a) : "l"(p));
    return a;
}
__device__ __forceinline__ void ldm_x4(uint32_t* r, uint32_t addr) {
    asm volatile("ldmatrix.sync.aligned.m8n8.x4.shared.b16 {%0,%1,%2,%3}, [%4];"
                 : "=r"(r[0]), "=r"(r[1]), "=r"(r[2]), "=r"(r[3]) : "r"(addr));
}
__device__ __forceinline__ void ldm_x4_t(uint32_t* r, uint32_t addr) {
    asm volatile("ldmatrix.sync.aligned.m8n8.x4.trans.shared.b16 {%0,%1,%2,%3}, [%4];"
                 : "=r"(r[0]), "=r"(r[1]), "=r"(r[2]), "=r"(r[3]) : "r"(addr));
}
__device__ __forceinline__ void mma16816(float* d, const uint32_t* a,
                                         uint32_t b0, uint32_t b1) {
    asm volatile(
        "mma.sync.aligned.m16n8k16.row.col.f32.bf16.bf16.f32 "
        "{%0,%1,%2,%3}, {%4,%5,%6,%7}, {%8,%9}, {%0,%1,%2,%3};"
        : "+f"(d[0]), "+f"(d[1]), "+f"(d[2]), "+f"(d[3])
        : "r"(a[0]), "r"(a[1]), "r"(a[2]), "r"(a[3]), "r"(b0), "r"(b1));
}
__device__ __forceinline__ uint32_t packbf(float lo, float hi) {
    __nv_bfloat162 t;
    t.x = __float2bfloat16(lo);
    t.y = __float2bfloat16(hi);
    return *(uint32_t*)&t;
}
__device__ __forceinline__ void cp16(uint32_t dst, const void* src) {
    asm volatile("cp.async.cg.shared.global [%0], [%1], 16;"
                 :: "r"(dst), "l"(src));
}
#define CP_COMMIT() asm volatile("cp.async.commit_group;" ::: "memory")
#define CP_WAIT1()  asm volatile("cp.async.wait_group 1;" ::: "memory")
#define CP_WAIT0()  asm volatile("cp.async.wait_group 0;" ::: "memory")
#define SWZ(b) ((b) ^ (((b) >> 3) & 0x70))
#define SUBT(r, u) ((((r) >> 4 << 1) + ((u) >> 1)) * 512 + ((r) & 15) * 32 + ((u) & 1) * 16)

// ---------------------------------------------------------------------------
// Split / conversion kernels (fp32 -> bf16 hi + bf16 lo residual)
// ---------------------------------------------------------------------------
__global__ void split_x_kernel(const float* __restrict__ s) {
    int i = blockIdx.x * 256 + threadIdx.x;
    float a = s[i];
    __nv_bfloat16 h = __float2bfloat16(a);
    g_xhi[i] = h;
    g_xlo[i] = __float2bfloat16(a - __bfloat162float(h));
}
// transpose [K,N] fp32 -> [N,K] bf16 hi/lo
template <int W>
__global__ void split_tr_kernel(const float* __restrict__ s, int Kd, int Nd) {
    __shared__ float t[32][33];
    int nb = blockIdx.x * 32, kb = blockIdx.y * 32;
    int tx = threadIdx.x & 31, ty = threadIdx.x >> 5;   // 32 x 8
    for (int r = ty; r < 32; r += 8)
        t[r][tx] = s[(size_t)(kb + r) * Nd + nb + tx];
    __syncthreads();
    __nv_bfloat16* hi = W ? g_wphi : g_wahi;
    __nv_bfloat16* lo = W ? g_wplo : g_walo;
    for (int r = ty; r < 32; r += 8) {
        float a = t[tx][r];
        __nv_bfloat16 h = __float2bfloat16(a);
        size_t o = (size_t)(nb + r) * Kd + kb + tx;
        hi[o] = h;
        lo[o] = __float2bfloat16(a - __bfloat162float(h));
    }
}

// ---------------------------------------------------------------------------
// HMMA bf16 hi/lo GEMM v2: CTA 128 x NT, K-chunk 32, 8 warps (2m x 4n),
// warp tile 64 x (NT/4). cp.async double-buffered (prefetch distance 2).
// SMEM stage: A(hi,lo) 16KB | B(hi,lo) NT*128 bytes.
// EPI==0: write q/k/v bf16 hi/lo [B,H,T,hd].  EPI==1: fp32 row-major out.
// ---------------------------------------------------------------------------
#define KCH    32
#define NKCH   (K_ / KCH)          // 24

template <int EPI, int NT>
__global__ __launch_bounds__(256)
void hgemm(const float* __restrict__ bias, float* __restrict__ Cout, int N)
{
    constexpr int WN    = NT / 4;          // warp n-tile
    constexpr int JN    = WN / 8;          // n8 tiles per warp
    constexpr int NT16  = WN / 16;         // n16 groups per warp
    constexpr int BHL   = NT * 64;         // bytes per B hi (or lo) tile
    constexpr int STAGE = 16384 + 2 * BHL; // A(hi+lo) + B(hi+lo)
    constexpr int B_IT  = NT / 32;         // cp.async iterations for B

    extern __shared__ char smem[];
    const uint32_t sb = smem_to_u32(smem);
    const int tid  = threadIdx.x;
    const int lane = tid & 31;
    const int w    = tid >> 5;
    const int mw   = w & 1;        // 2 m-warps
    const int nw   = w >> 1;       // 4 n-warps
    const int n0 = blockIdx.x * NT;
    const int m0 = blockIdx.y * 128;

    const __nv_bfloat16* Ahi = (EPI == 0) ? g_xhi : g_yhi;
    const __nv_bfloat16* Alo = (EPI == 0) ? g_xlo : g_ylo;
    const __nv_bfloat16* Bhi = (EPI == 0) ? g_wahi : g_wphi;
    const __nv_bfloat16* Blo = (EPI == 0) ? g_walo : g_wplo;

    float acc[4][JN][4];
#pragma unroll
    for (int i = 0; i < 4; i++)
#pragma unroll
        for (int j = 0; j < JN; j++)
#pragma unroll
            for (int q = 0; q < 4; q++) acc[i][j][q] = 0.f;

    auto issue = [&](int stage, int c) {
        const int kk = c * KCH;
        const uint32_t sbase = sb + stage * STAGE;
        // A hi/lo: 2 * 128 rows * 4 u = 1024 sixteen-byte pieces
#pragma unroll
        for (int it = 0; it < 4; it++) {
            int idx = it * 256 + tid;
            int hl = idx >> 9, rem = idx & 511;
            int r = rem >> 2, u = rem & 3;
            const __nv_bfloat16* src = hl ? Alo : Ahi;
            cp16(sbase + hl * 8192 + SUBT(r, u),
                 src + (size_t)(m0 + r) * K_ + kk + u * 8);
        }
        // B hi/lo: 2 * NT rows * 4 u
#pragma unroll
        for (int it = 0; it < B_IT; it++) {
            int idx = it * 256 + tid;
            int hl = (idx >= NT * 4) ? 1 : 0;
            int rem = idx - hl * NT * 4;
            int r = rem >> 2, u = rem & 3;
            const __nv_bfloat16* src = hl ? Blo : Bhi;
            cp16(sbase + 16384 + hl * BHL + SUBT(r, u),
                 src + (size_t)(n0 + r) * K_ + kk + u * 8);
        }
        CP_COMMIT();
    };

    const uint32_t a_in = (lane & 15) * 32 + (lane >> 4) * 16;
    const uint32_t b_in = ((lane & 7) + (lane >> 4) * 8) * 32 + ((lane >> 3) & 1) * 16;

    issue(0, 0);
    issue(1, 1);

    for (int c = 0; c < NKCH; c++) {
        if (c + 1 < NKCH) { CP_WAIT1(); } else { CP_WAIT0(); }
        __syncthreads();

        const uint32_t base = sb + (c & 1) * STAGE;
#pragma unroll
        for (int kc = 0; kc < 2; kc++) {
            uint32_t af[2][4][4];
#pragma unroll
            for (int hl = 0; hl < 2; hl++)
#pragma unroll
                for (int mt = 0; mt < 4; mt++) {
                    uint32_t addr = base + hl * 8192 +
                                    (((mw * 4 + mt) << 1) + kc) * 512 + a_in;
                    ldm_x4(af[hl][mt], addr);
                }
            uint32_t bfq[2][NT16][4];
#pragma unroll
            for (int hl = 0; hl < 2; hl++)
#pragma unroll
                for (int nt = 0; nt < NT16; nt++) {
                    uint32_t addr = base + 16384 + hl * BHL +
                                    (((nw * NT16 + nt) << 1) + kc) * 512 + b_in;
                    ldm_x4(bfq[hl][nt], addr);
                }
#pragma unroll
            for (int mt = 0; mt < 4; mt++)
#pragma unroll
                for (int nt = 0; nt < NT16; nt++)
#pragma unroll
                    for (int hf = 0; hf < 2; hf++) {
                        float* d = acc[mt][nt * 2 + hf];
                        mma16816(d, af[0][mt], bfq[0][nt][hf * 2], bfq[0][nt][hf * 2 + 1]);
                        mma16816(d, af[0][mt], bfq[1][nt][hf * 2], bfq[1][nt][hf * 2 + 1]);
                        mma16816(d, af[1][mt], bfq[0][nt][hf * 2], bfq[0][nt][hf * 2 + 1]);
                    }
        }
        __syncthreads();
        if (c + 2 < NKCH) issue(c & 1, c + 2);
    }

    // epilogue
    const int row_in = lane >> 2;
    const int col_in = (lane & 3) * 2;
#pragma unroll
    for (int mt = 0; mt < 4; mt++) {
#pragma unroll
        for (int j = 0; j < JN; j++) {
            const int c = n0 + nw * WN + j * 8 + col_in;
            const float b0v = bias[c], b1v = bias[c + 1];
#pragma unroll
            for (int hf = 0; hf < 2; hf++) {
                const int m = m0 + mw * 64 + mt * 16 + row_in + hf * 8;
                float v0 = acc[mt][j][hf * 2 + 0] + b0v;
                float v1 = acc[mt][j][hf * 2 + 1] + b1v;
                if (EPI == 0) {
                    int which = c / C_;
                    int cc = c - which * C_;
                    int h = cc >> 6, d = cc & 63;
                    int b = m >> 10, tt = m & 1023;
                    __nv_bfloat16* dh = (which == 0) ? g_qhi : ((which == 1) ? g_khi : g_vhi);
                    __nv_bfloat16* dl = (which == 0) ? g_qlo : ((which == 1) ? g_klo : g_vlo);
                    size_t o = ((size_t)(b * H_ + h) * T_ + tt) * HD_ + d;
                    float h0 = __bfloat162float(__float2bfloat16(v0));
                    float h1 = __bfloat162float(__float2bfloat16(v1));
                    *(uint32_t*)&dh[o] = packbf(v0, v1);
                    *(uint32_t*)&dl[o] = packbf(v0 - h0, v1 - h1);
                } else {
                    *(float2*)&Cout[(size_t)m * N + c] = make_float2(v0, v1);
                }
            }
        }
    }
}

// ---------------------------------------------------------------------------
// HMMA flash attention, causal. Grid (16 q-tiles, 96 bh), 128 threads (4 warps).
// cp.async double-buffered K/V stages (32KB each); Q at +64KB.
// Stage layout: Kh 0 | Kl 8K | Vh 16K | Vl 24K (XOR-swizzled rows of 128B).
// ---------------------------------------------------------------------------
#define ATT_SMEM (2 * 32768 + 16384)

__global__ __launch_bounds__(128)
void attn_mma_kernel()
{
    extern __shared__ char smem[];
    const uint32_t sb = smem_to_u32(smem);
    const int tid = threadIdx.x, lane = tid & 31, w = tid >> 5;
    const int qt = blockIdx.x, bh = blockIdx.y;
    const int q0 = qt * 64;
    const size_t base = (size_t)bh * T_ * HD_;

    // Each tile is 64 rows x 128 bytes = 8192 B -> 512 x 16B pieces per tile,
    // 2048 pieces for 4 tiles, 16 iterations of 128 threads.
    auto issue_kv = [&](int stage, int kt) {
        const int k0 = kt * 64;
        const uint32_t sbase = sb + stage * 32768;
#pragma unroll
        for (int it = 0; it < 16; it++) {
            int idx = it * 128 + tid;       // 0..2047
            int tile = idx >> 9;            // 0..3
            int rem = idx & 511;
            int r = rem >> 3, u = rem & 7;  // r 0..63, u 0..7
            const __nv_bfloat16* src = (tile == 0) ? g_khi : (tile == 1) ? g_klo
                                      : (tile == 2) ? g_vhi : g_vlo;
            cp16(sbase + tile * 8192 + SWZ(r * 128 + u * 16),
                 src + base + (size_t)(k0 + r) * HD_ + u * 8);
        }
        CP_COMMIT();
    };

    issue_kv(0, 0);
    if (qt >= 1) issue_kv(1, 1);

    // ---- load Q tiles (hi/lo) with plain stores, build fragments ----
#pragma unroll
    for (int half = 0; half < 2; half++) {
        const __nv_bfloat16* src = half ? g_qlo : g_qhi;
        uint32_t dstb = 65536 + half * 8192;
#pragma unroll
        for (int it = 0; it < 4; it++) {
            int idx = it * 128 + tid;
            int r = idx >> 3, u = idx & 7;
            uint4 v = *(const uint4*)(src + base + (size_t)(q0 + r) * HD_ + u * 8);
            *(uint4*)(smem + dstb + SWZ(r * 128 + u * 16)) = v;
        }
    }
    __syncthreads();

    uint32_t qh[4][4], ql[4][4];
    {
        uint32_t rowb = (uint32_t)(16 * w + (lane & 7) + ((lane >> 3) & 1) * 8) * 128;
#pragma unroll
        for (int ks = 0; ks < 4; ks++) {
            uint32_t cb = ks * 32 + (lane >> 4) * 16;
            ldm_x4(qh[ks], sb + 65536 + SWZ(rowb + cb));
            ldm_x4(ql[ks], sb + 73728 + SWZ(rowb + cb));
        }
    }

    float oacc[8][4];
#pragma unroll
    for (int i = 0; i < 8; i++)
#pragma unroll
        for (int j = 0; j < 4; j++) oacc[i][j] = 0.f;
    float m_s[2] = {-1e30f, -1e30f};
    float l_s[2] = {0.f, 0.f};

    const int rlo = q0 + 16 * w + (lane >> 2);
    const int rhi = rlo + 8;

    for (int kt = 0; kt <= qt; kt++) {
        const int k0 = kt * 64;
        if (kt < qt) { CP_WAIT1(); } else { CP_WAIT0(); }
        __syncthreads();
        const uint32_t stg = sb + (kt & 1) * 32768;

        // ---- S = Q K^T (hi/lo 3-MMA) ----
        float sacc[8][4];
#pragma unroll
        for (int i = 0; i < 8; i++)
#pragma unroll
            for (int j = 0; j < 4; j++) sacc[i][j] = 0.f;

#pragma unroll
        for (int kt16 = 0; kt16 < 4; kt16++) {
            uint32_t rowb = (uint32_t)(kt16 * 16 + (lane & 7) + (lane >> 4) * 8) * 128;
#pragma unroll
            for (int ks = 0; ks < 4; ks++) {
                uint32_t cb = ks * 32 + ((lane >> 3) & 1) * 16;
                uint32_t kh[4], kl[4];
                ldm_x4(kh, stg + 0    + SWZ(rowb + cb));
                ldm_x4(kl, stg + 8192 + SWZ(rowb + cb));
#pragma unroll
                for (int sub = 0; sub < 2; sub++) {
                    float* d = sacc[kt16 * 2 + sub];
                    mma16816(d, qh[ks], kh[sub * 2], kh[sub * 2 + 1]);
                    mma16816(d, qh[ks], kl[sub * 2], kl[sub * 2 + 1]);
                    mma16816(d, ql[ks], kh[sub * 2], kh[sub * 2 + 1]);
                }
            }
        }

        // ---- scale + causal mask ----
#pragma unroll
        for (int nt = 0; nt < 8; nt++) {
            int cb0 = k0 + nt * 8 + (lane & 3) * 2;
#pragma unroll
            for (int j = 0; j < 4; j++) sacc[nt][j] *= 0.125f;
            if (kt == qt) {
                if (cb0 > rlo)     sacc[nt][0] = -1e30f;
                if (cb0 + 1 > rlo) sacc[nt][1] = -1e30f;
                if (cb0 > rhi)     sacc[nt][2] = -1e30f;
                if (cb0 + 1 > rhi) sacc[nt][3] = -1e30f;
            }
        }

        // ---- online softmax (register, quad shfl reductions) ----
        float tmax0 = -1e30f, tmax1 = -1e30f;
#pragma unroll
        for (int nt = 0; nt < 8; nt++) {
            tmax0 = fmaxf(tmax0, fmaxf(sacc[nt][0], sacc[nt][1]));
            tmax1 = fmaxf(tmax1, fmaxf(sacc[nt][2], sacc[nt][3]));
        }
        tmax0 = fmaxf(tmax0, __shfl_xor_sync(0xffffffff, tmax0, 1));
        tmax0 = fmaxf(tmax0, __shfl_xor_sync(0xffffffff, tmax0, 2));
        tmax1 = fmaxf(tmax1, __shfl_xor_sync(0xffffffff, tmax1, 1));
        tmax1 = fmaxf(tmax1, __shfl_xor_sync(0xffffffff, tmax1, 2));
        float nm0 = fmaxf(m_s[0], tmax0), nm1 = fmaxf(m_s[1], tmax1);
        float al0 = __expf(m_s[0] - nm0), al1 = __expf(m_s[1] - nm1);
        m_s[0] = nm0; m_s[1] = nm1;

        float rs0 = 0.f, rs1 = 0.f;
#pragma unroll
        for (int nt = 0; nt < 8; nt++) {
            sacc[nt][0] = __expf(sacc[nt][0] - nm0);
            sacc[nt][1] = __expf(sacc[nt][1] - nm0);
            sacc[nt][2] = __expf(sacc[nt][2] - nm1);
            sacc[nt][3] = __expf(sacc[nt][3] - nm1);
            rs0 += sacc[nt][0] + sacc[nt][1];
            rs1 += sacc[nt][2] + sacc[nt][3];
        }
        rs0 += __shfl_xor_sync(0xffffffff, rs0, 1);
        rs0 += __shfl_xor_sync(0xffffffff, rs0, 2);
        rs1 += __shfl_xor_sync(0xffffffff, rs1, 1);
        rs1 += __shfl_xor_sync(0xffffffff, rs1, 2);
        l_s[0] = l_s[0] * al0 + rs0;
        l_s[1] = l_s[1] * al1 + rs1;

#pragma unroll
        for (int nt = 0; nt < 8; nt++) {
            oacc[nt][0] *= al0; oacc[nt][1] *= al0;
            oacc[nt][2] *= al1; oacc[nt][3] *= al1;
        }

        // ---- P fragments (hi/lo) ----
        uint32_t ph[4][4], pl[4][4];
#pragma unroll
        for (int ks = 0; ks < 4; ks++) {
            const float* t0 = sacc[2 * ks];
            const float* t1 = sacc[2 * ks + 1];
            float h00 = __bfloat162float(__float2bfloat16(t0[0]));
            float h01 = __bfloat162float(__float2bfloat16(t0[1]));
            float h02 = __bfloat162float(__float2bfloat16(t0[2]));
            float h03 = __bfloat162float(__float2bfloat16(t0[3]));
            float h10 = __bfloat162float(__float2bfloat16(t1[0]));
            float h11 = __bfloat162float(__float2bfloat16(t1[1]));
            float h12 = __bfloat162float(__float2bfloat16(t1[2]));
            float h13 = __bfloat162float(__float2bfloat16(t1[3]));
            ph[ks][0] = packbf(t0[0], t0[1]);
            ph[ks][1] = packbf(t0[2], t0[3]);
            ph[ks][2] = packbf(t1[0], t1[1]);
            ph[ks][3] = packbf(t1[2], t1[3]);
            pl[ks][0] = packbf(t0[0] - h00, t0[1] - h01);
            pl[ks][1] = packbf(t0[2] - h02, t0[3] - h03);
            pl[ks][2] = packbf(t1[0] - h10, t1[1] - h11);
            pl[ks][3] = packbf(t1[2] - h12, t1[3] - h13);
        }

        // ---- O += P V (hi/lo 3-MMA, V via ldmatrix.trans) ----
#pragma unroll
        for (int ks = 0; ks < 4; ks++) {
            uint32_t rowb = (uint32_t)(ks * 16 + (lane & 7) + ((lane >> 3) & 1) * 8) * 128;
#pragma unroll
            for (int np = 0; np < 4; np++) {
                uint32_t cb = np * 32 + (lane >> 4) * 16;
                uint32_t vh[4], vl[4];
                ldm_x4_t(vh, stg + 16384 + SWZ(rowb + cb));
                ldm_x4_t(vl, stg + 24576 + SWZ(rowb + cb));
#pragma unroll
                for (int sub = 0; sub < 2; sub++) {
                    float* d = oacc[np * 2 + sub];
                    mma16816(d, ph[ks], vh[sub * 2], vh[sub * 2 + 1]);
                    mma16816(d, ph[ks], vl[sub * 2], vl[sub * 2 + 1]);
                    mma16816(d, pl[ks], vh[sub * 2], vh[sub * 2 + 1]);
                }
            }
        }
        __syncthreads();
        if (kt + 2 <= qt) issue_kv(kt & 1, kt + 2);
    }

    // ---- epilogue: y (bf16 hi/lo) into [B,T,C], merging heads ----
    float inv0 = 1.f / l_s[0], inv1 = 1.f / l_s[1];
    int b = bh / H_, h = bh - b * H_;
    const int col = h * 64 + (lane & 3) * 2;
#pragma unroll
    for (int nt = 0; nt < 8; nt++) {
        float y0 = oacc[nt][0] * inv0, y1 = oacc[nt][1] * inv0;
        float y2 = oacc[nt][2] * inv1, y3 = oacc[nt][3] * inv1;
        size_t o0 = ((size_t)b * T_ + rlo) * C_ + col + nt * 8;
        size_t o1 = ((size_t)b * T_ + rhi) * C_ + col + nt * 8;
        float h0 = __bfloat162float(__float2bfloat16(y0));
        float h1 = __bfloat162float(__float2bfloat16(y1));
        float h2 = __bfloat162float(__float2bfloat16(y2));
        float h3 = __bfloat162float(__float2bfloat16(y3));
        *(uint32_t*)&g_yhi[o0] = packbf(y0, y1);
        *(uint32_t*)&g_ylo[o0] = packbf(y0 - h0, y1 - h1);
        *(uint32_t*)&g_yhi[o1] = packbf(y2, y3);
        *(uint32_t*)&g_ylo[o1] = packbf(y2 - h2, y3 - h3);
    }
}

// ---------------------------------------------------------------------------
extern "C" void kernel_launch(void* const* d_in, const int* in_sizes, int n_in,
                              void* d_out, int out_size)
{
    (void)in_sizes; (void)n_in; (void)out_size;
    const float* x      = (const float*)d_in[0];
    const float* W_attn = (const float*)d_in[1];
    const float* b_attn = (const float*)d_in[2];
    const float* W_proj = (const float*)d_in[3];
    const float* b_proj = (const float*)d_in[4];
    float* out = (float*)d_out;

    // conversions
    split_x_kernel<<<(M_ROWS * K_) / 256, 256>>>(x);
    split_tr_kernel<0><<<dim3(QKV_N / 32, K_ / 32), 256>>>(W_attn, K_, QKV_N);
    split_tr_kernel<1><<<dim3(C_ / 32, K_ / 32), 256>>>(W_proj, K_, C_);

    // 1) QKV GEMM (HMMA, 128x256 tiles) + bias -> q/k/v bf16 hi/lo
    constexpr int SM0 = 2 * (16384 + 2 * 256 * 64);   // 98304
    cudaFuncSetAttribute(hgemm<0, 256>,
                         cudaFuncAttributeMaxDynamicSharedMemorySize, SM0);
    hgemm<0, 256><<<dim3(QKV_N / 256, M_ROWS / 128), 256, SM0>>>(b_attn, nullptr, QKV_N);

    // 2) causal flash attention (HMMA, cp.async) -> g_yhi/g_ylo [B,T,C]
    cudaFuncSetAttribute(attn_mma_kernel,
                         cudaFuncAttributeMaxDynamicSharedMemorySize, ATT_SMEM);
    attn_mma_kernel<<<dim3(T_ / 64, B_ * H_), 128, ATT_SMEM>>>();

    // 3) output projection (HMMA, 128x128 tiles)
    constexpr int SM1 = 2 * (16384 + 2 * 128 * 64);   // 65536
    cudaFuncSetAttribute(hgemm<1, 128>,
                         cudaFuncAttributeMaxDynamicSharedMemorySize, SM1);
    hgemm<1, 128><<<dim3(C_ / 128, M_ROWS / 128), 256, SM1>>>(b_proj, out, C_);
}

// round 7
// speedup vs baseline: 3.1677x; 1.0272x over previous
#include <cuda_runtime.h>
#include <cuda_bf16.h>
#include <cstdint>
#include <cstddef>

// ---------------------------------------------------------------------------
// MultiHeadAttention: y = proj( causal_attention( x @ W_attn + b_attn ) )
// B=8, T=1024, C=768, H=12, hd=64
// Everything on HMMA (mma.sync bf16, hi/lo split -> ~fp32 accuracy).
// cp.async double-buffered pipelines; hgemm tuned for 2 CTAs/SM.
// ---------------------------------------------------------------------------

#define B_  8
#define T_  1024
#define C_  768
#define H_  12
#define HD_ 64
#define M_ROWS (B_ * T_)          // 8192
#define QKV_N  (3 * C_)           // 2304
#define K_     C_                 // 768

// ---------------- device scratch (no allocation allowed) -------------------
__device__ __nv_bfloat16 g_qhi[B_ * H_ * T_ * HD_], g_qlo[B_ * H_ * T_ * HD_];
__device__ __nv_bfloat16 g_khi[B_ * H_ * T_ * HD_], g_klo[B_ * H_ * T_ * HD_];
__device__ __nv_bfloat16 g_vhi[B_ * H_ * T_ * HD_], g_vlo[B_ * H_ * T_ * HD_];

__device__ __nv_bfloat16 g_xhi[M_ROWS * K_], g_xlo[M_ROWS * K_];
__device__ __nv_bfloat16 g_yhi[M_ROWS * K_], g_ylo[M_ROWS * K_];   // attn out
__device__ __nv_bfloat16 g_wahi[QKV_N * K_], g_walo[QKV_N * K_];   // W_attn^T [N,K]
__device__ __nv_bfloat16 g_wphi[C_ * K_],    g_wplo[C_ * K_];      // W_proj^T [N,K]

// ---------------- small PTX helpers (sm_80-level only) ---------------------
__device__ __forceinline__ uint32_t smem_to_u32(const void* p) {
    uint32_t a;
    asm("{ .reg .u64 t; cvta.to.shared.u64 t, %1; cvt.u32.u64 %0, t; }"
        : "=r"(a) : "l"(p));
    return a;
}
__device__ __forceinline__ void ldm_x4(uint32_t* r, uint32_t addr) {
    asm volatile("ldmatrix.sync.aligned.m8n8.x4.shared.b16 {%0,%1,%2,%3}, [%4];"
                 : "=r"(r[0]), "=r"(r[1]), "=r"(r[2]), "=r"(r[3]) : "r"(addr));
}
__device__ __forceinline__ void ldm_x4_t(uint32_t* r, uint32_t addr) {
    asm volatile("ldmatrix.sync.aligned.m8n8.x4.trans.shared.b16 {%0,%1,%2,%3}, [%4];"
                 : "=r"(r[0]), "=r"(r[1]), "=r"(r[2]), "=r"(r[3]) : "r"(addr));
}
__device__ __forceinline__ void mma16816(float* d, const uint32_t* a,
                                         uint32_t b0, uint32_t b1) {
    asm volatile(
        "mma.sync.aligned.m16n8k16.row.col.f32.bf16.bf16.f32 "
        "{%0,%1,%2,%3}, {%4,%5,%6,%7}, {%8,%9}, {%0,%1,%2,%3};"
        : "+f"(d[0]), "+f"(d[1]), "+f"(d[2]), "+f"(d[3])
        : "r"(a[0]), "r"(a[1]), "r"(a[2]), "r"(a[3]), "r"(b0), "r"(b1));
}
__device__ __forceinline__ uint32_t packbf(float lo, float hi) {
    __nv_bfloat162 t;
    t.x = __float2bfloat16(lo);
    t.y = __float2bfloat16(hi);
    return *(uint32_t*)&t;
}
__device__ __forceinline__ void cp16(uint32_t dst, const void* src) {
    asm volatile("cp.async.cg.shared.global [%0], [%1], 16;"
                 :: "r"(dst), "l"(src));
}
#define CP_COMMIT() asm volatile("cp.async.commit_group;" ::: "memory")
#define CP_WAIT1()  asm volatile("cp.async.wait_group 1;" ::: "memory")
#define CP_WAIT0()  asm volatile("cp.async.wait_group 0;" ::: "memory")
#define SWZ(b) ((b) ^ (((b) >> 3) & 0x70))
#define SUBT(r, u) ((((r) >> 4 << 1) + ((u) >> 1)) * 512 + ((r) & 15) * 32 + ((u) & 1) * 16)

// ---------------------------------------------------------------------------
// Split / conversion kernels (fp32 -> bf16 hi + bf16 lo residual)
// ---------------------------------------------------------------------------
__global__ void split_x_kernel(const float* __restrict__ s) {
    int i = blockIdx.x * 256 + threadIdx.x;
    float a = s[i];
    __nv_bfloat16 h = __float2bfloat16(a);
    g_xhi[i] = h;
    g_xlo[i] = __float2bfloat16(a - __bfloat162float(h));
}
// transpose [K,N] fp32 -> [N,K] bf16 hi/lo
template <int W>
__global__ void split_tr_kernel(const float* __restrict__ s, int Kd, int Nd) {
    __shared__ float t[32][33];
    int nb = blockIdx.x * 32, kb = blockIdx.y * 32;
    int tx = threadIdx.x & 31, ty = threadIdx.x >> 5;   // 32 x 8
    for (int r = ty; r < 32; r += 8)
        t[r][tx] = s[(size_t)(kb + r) * Nd + nb + tx];
    __syncthreads();
    __nv_bfloat16* hi = W ? g_wphi : g_wahi;
    __nv_bfloat16* lo = W ? g_wplo : g_walo;
    for (int r = ty; r < 32; r += 8) {
        float a = t[tx][r];
        __nv_bfloat16 h = __float2bfloat16(a);
        size_t o = (size_t)(nb + r) * Kd + kb + tx;
        hi[o] = h;
        lo[o] = __float2bfloat16(a - __bfloat162float(h));
    }
}

// ---------------------------------------------------------------------------
// HMMA bf16 hi/lo GEMM v3: CTA 128x128, K-chunk 32, 8 warps (2m x 4n),
// warp tile 64x32 (acc = 64 regs). cp.async double-buffered, prefetch dist 2.
// __launch_bounds__(256, 2) caps regs at 128 -> 2 CTAs/SM = 16 warps/SM.
// SMEM stage: A(hi,lo) 16KB | B(hi,lo) 16KB; 2 stages = 64KB/CTA.
// EPI==0: write q/k/v bf16 hi/lo [B,H,T,hd].  EPI==1: fp32 row-major out.
// ---------------------------------------------------------------------------
#define KCH    32
#define NKCH   (K_ / KCH)          // 24
#define HSTAGE 32768               // 16KB A + 16KB B

template <int EPI>
__global__ __launch_bounds__(256, 2)
void hgemm(const float* __restrict__ bias, float* __restrict__ Cout, int N)
{
    extern __shared__ char smem[];
    const uint32_t sb = smem_to_u32(smem);
    const int tid  = threadIdx.x;
    const int lane = tid & 31;
    const int w    = tid >> 5;
    const int mw   = w & 1;        // 2 m-warps (64 rows each)
    const int nw   = w >> 1;       // 4 n-warps (32 cols each)
    const int n0 = blockIdx.x * 128;
    const int m0 = blockIdx.y * 128;

    const __nv_bfloat16* Ahi = (EPI == 0) ? g_xhi : g_yhi;
    const __nv_bfloat16* Alo = (EPI == 0) ? g_xlo : g_ylo;
    const __nv_bfloat16* Bhi = (EPI == 0) ? g_wahi : g_wphi;
    const __nv_bfloat16* Blo = (EPI == 0) ? g_walo : g_wplo;

    float acc[4][4][4];           // [mt 16-row][j n8][quad]
#pragma unroll
    for (int i = 0; i < 4; i++)
#pragma unroll
        for (int j = 0; j < 4; j++)
#pragma unroll
            for (int q = 0; q < 4; q++) acc[i][j][q] = 0.f;

    auto issue = [&](int stage, int c) {
        const int kk = c * KCH;
        const uint32_t sbase = sb + stage * HSTAGE;
        // A hi/lo: 2 * 128 rows * 4 u = 1024 pieces (4 its)
#pragma unroll
        for (int it = 0; it < 4; it++) {
            int idx = it * 256 + tid;
            int hl = idx >> 9, rem = idx & 511;
            int r = rem >> 2, u = rem & 3;
            const __nv_bfloat16* src = hl ? Alo : Ahi;
            cp16(sbase + hl * 8192 + SUBT(r, u),
                 src + (size_t)(m0 + r) * K_ + kk + u * 8);
        }
        // B hi/lo: 2 * 128 rows * 4 u = 1024 pieces (4 its)
#pragma unroll
        for (int it = 0; it < 4; it++) {
            int idx = it * 256 + tid;
            int hl = idx >> 9, rem = idx & 511;
            int r = rem >> 2, u = rem & 3;
            const __nv_bfloat16* src = hl ? Blo : Bhi;
            cp16(sbase + 16384 + hl * 8192 + SUBT(r, u),
                 src + (size_t)(n0 + r) * K_ + kk + u * 8);
        }
        CP_COMMIT();
    };

    const uint32_t a_in = (lane & 15) * 32 + (lane >> 4) * 16;
    const uint32_t b_in = ((lane & 7) + (lane >> 4) * 8) * 32 + ((lane >> 3) & 1) * 16;

    issue(0, 0);
    issue(1, 1);

    for (int c = 0; c < NKCH; c++) {
        if (c + 1 < NKCH) { CP_WAIT1(); } else { CP_WAIT0(); }
        __syncthreads();

        const uint32_t base = sb + (c & 1) * HSTAGE;
#pragma unroll
        for (int kc = 0; kc < 2; kc++) {
            // B fragments for this warp's 32 columns (2 n16 groups, hi+lo)
            uint32_t bfq[2][2][4];
#pragma unroll
            for (int hl = 0; hl < 2; hl++)
#pragma unroll
                for (int nt = 0; nt < 2; nt++) {
                    uint32_t addr = base + 16384 + hl * 8192 +
                                    (((nw * 2 + nt) << 1) + kc) * 512 + b_in;
                    ldm_x4(bfq[hl][nt], addr);
                }
            // A fragments loaded per-mt to keep live registers low
#pragma unroll
            for (int mt = 0; mt < 4; mt++) {
                uint32_t afh[4], afl[4];
                uint32_t arow = (((mw * 4 + mt) << 1) + kc) * 512 + a_in;
                ldm_x4(afh, base + arow);
                ldm_x4(afl, base + 8192 + arow);
#pragma unroll
                for (int nt = 0; nt < 2; nt++)
#pragma unroll
                    for (int hf = 0; hf < 2; hf++) {
                        float* d = acc[mt][nt * 2 + hf];
                        mma16816(d, afh, bfq[0][nt][hf * 2], bfq[0][nt][hf * 2 + 1]);
                        mma16816(d, afh, bfq[1][nt][hf * 2], bfq[1][nt][hf * 2 + 1]);
                        mma16816(d, afl, bfq[0][nt][hf * 2], bfq[0][nt][hf * 2 + 1]);
                    }
            }
        }
        __syncthreads();
        if (c + 2 < NKCH) issue(c & 1, c + 2);
    }

    // epilogue
    const int row_in = lane >> 2;
    const int col_in = (lane & 3) * 2;
#pragma unroll
    for (int mt = 0; mt < 4; mt++) {
#pragma unroll
        for (int j = 0; j < 4; j++) {
            const int c = n0 + nw * 32 + j * 8 + col_in;
            const float b0v = bias[c], b1v = bias[c + 1];
#pragma unroll
            for (int hf = 0; hf < 2; hf++) {
                const int m = m0 + mw * 64 + mt * 16 + row_in + hf * 8;
                float v0 = acc[mt][j][hf * 2 + 0] + b0v;
                float v1 = acc[mt][j][hf * 2 + 1] + b1v;
                if (EPI == 0) {
                    int which = c / C_;
                    int cc = c - which * C_;
                    int h = cc >> 6, d = cc & 63;
                    int b = m >> 10, tt = m & 1023;
                    __nv_bfloat16* dh = (which == 0) ? g_qhi : ((which == 1) ? g_khi : g_vhi);
                    __nv_bfloat16* dl = (which == 0) ? g_qlo : ((which == 1) ? g_klo : g_vlo);
                    size_t o = ((size_t)(b * H_ + h) * T_ + tt) * HD_ + d;
                    float h0 = __bfloat162float(__float2bfloat16(v0));
                    float h1 = __bfloat162float(__float2bfloat16(v1));
                    *(uint32_t*)&dh[o] = packbf(v0, v1);
                    *(uint32_t*)&dl[o] = packbf(v0 - h0, v1 - h1);
                } else {
                    *(float2*)&Cout[(size_t)m * N + c] = make_float2(v0, v1);
                }
            }
        }
    }
}

// ---------------------------------------------------------------------------
// HMMA flash attention, causal. Grid (16 q-tiles, 96 bh), 128 threads (4 warps).
// cp.async double-buffered K/V stages (32KB each); Q at +64KB. (round-6 proven)
// ---------------------------------------------------------------------------
#define ATT_SMEM (2 * 32768 + 16384)

__global__ __launch_bounds__(128)
void attn_mma_kernel()
{
    extern __shared__ char smem[];
    const uint32_t sb = smem_to_u32(smem);
    const int tid = threadIdx.x, lane = tid & 31, w = tid >> 5;
    const int qt = blockIdx.x, bh = blockIdx.y;
    const int q0 = qt * 64;
    const size_t base = (size_t)bh * T_ * HD_;

    auto issue_kv = [&](int stage, int kt) {
        const int k0 = kt * 64;
        const uint32_t sbase = sb + stage * 32768;
#pragma unroll
        for (int it = 0; it < 16; it++) {
            int idx = it * 128 + tid;       // 0..2047
            int tile = idx >> 9;            // 0..3
            int rem = idx & 511;
            int r = rem >> 3, u = rem & 7;  // r 0..63, u 0..7
            const __nv_bfloat16* src = (tile == 0) ? g_khi : (tile == 1) ? g_klo
                                      : (tile == 2) ? g_vhi : g_vlo;
            cp16(sbase + tile * 8192 + SWZ(r * 128 + u * 16),
                 src + base + (size_t)(k0 + r) * HD_ + u * 8);
        }
        CP_COMMIT();
    };

    issue_kv(0, 0);
    if (qt >= 1) issue_kv(1, 1);

    // ---- load Q tiles (hi/lo) with plain stores, build fragments ----
#pragma unroll
    for (int half = 0; half < 2; half++) {
        const __nv_bfloat16* src = half ? g_qlo : g_qhi;
        uint32_t dstb = 65536 + half * 8192;
#pragma unroll
        for (int it = 0; it < 4; it++) {
            int idx = it * 128 + tid;
            int r = idx >> 3, u = idx & 7;
            uint4 v = *(const uint4*)(src + base + (size_t)(q0 + r) * HD_ + u * 8);
            *(uint4*)(smem + dstb + SWZ(r * 128 + u * 16)) = v;
        }
    }
    __syncthreads();

    uint32_t qh[4][4], ql[4][4];
    {
        uint32_t rowb = (uint32_t)(16 * w + (lane & 7) + ((lane >> 3) & 1) * 8) * 128;
#pragma unroll
        for (int ks = 0; ks < 4; ks++) {
            uint32_t cb = ks * 32 + (lane >> 4) * 16;
            ldm_x4(qh[ks], sb + 65536 + SWZ(rowb + cb));
            ldm_x4(ql[ks], sb + 73728 + SWZ(rowb + cb));
        }
    }

    float oacc[8][4];
#pragma unroll
    for (int i = 0; i < 8; i++)
#pragma unroll
        for (int j = 0; j < 4; j++) oacc[i][j] = 0.f;
    float m_s[2] = {-1e30f, -1e30f};
    float l_s[2] = {0.f, 0.f};

    const int rlo = q0 + 16 * w + (lane >> 2);
    const int rhi = rlo + 8;

    for (int kt = 0; kt <= qt; kt++) {
        const int k0 = kt * 64;
        if (kt < qt) { CP_WAIT1(); } else { CP_WAIT0(); }
        __syncthreads();
        const uint32_t stg = sb + (kt & 1) * 32768;

        // ---- S = Q K^T (hi/lo 3-MMA) ----
        float sacc[8][4];
#pragma unroll
        for (int i = 0; i < 8; i++)
#pragma unroll
            for (int j = 0; j < 4; j++) sacc[i][j] = 0.f;

#pragma unroll
        for (int kt16 = 0; kt16 < 4; kt16++) {
            uint32_t rowb = (uint32_t)(kt16 * 16 + (lane & 7) + (lane >> 4) * 8) * 128;
#pragma unroll
            for (int ks = 0; ks < 4; ks++) {
                uint32_t cb = ks * 32 + ((lane >> 3) & 1) * 16;
                uint32_t kh[4], kl[4];
                ldm_x4(kh, stg + 0    + SWZ(rowb + cb));
                ldm_x4(kl, stg + 8192 + SWZ(rowb + cb));
#pragma unroll
                for (int sub = 0; sub < 2; sub++) {
                    float* d = sacc[kt16 * 2 + sub];
                    mma16816(d, qh[ks], kh[sub * 2], kh[sub * 2 + 1]);
                    mma16816(d, qh[ks], kl[sub * 2], kl[sub * 2 + 1]);
                    mma16816(d, ql[ks], kh[sub * 2], kh[sub * 2 + 1]);
                }
            }
        }

        // ---- scale + causal mask ----
#pragma unroll
        for (int nt = 0; nt < 8; nt++) {
            int cb0 = k0 + nt * 8 + (lane & 3) * 2;
#pragma unroll
            for (int j = 0; j < 4; j++) sacc[nt][j] *= 0.125f;
            if (kt == qt) {
                if (cb0 > rlo)     sacc[nt][0] = -1e30f;
                if (cb0 + 1 > rlo) sacc[nt][1] = -1e30f;
                if (cb0 > rhi)     sacc[nt][2] = -1e30f;
                if (cb0 + 1 > rhi) sacc[nt][3] = -1e30f;
            }
        }

        // ---- online softmax (register, quad shfl reductions) ----
        float tmax0 = -1e30f, tmax1 = -1e30f;
#pragma unroll
        for (int nt = 0; nt < 8; nt++) {
            tmax0 = fmaxf(tmax0, fmaxf(sacc[nt][0], sacc[nt][1]));
            tmax1 = fmaxf(tmax1, fmaxf(sacc[nt][2], sacc[nt][3]));
        }
        tmax0 = fmaxf(tmax0, __shfl_xor_sync(0xffffffff, tmax0, 1));
        tmax0 = fmaxf(tmax0, __shfl_xor_sync(0xffffffff, tmax0, 2));
        tmax1 = fmaxf(tmax1, __shfl_xor_sync(0xffffffff, tmax1, 1));
        tmax1 = fmaxf(tmax1, __shfl_xor_sync(0xffffffff, tmax1, 2));
        float nm0 = fmaxf(m_s[0], tmax0), nm1 = fmaxf(m_s[1], tmax1);
        float al0 = __expf(m_s[0] - nm0), al1 = __expf(m_s[1] - nm1);
        m_s[0] = nm0; m_s[1] = nm1;

        float rs0 = 0.f, rs1 = 0.f;
#pragma unroll
        for (int nt = 0; nt < 8; nt++) {
            sacc[nt][0] = __expf(sacc[nt][0] - nm0);
            sacc[nt][1] = __expf(sacc[nt][1] - nm0);
            sacc[nt][2] = __expf(sacc[nt][2] - nm1);
            sacc[nt][3] = __expf(sacc[nt][3] - nm1);
            rs0 += sacc[nt][0] + sacc[nt][1];
            rs1 += sacc[nt][2] + sacc[nt][3];
        }
        rs0 += __shfl_xor_sync(0xffffffff, rs0, 1);
        rs0 += __shfl_xor_sync(0xffffffff, rs0, 2);
        rs1 += __shfl_xor_sync(0xffffffff, rs1, 1);
        rs1 += __shfl_xor_sync(0xffffffff, rs1, 2);
        l_s[0] = l_s[0] * al0 + rs0;
        l_s[1] = l_s[1] * al1 + rs1;

#pragma unroll
        for (int nt = 0; nt < 8; nt++) {
            oacc[nt][0] *= al0; oacc[nt][1] *= al0;
            oacc[nt][2] *= al1; oacc[nt][3] *= al1;
        }

        // ---- P fragments (hi/lo) ----
        uint32_t ph[4][4], pl[4][4];
#pragma unroll
        for (int ks = 0; ks < 4; ks++) {
            const float* t0 = sacc[2 * ks];
            const float* t1 = sacc[2 * ks + 1];
            float h00 = __bfloat162float(__float2bfloat16(t0[0]));
            float h01 = __bfloat162float(__float2bfloat16(t0[1]));
            float h02 = __bfloat162float(__float2bfloat16(t0[2]));
            float h03 = __bfloat162float(__float2bfloat16(t0[3]));
            float h10 = __bfloat162float(__float2bfloat16(t1[0]));
            float h11 = __bfloat162float(__float2bfloat16(t1[1]));
            float h12 = __bfloat162float(__float2bfloat16(t1[2]));
            float h13 = __bfloat162float(__float2bfloat16(t1[3]));
            ph[ks][0] = packbf(t0[0], t0[1]);
            ph[ks][1] = packbf(t0[2], t0[3]);
            ph[ks][2] = packbf(t1[0], t1[1]);
            ph[ks][3] = packbf(t1[2], t1[3]);
            pl[ks][0] = packbf(t0[0] - h00, t0[1] - h01);
            pl[ks][1] = packbf(t0[2] - h02, t0[3] - h03);
            pl[ks][2] = packbf(t1[0] - h10, t1[1] - h11);
            pl[ks][3] = packbf(t1[2] - h12, t1[3] - h13);
        }

        // ---- O += P V (hi/lo 3-MMA, V via ldmatrix.trans) ----
#pragma unroll
        for (int ks = 0; ks < 4; ks++) {
            uint32_t rowb = (uint32_t)(ks * 16 + (lane & 7) + ((lane >> 3) & 1) * 8) * 128;
#pragma unroll
            for (int np = 0; np < 4; np++) {
                uint32_t cb = np * 32 + (lane >> 4) * 16;
                uint32_t vh[4], vl[4];
                ldm_x4_t(vh, stg + 16384 + SWZ(rowb + cb));
                ldm_x4_t(vl, stg + 24576 + SWZ(rowb + cb));
#pragma unroll
                for (int sub = 0; sub < 2; sub++) {
                    float* d = oacc[np * 2 + sub];
                    mma16816(d, ph[ks], vh[sub * 2], vh[sub * 2 + 1]);
                    mma16816(d, ph[ks], vl[sub * 2], vl[sub * 2 + 1]);
                    mma16816(d, pl[ks], vh[sub * 2], vh[sub * 2 + 1]);
                }
            }
        }
        __syncthreads();
        if (kt + 2 <= qt) issue_kv(kt & 1, kt + 2);
    }

    // ---- epilogue: y (bf16 hi/lo) into [B,T,C], merging heads ----
    float inv0 = 1.f / l_s[0], inv1 = 1.f / l_s[1];
    int b = bh / H_, h = bh - b * H_;
    const int col = h * 64 + (lane & 3) * 2;
#pragma unroll
    for (int nt = 0; nt < 8; nt++) {
        float y0 = oacc[nt][0] * inv0, y1 = oacc[nt][1] * inv0;
        float y2 = oacc[nt][2] * inv1, y3 = oacc[nt][3] * inv1;
        size_t o0 = ((size_t)b * T_ + rlo) * C_ + col + nt * 8;
        size_t o1 = ((size_t)b * T_ + rhi) * C_ + col + nt * 8;
        float h0 = __bfloat162float(__float2bfloat16(y0));
        float h1 = __bfloat162float(__float2bfloat16(y1));
        float h2 = __bfloat162float(__float2bfloat16(y2));
        float h3 = __bfloat162float(__float2bfloat16(y3));
        *(uint32_t*)&g_yhi[o0] = packbf(y0, y1);
        *(uint32_t*)&g_ylo[o0] = packbf(y0 - h0, y1 - h1);
        *(uint32_t*)&g_yhi[o1] = packbf(y2, y3);
        *(uint32_t*)&g_ylo[o1] = packbf(y2 - h2, y3 - h3);
    }
}

// ---------------------------------------------------------------------------
extern "C" void kernel_launch(void* const* d_in, const int* in_sizes, int n_in,
                              void* d_out, int out_size)
{
    (void)in_sizes; (void)n_in; (void)out_size;
    const float* x      = (const float*)d_in[0];
    const float* W_attn = (const float*)d_in[1];
    const float* b_attn = (const float*)d_in[2];
    const float* W_proj = (const float*)d_in[3];
    const float* b_proj = (const float*)d_in[4];
    float* out = (float*)d_out;

    // conversions
    split_x_kernel<<<(M_ROWS * K_) / 256, 256>>>(x);
    split_tr_kernel<0><<<dim3(QKV_N / 32, K_ / 32), 256>>>(W_attn, K_, QKV_N);
    split_tr_kernel<1><<<dim3(C_ / 32, K_ / 32), 256>>>(W_proj, K_, C_);

    constexpr int SMH = 2 * HSTAGE;   // 64 KB

    // 1) QKV GEMM (HMMA, 128x128 tiles, 2 CTAs/SM) -> q/k/v bf16 hi/lo
    cudaFuncSetAttribute(hgemm<0>,
                         cudaFuncAttributeMaxDynamicSharedMemorySize, SMH);
    hgemm<0><<<dim3(QKV_N / 128, M_ROWS / 128), 256, SMH>>>(b_attn, nullptr, QKV_N);

    // 2) causal flash attention (HMMA, cp.async) -> g_yhi/g_ylo [B,T,C]
    cudaFuncSetAttribute(attn_mma_kernel,
                         cudaFuncAttributeMaxDynamicSharedMemorySize, ATT_SMEM);
    attn_mma_kernel<<<dim3(T_ / 64, B_ * H_), 128, ATT_SMEM>>>();

    // 3) output projection (HMMA)
    cudaFuncSetAttribute(hgemm<1>,
                         cudaFuncAttributeMaxDynamicSharedMemorySize, SMH);
    hgemm<1><<<dim3(C_ / 128, M_ROWS / 128), 256, SMH>>>(b_proj, out, C_);
}

// round 8
// speedup vs baseline: 3.9978x; 1.2621x over previous
#include <cuda_runtime.h>
#include <cuda_fp16.h>
#include <cstdint>
#include <cstddef>

// ---------------------------------------------------------------------------
// MultiHeadAttention: y = proj( causal_attention( x @ W_attn + b_attn ) )
// B=8, T=1024, C=768, H=12, hd=64
// All matmuls on HMMA fp16 with 2-MMA scheme: activations split hi/lo fp16,
// weights/K/V single fp16  ->  error ~= weight-quantization only (~2.8e-4).
// cp.async double-buffered pipelines; hgemm tuned for 2 CTAs/SM.
// ---------------------------------------------------------------------------

#define B_  8
#define T_  1024
#define C_  768
#define H_  12
#define HD_ 64
#define M_ROWS (B_ * T_)          // 8192
#define QKV_N  (3 * C_)           // 2304
#define K_     C_                 // 768

// ---------------- device scratch (no allocation allowed) -------------------
__device__ __half g_qh[B_ * H_ * T_ * HD_], g_ql[B_ * H_ * T_ * HD_];
__device__ __half g_kh[B_ * H_ * T_ * HD_];
__device__ __half g_vh[B_ * H_ * T_ * HD_];

__device__ __half g_xh[M_ROWS * K_], g_xl[M_ROWS * K_];
__device__ __half g_yh[M_ROWS * K_], g_yl[M_ROWS * K_];   // attn out
__device__ __half g_wah[QKV_N * K_];                      // W_attn^T [N,K]
__device__ __half g_wph[C_ * K_];                         // W_proj^T [N,K]

// ---------------- small PTX helpers (sm_80-level only) ---------------------
__device__ __forceinline__ uint32_t smem_to_u32(const void* p) {
    uint32_t a;
    asm("{ .reg .u64 t; cvta.to.shared.u64 t, %1; cvt.u32.u64 %0, t; }"
        : "=r"(a) : "l"(p));
    return a;
}
__device__ __forceinline__ void ldm_x4(uint32_t* r, uint32_t addr) {
    asm volatile("ldmatrix.sync.aligned.m8n8.x4.shared.b16 {%0,%1,%2,%3}, [%4];"
                 : "=r"(r[0]), "=r"(r[1]), "=r"(r[2]), "=r"(r[3]) : "r"(addr));
}
__device__ __forceinline__ void ldm_x4_t(uint32_t* r, uint32_t addr) {
    asm volatile("ldmatrix.sync.aligned.m8n8.x4.trans.shared.b16 {%0,%1,%2,%3}, [%4];"
                 : "=r"(r[0]), "=r"(r[1]), "=r"(r[2]), "=r"(r[3]) : "r"(addr));
}
__device__ __forceinline__ void mma16816(float* d, const uint32_t* a,
                                         uint32_t b0, uint32_t b1) {
    asm volatile(
        "mma.sync.aligned.m16n8k16.row.col.f32.f16.f16.f32 "
        "{%0,%1,%2,%3}, {%4,%5,%6,%7}, {%8,%9}, {%0,%1,%2,%3};"
        : "+f"(d[0]), "+f"(d[1]), "+f"(d[2]), "+f"(d[3])
        : "r"(a[0]), "r"(a[1]), "r"(a[2]), "r"(a[3]), "r"(b0), "r"(b1));
}
__device__ __forceinline__ uint32_t packh(float lo, float hi) {
    __half2 t = __floats2half2_rn(lo, hi);
    return *(uint32_t*)&t;
}
__device__ __forceinline__ void cp16(uint32_t dst, const void* src) {
    asm volatile("cp.async.cg.shared.global [%0], [%1], 16;"
                 :: "r"(dst), "l"(src));
}
#define CP_COMMIT() asm volatile("cp.async.commit_group;" ::: "memory")
#define CP_WAIT1()  asm volatile("cp.async.wait_group 1;" ::: "memory")
#define CP_WAIT0()  asm volatile("cp.async.wait_group 0;" ::: "memory")
#define SWZ(b) ((b) ^ (((b) >> 3) & 0x70))
#define SUBT(r, u) ((((r) >> 4 << 1) + ((u) >> 1)) * 512 + ((r) & 15) * 32 + ((u) & 1) * 16)

// ---------------------------------------------------------------------------
// Split / conversion kernels
// ---------------------------------------------------------------------------
__global__ void split_x_kernel(const float* __restrict__ s) {
    int i = blockIdx.x * 256 + threadIdx.x;
    float a = s[i];
    __half h = __float2half_rn(a);
    g_xh[i] = h;
    g_xl[i] = __float2half_rn(a - __half2float(h));
}
// transpose [K,N] fp32 -> [N,K] fp16 (single precision level: weights)
template <int W>
__global__ void split_tr_kernel(const float* __restrict__ s, int Kd, int Nd) {
    __shared__ float t[32][33];
    int nb = blockIdx.x * 32, kb = blockIdx.y * 32;
    int tx = threadIdx.x & 31, ty = threadIdx.x >> 5;   // 32 x 8
    for (int r = ty; r < 32; r += 8)
        t[r][tx] = s[(size_t)(kb + r) * Nd + nb + tx];
    __syncthreads();
    __half* hi = W ? g_wph : g_wah;
    for (int r = ty; r < 32; r += 8) {
        size_t o = (size_t)(nb + r) * Kd + kb + tx;
        hi[o] = __float2half_rn(t[tx][r]);
    }
}

// ---------------------------------------------------------------------------
// HMMA fp16 2-MMA GEMM: CTA 128x128, K-chunk 32, 8 warps (2m x 4n),
// warp tile 64x32. cp.async double-buffered, prefetch distance 2.
// SMEM stage: A(hi,lo) 16KB | B 8KB; 2 stages = 48KB/CTA -> 2 CTAs/SM.
// EPI==0: q hi/lo + k/v single fp16 [B,H,T,hd].  EPI==1: fp32 row-major out.
// ---------------------------------------------------------------------------
#define KCH    32
#define NKCH   (K_ / KCH)          // 24
#define HSTAGE 24576               // 8KB Ah + 8KB Al + 8KB B

template <int EPI>
__global__ __launch_bounds__(256, 2)
void hgemm(const float* __restrict__ bias, float* __restrict__ Cout, int N)
{
    extern __shared__ char smem[];
    const uint32_t sb = smem_to_u32(smem);
    const int tid  = threadIdx.x;
    const int lane = tid & 31;
    const int w    = tid >> 5;
    const int mw   = w & 1;        // 2 m-warps (64 rows each)
    const int nw   = w >> 1;       // 4 n-warps (32 cols each)
    const int n0 = blockIdx.x * 128;
    const int m0 = blockIdx.y * 128;

    const __half* Ahi = (EPI == 0) ? g_xh : g_yh;
    const __half* Alo = (EPI == 0) ? g_xl : g_yl;
    const __half* Bs  = (EPI == 0) ? g_wah : g_wph;

    float acc[4][4][4];           // [mt 16-row][j n8][quad]
#pragma unroll
    for (int i = 0; i < 4; i++)
#pragma unroll
        for (int j = 0; j < 4; j++)
#pragma unroll
            for (int q = 0; q < 4; q++) acc[i][j][q] = 0.f;

    auto issue = [&](int stage, int c) {
        const int kk = c * KCH;
        const uint32_t sbase = sb + stage * HSTAGE;
        // A hi/lo: 2 * 128 rows * 4 u = 1024 pieces (4 its)
#pragma unroll
        for (int it = 0; it < 4; it++) {
            int idx = it * 256 + tid;
            int hl = idx >> 9, rem = idx & 511;
            int r = rem >> 2, u = rem & 3;
            const __half* src = hl ? Alo : Ahi;
            cp16(sbase + hl * 8192 + SUBT(r, u),
                 src + (size_t)(m0 + r) * K_ + kk + u * 8);
        }
        // B single: 128 rows * 4 u = 512 pieces (2 its)
#pragma unroll
        for (int it = 0; it < 2; it++) {
            int idx = it * 256 + tid;
            int r = idx >> 2, u = idx & 3;
            cp16(sbase + 16384 + SUBT(r, u),
                 Bs + (size_t)(n0 + r) * K_ + kk + u * 8);
        }
        CP_COMMIT();
    };

    const uint32_t a_in = (lane & 15) * 32 + (lane >> 4) * 16;
    const uint32_t b_in = ((lane & 7) + (lane >> 4) * 8) * 32 + ((lane >> 3) & 1) * 16;

    issue(0, 0);
    issue(1, 1);

    for (int c = 0; c < NKCH; c++) {
        if (c + 1 < NKCH) { CP_WAIT1(); } else { CP_WAIT0(); }
        __syncthreads();

        const uint32_t base = sb + (c & 1) * HSTAGE;
#pragma unroll
        for (int kc = 0; kc < 2; kc++) {
            // B fragments for this warp's 32 columns (2 n16 groups)
            uint32_t bfq[2][4];
#pragma unroll
            for (int nt = 0; nt < 2; nt++) {
                uint32_t addr = base + 16384 +
                                (((nw * 2 + nt) << 1) + kc) * 512 + b_in;
                ldm_x4(bfq[nt], addr);
            }
            // A fragments loaded per-mt to keep live registers low
#pragma unroll
            for (int mt = 0; mt < 4; mt++) {
                uint32_t afh[4], afl[4];
                uint32_t arow = (((mw * 4 + mt) << 1) + kc) * 512 + a_in;
                ldm_x4(afh, base + arow);
                ldm_x4(afl, base + 8192 + arow);
#pragma unroll
                for (int nt = 0; nt < 2; nt++)
#pragma unroll
                    for (int hf = 0; hf < 2; hf++) {
                        float* d = acc[mt][nt * 2 + hf];
                        mma16816(d, afh, bfq[nt][hf * 2], bfq[nt][hf * 2 + 1]);
                        mma16816(d, afl, bfq[nt][hf * 2], bfq[nt][hf * 2 + 1]);
                    }
            }
        }
        __syncthreads();
        if (c + 2 < NKCH) issue(c & 1, c + 2);
    }

    // epilogue
    const int row_in = lane >> 2;
    const int col_in = (lane & 3) * 2;
#pragma unroll
    for (int mt = 0; mt < 4; mt++) {
#pragma unroll
        for (int j = 0; j < 4; j++) {
            const int c = n0 + nw * 32 + j * 8 + col_in;
            const float b0v = bias[c], b1v = bias[c + 1];
#pragma unroll
            for (int hf = 0; hf < 2; hf++) {
                const int m = m0 + mw * 64 + mt * 16 + row_in + hf * 8;
                float v0 = acc[mt][j][hf * 2 + 0] + b0v;
                float v1 = acc[mt][j][hf * 2 + 1] + b1v;
                if (EPI == 0) {
                    int which = c / C_;
                    int cc = c - which * C_;
                    int h = cc >> 6, d = cc & 63;
                    int b = m >> 10, tt = m & 1023;
                    size_t o = ((size_t)(b * H_ + h) * T_ + tt) * HD_ + d;
                    if (which == 0) {
                        float h0 = __half2float(__float2half_rn(v0));
                        float h1 = __half2float(__float2half_rn(v1));
                        *(uint32_t*)&g_qh[o] = packh(v0, v1);
                        *(uint32_t*)&g_ql[o] = packh(v0 - h0, v1 - h1);
                    } else if (which == 1) {
                        *(uint32_t*)&g_kh[o] = packh(v0, v1);
                    } else {
                        *(uint32_t*)&g_vh[o] = packh(v0, v1);
                    }
                } else {
                    *(float2*)&Cout[(size_t)m * N + c] = make_float2(v0, v1);
                }
            }
        }
    }
}

// ---------------------------------------------------------------------------
// HMMA flash attention, causal. Grid (16 q-tiles, 96 bh), 128 threads (4 warps).
// cp.async double-buffered K/V stages (16KB each: K 8K | V 8K); Q hi/lo at 32K.
// S = (Qh+Ql) K^T (2 MMAs), O += (Ph+Pl) V (2 MMAs). fp16 single K/V.
// ---------------------------------------------------------------------------
#define ATT_SMEM (2 * 16384 + 16384)

__global__ __launch_bounds__(128)
void attn_mma_kernel()
{
    extern __shared__ char smem[];
    const uint32_t sb = smem_to_u32(smem);
    const int tid = threadIdx.x, lane = tid & 31, w = tid >> 5;
    const int qt = blockIdx.x, bh = blockIdx.y;
    const int q0 = qt * 64;
    const size_t base = (size_t)bh * T_ * HD_;

    // 2 tiles (K, V), each 64 rows x 128B = 512 x 16B pieces -> 1024 pieces.
    auto issue_kv = [&](int stage, int kt) {
        const int k0 = kt * 64;
        const uint32_t sbase = sb + stage * 16384;
#pragma unroll
        for (int it = 0; it < 8; it++) {
            int idx = it * 128 + tid;       // 0..1023
            int tile = idx >> 9;            // 0..1
            int rem = idx & 511;
            int r = rem >> 3, u = rem & 7;  // r 0..63, u 0..7
            const __half* src = tile ? g_vh : g_kh;
            cp16(sbase + tile * 8192 + SWZ(r * 128 + u * 16),
                 src + base + (size_t)(k0 + r) * HD_ + u * 8);
        }
        CP_COMMIT();
    };

    issue_kv(0, 0);
    if (qt >= 1) issue_kv(1, 1);

    // ---- load Q tiles (hi/lo) with plain stores, build fragments ----
#pragma unroll
    for (int half = 0; half < 2; half++) {
        const __half* src = half ? g_ql : g_qh;
        uint32_t dstb = 32768 + half * 8192;
#pragma unroll
        for (int it = 0; it < 4; it++) {
            int idx = it * 128 + tid;
            int r = idx >> 3, u = idx & 7;
            uint4 v = *(const uint4*)(src + base + (size_t)(q0 + r) * HD_ + u * 8);
            *(uint4*)(smem + dstb + SWZ(r * 128 + u * 16)) = v;
        }
    }
    __syncthreads();

    uint32_t qh[4][4], ql[4][4];
    {
        uint32_t rowb = (uint32_t)(16 * w + (lane & 7) + ((lane >> 3) & 1) * 8) * 128;
#pragma unroll
        for (int ks = 0; ks < 4; ks++) {
            uint32_t cb = ks * 32 + (lane >> 4) * 16;
            ldm_x4(qh[ks], sb + 32768 + SWZ(rowb + cb));
            ldm_x4(ql[ks], sb + 40960 + SWZ(rowb + cb));
        }
    }

    float oacc[8][4];
#pragma unroll
    for (int i = 0; i < 8; i++)
#pragma unroll
        for (int j = 0; j < 4; j++) oacc[i][j] = 0.f;
    float m_s[2] = {-1e30f, -1e30f};
    float l_s[2] = {0.f, 0.f};

    const int rlo = q0 + 16 * w + (lane >> 2);
    const int rhi = rlo + 8;

    for (int kt = 0; kt <= qt; kt++) {
        const int k0 = kt * 64;
        if (kt < qt) { CP_WAIT1(); } else { CP_WAIT0(); }
        __syncthreads();
        const uint32_t stg = sb + (kt & 1) * 16384;

        // ---- S = Q K^T (2-MMA hi/lo) ----
        float sacc[8][4];
#pragma unroll
        for (int i = 0; i < 8; i++)
#pragma unroll
            for (int j = 0; j < 4; j++) sacc[i][j] = 0.f;

#pragma unroll
        for (int kt16 = 0; kt16 < 4; kt16++) {
            uint32_t rowb = (uint32_t)(kt16 * 16 + (lane & 7) + (lane >> 4) * 8) * 128;
#pragma unroll
            for (int ks = 0; ks < 4; ks++) {
                uint32_t cb = ks * 32 + ((lane >> 3) & 1) * 16;
                uint32_t kf[4];
                ldm_x4(kf, stg + SWZ(rowb + cb));
#pragma unroll
                for (int sub = 0; sub < 2; sub++) {
                    float* d = sacc[kt16 * 2 + sub];
                    mma16816(d, qh[ks], kf[sub * 2], kf[sub * 2 + 1]);
                    mma16816(d, ql[ks], kf[sub * 2], kf[sub * 2 + 1]);
                }
            }
        }

        // ---- scale + causal mask ----
#pragma unroll
        for (int nt = 0; nt < 8; nt++) {
            int cb0 = k0 + nt * 8 + (lane & 3) * 2;
#pragma unroll
            for (int j = 0; j < 4; j++) sacc[nt][j] *= 0.125f;
            if (kt == qt) {
                if (cb0 > rlo)     sacc[nt][0] = -1e30f;
                if (cb0 + 1 > rlo) sacc[nt][1] = -1e30f;
                if (cb0 > rhi)     sacc[nt][2] = -1e30f;
                if (cb0 + 1 > rhi) sacc[nt][3] = -1e30f;
            }
        }

        // ---- online softmax (register, quad shfl reductions) ----
        float tmax0 = -1e30f, tmax1 = -1e30f;
#pragma unroll
        for (int nt = 0; nt < 8; nt++) {
            tmax0 = fmaxf(tmax0, fmaxf(sacc[nt][0], sacc[nt][1]));
            tmax1 = fmaxf(tmax1, fmaxf(sacc[nt][2], sacc[nt][3]));
        }
        tmax0 = fmaxf(tmax0, __shfl_xor_sync(0xffffffff, tmax0, 1));
        tmax0 = fmaxf(tmax0, __shfl_xor_sync(0xffffffff, tmax0, 2));
        tmax1 = fmaxf(tmax1, __shfl_xor_sync(0xffffffff, tmax1, 1));
        tmax1 = fmaxf(tmax1, __shfl_xor_sync(0xffffffff, tmax1, 2));
        float nm0 = fmaxf(m_s[0], tmax0), nm1 = fmaxf(m_s[1], tmax1);
        float al0 = __expf(m_s[0] - nm0), al1 = __expf(m_s[1] - nm1);
        m_s[0] = nm0; m_s[1] = nm1;

        float rs0 = 0.f, rs1 = 0.f;
#pragma unroll
        for (int nt = 0; nt < 8; nt++) {
            sacc[nt][0] = __expf(sacc[nt][0] - nm0);
            sacc[nt][1] = __expf(sacc[nt][1] - nm0);
            sacc[nt][2] = __expf(sacc[nt][2] - nm1);
            sacc[nt][3] = __expf(sacc[nt][3] - nm1);
            rs0 += sacc[nt][0] + sacc[nt][1];
            rs1 += sacc[nt][2] + sacc[nt][3];
        }
        rs0 += __shfl_xor_sync(0xffffffff, rs0, 1);
        rs0 += __shfl_xor_sync(0xffffffff, rs0, 2);
        rs1 += __shfl_xor_sync(0xffffffff, rs1, 1);
        rs1 += __shfl_xor_sync(0xffffffff, rs1, 2);
        l_s[0] = l_s[0] * al0 + rs0;
        l_s[1] = l_s[1] * al1 + rs1;

#pragma unroll
        for (int nt = 0; nt < 8; nt++) {
            oacc[nt][0] *= al0; oacc[nt][1] *= al0;
            oacc[nt][2] *= al1; oacc[nt][3] *= al1;
        }

        // ---- P fragments (fp16 hi/lo) ----
        uint32_t ph[4][4], pl[4][4];
#pragma unroll
        for (int ks = 0; ks < 4; ks++) {
            const float* t0 = sacc[2 * ks];
            const float* t1 = sacc[2 * ks + 1];
            float h00 = __half2float(__float2half_rn(t0[0]));
            float h01 = __half2float(__float2half_rn(t0[1]));
            float h02 = __half2float(__float2half_rn(t0[2]));
            float h03 = __half2float(__float2half_rn(t0[3]));
            float h10 = __half2float(__float2half_rn(t1[0]));
            float h11 = __half2float(__float2half_rn(t1[1]));
            float h12 = __half2float(__float2half_rn(t1[2]));
            float h13 = __half2float(__float2half_rn(t1[3]));
            ph[ks][0] = packh(t0[0], t0[1]);
            ph[ks][1] = packh(t0[2], t0[3]);
            ph[ks][2] = packh(t1[0], t1[1]);
            ph[ks][3] = packh(t1[2], t1[3]);
            pl[ks][0] = packh(t0[0] - h00, t0[1] - h01);
            pl[ks][1] = packh(t0[2] - h02, t0[3] - h03);
            pl[ks][2] = packh(t1[0] - h10, t1[1] - h11);
            pl[ks][3] = packh(t1[2] - h12, t1[3] - h13);
        }

        // ---- O += P V (2-MMA hi/lo, V via ldmatrix.trans) ----
#pragma unroll
        for (int ks = 0; ks < 4; ks++) {
            uint32_t rowb = (uint32_t)(ks * 16 + (lane & 7) + ((lane >> 3) & 1) * 8) * 128;
#pragma unroll
            for (int np = 0; np < 4; np++) {
                uint32_t cb = np * 32 + (lane >> 4) * 16;
                uint32_t vf[4];
                ldm_x4_t(vf, stg + 8192 + SWZ(rowb + cb));
#pragma unroll
                for (int sub = 0; sub < 2; sub++) {
                    float* d = oacc[np * 2 + sub];
                    mma16816(d, ph[ks], vf[sub * 2], vf[sub * 2 + 1]);
                    mma16816(d, pl[ks], vf[sub * 2], vf[sub * 2 + 1]);
                }
            }
        }
        __syncthreads();
        if (kt + 2 <= qt) issue_kv(kt & 1, kt + 2);
    }

    // ---- epilogue: y (fp16 hi/lo) into [B,T,C], merging heads ----
    float inv0 = 1.f / l_s[0], inv1 = 1.f / l_s[1];
    int b = bh / H_, h = bh - b * H_;
    const int col = h * 64 + (lane & 3) * 2;
#pragma unroll
    for (int nt = 0; nt < 8; nt++) {
        float y0 = oacc[nt][0] * inv0, y1 = oacc[nt][1] * inv0;
        float y2 = oacc[nt][2] * inv1, y3 = oacc[nt][3] * inv1;
        size_t o0 = ((size_t)b * T_ + rlo) * C_ + col + nt * 8;
        size_t o1 = ((size_t)b * T_ + rhi) * C_ + col + nt * 8;
        float h0 = __half2float(__float2half_rn(y0));
        float h1 = __half2float(__float2half_rn(y1));
        float h2 = __half2float(__float2half_rn(y2));
        float h3 = __half2float(__float2half_rn(y3));
        *(uint32_t*)&g_yh[o0] = packh(y0, y1);
        *(uint32_t*)&g_yl[o0] = packh(y0 - h0, y1 - h1);
        *(uint32_t*)&g_yh[o1] = packh(y2, y3);
        *(uint32_t*)&g_yl[o1] = packh(y2 - h2, y3 - h3);
    }
}

// ---------------------------------------------------------------------------
extern "C" void kernel_launch(void* const* d_in, const int* in_sizes, int n_in,
                              void* d_out, int out_size)
{
    (void)in_sizes; (void)n_in; (void)out_size;
    const float* x      = (const float*)d_in[0];
    const float* W_attn = (const float*)d_in[1];
    const float* b_attn = (const float*)d_in[2];
    const float* W_proj = (const float*)d_in[3];
    const float* b_proj = (const float*)d_in[4];
    float* out = (float*)d_out;

    // conversions
    split_x_kernel<<<(M_ROWS * K_) / 256, 256>>>(x);
    split_tr_kernel<0><<<dim3(QKV_N / 32, K_ / 32), 256>>>(W_attn, K_, QKV_N);
    split_tr_kernel<1><<<dim3(C_ / 32, K_ / 32), 256>>>(W_proj, K_, C_);

    constexpr int SMH = 2 * HSTAGE;   // 48 KB

    // 1) QKV GEMM (HMMA fp16 2-MMA, 2 CTAs/SM) -> q hi/lo, k/v single fp16
    cudaFuncSetAttribute(hgemm<0>,
                         cudaFuncAttributeMaxDynamicSharedMemorySize, SMH);
    hgemm<0><<<dim3(QKV_N / 128, M_ROWS / 128), 256, SMH>>>(b_attn, nullptr, QKV_N);

    // 2) causal flash attention (HMMA fp16 2-MMA, cp.async) -> g_yh/g_yl
    cudaFuncSetAttribute(attn_mma_kernel,
                         cudaFuncAttributeMaxDynamicSharedMemorySize, ATT_SMEM);
    attn_mma_kernel<<<dim3(T_ / 64, B_ * H_), 128, ATT_SMEM>>>();

    // 3) output projection (HMMA fp16 2-MMA)
    cudaFuncSetAttribute(hgemm<1>,
                         cudaFuncAttributeMaxDynamicSharedMemorySize, SMH);
    hgemm<1><<<dim3(C_ / 128, M_ROWS / 128), 256, SMH>>>(b_proj, out, C_);
}

// round 9
// speedup vs baseline: 4.0652x; 1.0169x over previous
#include <cuda_runtime.h>
#include <cuda_fp16.h>
#include <cstdint>
#include <cstddef>

// ---------------------------------------------------------------------------
// MultiHeadAttention: y = proj( causal_attention( x @ W_attn + b_attn ) )
// B=8, T=1024, C=768, H=12, hd=64
// All matmuls on HMMA fp16 2-MMA (activations split hi/lo, weights single).
// 3-stage cp.async pipelines, single barrier per chunk, hi/lo MMA passes split.
// ---------------------------------------------------------------------------

#define B_  8
#define T_  1024
#define C_  768
#define H_  12
#define HD_ 64
#define M_ROWS (B_ * T_)          // 8192
#define QKV_N  (3 * C_)           // 2304
#define K_     C_                 // 768

// ---------------- device scratch (no allocation allowed) -------------------
__device__ __half g_qh[B_ * H_ * T_ * HD_], g_ql[B_ * H_ * T_ * HD_];
__device__ __half g_kh[B_ * H_ * T_ * HD_];
__device__ __half g_vh[B_ * H_ * T_ * HD_];

__device__ __half g_xh[M_ROWS * K_], g_xl[M_ROWS * K_];
__device__ __half g_yh[M_ROWS * K_], g_yl[M_ROWS * K_];   // attn out
__device__ __half g_wah[QKV_N * K_];                      // W_attn^T [N,K]
__device__ __half g_wph[C_ * K_];                         // W_proj^T [N,K]

// ---------------- small PTX helpers (sm_80-level only) ---------------------
__device__ __forceinline__ uint32_t smem_to_u32(const void* p) {
    uint32_t a;
    asm("{ .reg .u64 t; cvta.to.shared.u64 t, %1; cvt.u32.u64 %0, t; }"
        : "=r"(a) : "l"(p));
    return a;
}
__device__ __forceinline__ void ldm_x4(uint32_t* r, uint32_t addr) {
    asm volatile("ldmatrix.sync.aligned.m8n8.x4.shared.b16 {%0,%1,%2,%3}, [%4];"
                 : "=r"(r[0]), "=r"(r[1]), "=r"(r[2]), "=r"(r[3]) : "r"(addr));
}
__device__ __forceinline__ void ldm_x4_t(uint32_t* r, uint32_t addr) {
    asm volatile("ldmatrix.sync.aligned.m8n8.x4.trans.shared.b16 {%0,%1,%2,%3}, [%4];"
                 : "=r"(r[0]), "=r"(r[1]), "=r"(r[2]), "=r"(r[3]) : "r"(addr));
}
__device__ __forceinline__ void mma16816(float* d, const uint32_t* a,
                                         uint32_t b0, uint32_t b1) {
    asm volatile(
        "mma.sync.aligned.m16n8k16.row.col.f32.f16.f16.f32 "
        "{%0,%1,%2,%3}, {%4,%5,%6,%7}, {%8,%9}, {%0,%1,%2,%3};"
        : "+f"(d[0]), "+f"(d[1]), "+f"(d[2]), "+f"(d[3])
        : "r"(a[0]), "r"(a[1]), "r"(a[2]), "r"(a[3]), "r"(b0), "r"(b1));
}
__device__ __forceinline__ uint32_t packh(float lo, float hi) {
    __half2 t = __floats2half2_rn(lo, hi);
    return *(uint32_t*)&t;
}
__device__ __forceinline__ void cp16(uint32_t dst, const void* src) {
    asm volatile("cp.async.cg.shared.global [%0], [%1], 16;"
                 :: "r"(dst), "l"(src));
}
#define CP_COMMIT() asm volatile("cp.async.commit_group;" ::: "memory")
#define CP_WAIT1()  asm volatile("cp.async.wait_group 1;" ::: "memory")
#define CP_WAIT0()  asm volatile("cp.async.wait_group 0;" ::: "memory")
#define SWZ(b) ((b) ^ (((b) >> 3) & 0x70))
#define SUBT(r, u) ((((r) >> 4 << 1) + ((u) >> 1)) * 512 + ((r) & 15) * 32 + ((u) & 1) * 16)

// ---------------------------------------------------------------------------
// Split / conversion kernels
// ---------------------------------------------------------------------------
__global__ void split_x_kernel(const float* __restrict__ s) {
    int i = blockIdx.x * 256 + threadIdx.x;
    float a = s[i];
    __half h = __float2half_rn(a);
    g_xh[i] = h;
    g_xl[i] = __float2half_rn(a - __half2float(h));
}
// transpose [K,N] fp32 -> [N,K] fp16 (weights single precision)
template <int W>
__global__ void split_tr_kernel(const float* __restrict__ s, int Kd, int Nd) {
    __shared__ float t[32][33];
    int nb = blockIdx.x * 32, kb = blockIdx.y * 32;
    int tx = threadIdx.x & 31, ty = threadIdx.x >> 5;   // 32 x 8
    for (int r = ty; r < 32; r += 8)
        t[r][tx] = s[(size_t)(kb + r) * Nd + nb + tx];
    __syncthreads();
    __half* hi = W ? g_wph : g_wah;
    for (int r = ty; r < 32; r += 8) {
        size_t o = (size_t)(nb + r) * Kd + kb + tx;
        hi[o] = __float2half_rn(t[tx][r]);
    }
}

// ---------------------------------------------------------------------------
// HMMA fp16 2-MMA GEMM: CTA 128x128, K-chunk 32, 8 warps (2m x 4n),
// warp tile 64x32. 3-stage cp.async pipeline, ONE barrier per chunk.
// SMEM stage: Ah 8K | Al 8K | B 8K; 3 stages = 72KB/CTA -> 2 CTAs/SM.
// EPI==0: q hi/lo + k/v single fp16 [B,H,T,hd].  EPI==1: fp32 row-major out.
// ---------------------------------------------------------------------------
#define KCH    32
#define NKCH   (K_ / KCH)          // 24
#define HSTAGE 24576               // 8KB Ah + 8KB Al + 8KB B
#define SMH    (3 * HSTAGE)        // 73728

template <int EPI>
__global__ __launch_bounds__(256, 2)
void hgemm(const float* __restrict__ bias, float* __restrict__ Cout, int N)
{
    extern __shared__ char smem[];
    const uint32_t sb = smem_to_u32(smem);
    const int tid  = threadIdx.x;
    const int lane = tid & 31;
    const int w    = tid >> 5;
    const int mw   = w & 1;        // 2 m-warps (64 rows each)
    const int nw   = w >> 1;       // 4 n-warps (32 cols each)
    const int n0 = blockIdx.x * 128;
    const int m0 = blockIdx.y * 128;

    const __half* Ahi = (EPI == 0) ? g_xh : g_yh;
    const __half* Alo = (EPI == 0) ? g_xl : g_yl;
    const __half* Bs  = (EPI == 0) ? g_wah : g_wph;

    float acc[4][4][4];           // [mt 16-row][j n8][quad]
#pragma unroll
    for (int i = 0; i < 4; i++)
#pragma unroll
        for (int j = 0; j < 4; j++)
#pragma unroll
            for (int q = 0; q < 4; q++) acc[i][j][q] = 0.f;

    auto issue = [&](int stage, int c) {
        const int kk = c * KCH;
        const uint32_t sbase = sb + stage * HSTAGE;
#pragma unroll
        for (int it = 0; it < 4; it++) {
            int idx = it * 256 + tid;
            int hl = idx >> 9, rem = idx & 511;
            int r = rem >> 2, u = rem & 3;
            const __half* src = hl ? Alo : Ahi;
            cp16(sbase + hl * 8192 + SUBT(r, u),
                 src + (size_t)(m0 + r) * K_ + kk + u * 8);
        }
#pragma unroll
        for (int it = 0; it < 2; it++) {
            int idx = it * 256 + tid;
            int r = idx >> 2, u = idx & 3;
            cp16(sbase + 16384 + SUBT(r, u),
                 Bs + (size_t)(n0 + r) * K_ + kk + u * 8);
        }
        CP_COMMIT();
    };

    const uint32_t a_in = (lane & 15) * 32 + (lane >> 4) * 16;
    const uint32_t b_in = ((lane & 7) + (lane >> 4) * 8) * 32 + ((lane >> 3) & 1) * 16;

    issue(0, 0);
    issue(1, 1);

    for (int c = 0; c < NKCH; c++) {
        if (c + 1 < NKCH) { CP_WAIT1(); } else { CP_WAIT0(); }
        __syncthreads();
        if (c + 2 < NKCH) issue((c + 2) % 3, c + 2);

        const uint32_t base = sb + (c % 3) * HSTAGE;
#pragma unroll
        for (int kc = 0; kc < 2; kc++) {
            uint32_t bfq[2][4];
#pragma unroll
            for (int nt = 0; nt < 2; nt++) {
                uint32_t addr = base + 16384 +
                                (((nw * 2 + nt) << 1) + kc) * 512 + b_in;
                ldm_x4(bfq[nt], addr);
            }
#pragma unroll
            for (int mt = 0; mt < 4; mt++) {
                uint32_t afh[4], afl[4];
                uint32_t arow = (((mw * 4 + mt) << 1) + kc) * 512 + a_in;
                ldm_x4(afh, base + arow);
                ldm_x4(afl, base + 8192 + arow);
                // hi pass (4 independent accumulators)
#pragma unroll
                for (int nt = 0; nt < 2; nt++)
#pragma unroll
                    for (int hf = 0; hf < 2; hf++)
                        mma16816(acc[mt][nt * 2 + hf], afh,
                                 bfq[nt][hf * 2], bfq[nt][hf * 2 + 1]);
                // lo pass (same accumulators, RAW distance 4)
#pragma unroll
                for (int nt = 0; nt < 2; nt++)
#pragma unroll
                    for (int hf = 0; hf < 2; hf++)
                        mma16816(acc[mt][nt * 2 + hf], afl,
                                 bfq[nt][hf * 2], bfq[nt][hf * 2 + 1]);
            }
        }
        // no trailing barrier: next iteration's barrier protects stage reuse
    }

    // epilogue
    const int row_in = lane >> 2;
    const int col_in = (lane & 3) * 2;
#pragma unroll
    for (int mt = 0; mt < 4; mt++) {
#pragma unroll
        for (int j = 0; j < 4; j++) {
            const int c = n0 + nw * 32 + j * 8 + col_in;
            const float b0v = bias[c], b1v = bias[c + 1];
#pragma unroll
            for (int hf = 0; hf < 2; hf++) {
                const int m = m0 + mw * 64 + mt * 16 + row_in + hf * 8;
                float v0 = acc[mt][j][hf * 2 + 0] + b0v;
                float v1 = acc[mt][j][hf * 2 + 1] + b1v;
                if (EPI == 0) {
                    int which = c / C_;
                    int cc = c - which * C_;
                    int h = cc >> 6, d = cc & 63;
                    int b = m >> 10, tt = m & 1023;
                    size_t o = ((size_t)(b * H_ + h) * T_ + tt) * HD_ + d;
                    if (which == 0) {
                        float h0 = __half2float(__float2half_rn(v0));
                        float h1 = __half2float(__float2half_rn(v1));
                        *(uint32_t*)&g_qh[o] = packh(v0, v1);
                        *(uint32_t*)&g_ql[o] = packh(v0 - h0, v1 - h1);
                    } else if (which == 1) {
                        *(uint32_t*)&g_kh[o] = packh(v0, v1);
                    } else {
                        *(uint32_t*)&g_vh[o] = packh(v0, v1);
                    }
                } else {
                    *(float2*)&Cout[(size_t)m * N + c] = make_float2(v0, v1);
                }
            }
        }
    }
}

// ---------------------------------------------------------------------------
// HMMA flash attention, causal. Grid (16 q-tiles, 96 bh), 128 threads (4 warps).
// 3-stage cp.async K/V pipeline (16KB/stage: K 8K | V 8K), ONE barrier per kt.
// Q hi/lo at 48KB. S = (Qh+Ql) K^T, O += (Ph+Pl) V. fp16 single K/V.
// ---------------------------------------------------------------------------
#define ATT_SMEM (3 * 16384 + 16384)   // 65536

__global__ __launch_bounds__(128)
void attn_mma_kernel()
{
    extern __shared__ char smem[];
    const uint32_t sb = smem_to_u32(smem);
    const int tid = threadIdx.x, lane = tid & 31, w = tid >> 5;
    const int qt = blockIdx.x, bh = blockIdx.y;
    const int q0 = qt * 64;
    const size_t base = (size_t)bh * T_ * HD_;

    auto issue_kv = [&](int stage, int kt) {
        const int k0 = kt * 64;
        const uint32_t sbase = sb + stage * 16384;
#pragma unroll
        for (int it = 0; it < 8; it++) {
            int idx = it * 128 + tid;       // 0..1023
            int tile = idx >> 9;            // 0..1
            int rem = idx & 511;
            int r = rem >> 3, u = rem & 7;  // r 0..63, u 0..7
            const __half* src = tile ? g_vh : g_kh;
            cp16(sbase + tile * 8192 + SWZ(r * 128 + u * 16),
                 src + base + (size_t)(k0 + r) * HD_ + u * 8);
        }
        CP_COMMIT();
    };

    issue_kv(0, 0);
    if (qt >= 1) issue_kv(1, 1);

    // ---- load Q tiles (hi/lo) with plain stores, build fragments ----
#pragma unroll
    for (int half = 0; half < 2; half++) {
        const __half* src = half ? g_ql : g_qh;
        uint32_t dstb = 49152 + half * 8192;
#pragma unroll
        for (int it = 0; it < 4; it++) {
            int idx = it * 128 + tid;
            int r = idx >> 3, u = idx & 7;
            uint4 v = *(const uint4*)(src + base + (size_t)(q0 + r) * HD_ + u * 8);
            *(uint4*)(smem + dstb + SWZ(r * 128 + u * 16)) = v;
        }
    }
    __syncthreads();

    uint32_t qh[4][4], ql[4][4];
    {
        uint32_t rowb = (uint32_t)(16 * w + (lane & 7) + ((lane >> 3) & 1) * 8) * 128;
#pragma unroll
        for (int ks = 0; ks < 4; ks++) {
            uint32_t cb = ks * 32 + (lane >> 4) * 16;
            ldm_x4(qh[ks], sb + 49152 + SWZ(rowb + cb));
            ldm_x4(ql[ks], sb + 57344 + SWZ(rowb + cb));
        }
    }

    float oacc[8][4];
#pragma unroll
    for (int i = 0; i < 8; i++)
#pragma unroll
        for (int j = 0; j < 4; j++) oacc[i][j] = 0.f;
    float m_s[2] = {-1e30f, -1e30f};
    float l_s[2] = {0.f, 0.f};

    const int rlo = q0 + 16 * w + (lane >> 2);
    const int rhi = rlo + 8;

    for (int kt = 0; kt <= qt; kt++) {
        const int k0 = kt * 64;
        if (kt < qt) { CP_WAIT1(); } else { CP_WAIT0(); }
        __syncthreads();
        if (kt + 2 <= qt) issue_kv((kt + 2) % 3, kt + 2);
        const uint32_t stg = sb + (kt % 3) * 16384;

        // ---- S = Q K^T (2-MMA hi/lo, split passes) ----
        float sacc[8][4];
#pragma unroll
        for (int i = 0; i < 8; i++)
#pragma unroll
            for (int j = 0; j < 4; j++) sacc[i][j] = 0.f;

#pragma unroll
        for (int kt16 = 0; kt16 < 4; kt16++) {
            uint32_t rowb = (uint32_t)(kt16 * 16 + (lane & 7) + (lane >> 4) * 8) * 128;
            uint32_t kf[4][4];
#pragma unroll
            for (int ks = 0; ks < 4; ks++)
                ldm_x4(kf[ks], stg + SWZ(rowb + ks * 32 + ((lane >> 3) & 1) * 16));
            // qh pass
#pragma unroll
            for (int ks = 0; ks < 4; ks++)
#pragma unroll
                for (int sub = 0; sub < 2; sub++)
                    mma16816(sacc[kt16 * 2 + sub], qh[ks],
                             kf[ks][sub * 2], kf[ks][sub * 2 + 1]);
            // ql pass
#pragma unroll
            for (int ks = 0; ks < 4; ks++)
#pragma unroll
                for (int sub = 0; sub < 2; sub++)
                    mma16816(sacc[kt16 * 2 + sub], ql[ks],
                             kf[ks][sub * 2], kf[ks][sub * 2 + 1]);
        }

        // ---- scale + causal mask ----
#pragma unroll
        for (int nt = 0; nt < 8; nt++) {
            int cb0 = k0 + nt * 8 + (lane & 3) * 2;
#pragma unroll
            for (int j = 0; j < 4; j++) sacc[nt][j] *= 0.125f;
            if (kt == qt) {
                if (cb0 > rlo)     sacc[nt][0] = -1e30f;
                if (cb0 + 1 > rlo) sacc[nt][1] = -1e30f;
                if (cb0 > rhi)     sacc[nt][2] = -1e30f;
                if (cb0 + 1 > rhi) sacc[nt][3] = -1e30f;
            }
        }

        // ---- online softmax (register, quad shfl reductions) ----
        float tmax0 = -1e30f, tmax1 = -1e30f;
#pragma unroll
        for (int nt = 0; nt < 8; nt++) {
            tmax0 = fmaxf(tmax0, fmaxf(sacc[nt][0], sacc[nt][1]));
            tmax1 = fmaxf(tmax1, fmaxf(sacc[nt][2], sacc[nt][3]));
        }
        tmax0 = fmaxf(tmax0, __shfl_xor_sync(0xffffffff, tmax0, 1));
        tmax0 = fmaxf(tmax0, __shfl_xor_sync(0xffffffff, tmax0, 2));
        tmax1 = fmaxf(tmax1, __shfl_xor_sync(0xffffffff, tmax1, 1));
        tmax1 = fmaxf(tmax1, __shfl_xor_sync(0xffffffff, tmax1, 2));
        float nm0 = fmaxf(m_s[0], tmax0), nm1 = fmaxf(m_s[1], tmax1);
        float al0 = __expf(m_s[0] - nm0), al1 = __expf(m_s[1] - nm1);
        m_s[0] = nm0; m_s[1] = nm1;

        float rs0 = 0.f, rs1 = 0.f;
#pragma unroll
        for (int nt = 0; nt < 8; nt++) {
            sacc[nt][0] = __expf(sacc[nt][0] - nm0);
            sacc[nt][1] = __expf(sacc[nt][1] - nm0);
            sacc[nt][2] = __expf(sacc[nt][2] - nm1);
            sacc[nt][3] = __expf(sacc[nt][3] - nm1);
            rs0 += sacc[nt][0] + sacc[nt][1];
            rs1 += sacc[nt][2] + sacc[nt][3];
        }
        rs0 += __shfl_xor_sync(0xffffffff, rs0, 1);
        rs0 += __shfl_xor_sync(0xffffffff, rs0, 2);
        rs1 += __shfl_xor_sync(0xffffffff, rs1, 1);
        rs1 += __shfl_xor_sync(0xffffffff, rs1, 2);
        l_s[0] = l_s[0] * al0 + rs0;
        l_s[1] = l_s[1] * al1 + rs1;

#pragma unroll
        for (int nt = 0; nt < 8; nt++) {
            oacc[nt][0] *= al0; oacc[nt][1] *= al0;
            oacc[nt][2] *= al1; oacc[nt][3] *= al1;
        }

        // ---- P fragments (fp16 hi/lo) ----
        uint32_t ph[4][4], pl[4][4];
#pragma unroll
        for (int ks = 0; ks < 4; ks++) {
            const float* t0 = sacc[2 * ks];
            const float* t1 = sacc[2 * ks + 1];
            float h00 = __half2float(__float2half_rn(t0[0]));
            float h01 = __half2float(__float2half_rn(t0[1]));
            float h02 = __half2float(__float2half_rn(t0[2]));
            float h03 = __half2float(__float2half_rn(t0[3]));
            float h10 = __half2float(__float2half_rn(t1[0]));
            float h11 = __half2float(__float2half_rn(t1[1]));
            float h12 = __half2float(__float2half_rn(t1[2]));
            float h13 = __half2float(__float2half_rn(t1[3]));
            ph[ks][0] = packh(t0[0], t0[1]);
            ph[ks][1] = packh(t0[2], t0[3]);
            ph[ks][2] = packh(t1[0], t1[1]);
            ph[ks][3] = packh(t1[2], t1[3]);
            pl[ks][0] = packh(t0[0] - h00, t0[1] - h01);
            pl[ks][1] = packh(t0[2] - h02, t0[3] - h03);
            pl[ks][2] = packh(t1[0] - h10, t1[1] - h11);
            pl[ks][3] = packh(t1[2] - h12, t1[3] - h13);
        }

        // ---- O += P V (2-MMA hi/lo, split passes; V via ldmatrix.trans) ----
#pragma unroll
        for (int ks = 0; ks < 4; ks++) {
            uint32_t rowb = (uint32_t)(ks * 16 + (lane & 7) + ((lane >> 3) & 1) * 8) * 128;
            uint32_t vf[4][4];
#pragma unroll
            for (int np = 0; np < 4; np++)
                ldm_x4_t(vf[np], stg + 8192 + SWZ(rowb + np * 32 + (lane >> 4) * 16));
            // ph pass (8 independent accumulators)
#pragma unroll
            for (int np = 0; np < 4; np++)
#pragma unroll
                for (int sub = 0; sub < 2; sub++)
                    mma16816(oacc[np * 2 + sub], ph[ks],
                             vf[np][sub * 2], vf[np][sub * 2 + 1]);
            // pl pass
#pragma unroll
            for (int np = 0; np < 4; np++)
#pragma unroll
                for (int sub = 0; sub < 2; sub++)
                    mma16816(oacc[np * 2 + sub], pl[ks],
                             vf[np][sub * 2], vf[np][sub * 2 + 1]);
        }
        // no trailing barrier: next iteration's barrier protects stage reuse
    }

    // ---- epilogue: y (fp16 hi/lo) into [B,T,C], merging heads ----
    float inv0 = 1.f / l_s[0], inv1 = 1.f / l_s[1];
    int b = bh / H_, h = bh - b * H_;
    const int col = h * 64 + (lane & 3) * 2;
#pragma unroll
    for (int nt = 0; nt < 8; nt++) {
        float y0 = oacc[nt][0] * inv0, y1 = oacc[nt][1] * inv0;
        float y2 = oacc[nt][2] * inv1, y3 = oacc[nt][3] * inv1;
        size_t o0 = ((size_t)b * T_ + rlo) * C_ + col + nt * 8;
        size_t o1 = ((size_t)b * T_ + rhi) * C_ + col + nt * 8;
        float h0 = __half2float(__float2half_rn(y0));
        float h1 = __half2float(__float2half_rn(y1));
        float h2 = __half2float(__float2half_rn(y2));
        float h3 = __half2float(__float2half_rn(y3));
        *(uint32_t*)&g_yh[o0] = packh(y0, y1);
        *(uint32_t*)&g_yl[o0] = packh(y0 - h0, y1 - h1);
        *(uint32_t*)&g_yh[o1] = packh(y2, y3);
        *(uint32_t*)&g_yl[o1] = packh(y2 - h2, y3 - h3);
    }
}

// ---------------------------------------------------------------------------
extern "C" void kernel_launch(void* const* d_in, const int* in_sizes, int n_in,
                              void* d_out, int out_size)
{
    (void)in_sizes; (void)n_in; (void)out_size;
    const float* x      = (const float*)d_in[0];
    const float* W_attn = (const float*)d_in[1];
    const float* b_attn = (const float*)d_in[2];
    const float* W_proj = (const float*)d_in[3];
    const float* b_proj = (const float*)d_in[4];
    float* out = (float*)d_out;

    // conversions
    split_x_kernel<<<(M_ROWS * K_) / 256, 256>>>(x);
    split_tr_kernel<0><<<dim3(QKV_N / 32, K_ / 32), 256>>>(W_attn, K_, QKV_N);
    split_tr_kernel<1><<<dim3(C_ / 32, K_ / 32), 256>>>(W_proj, K_, C_);

    // 1) QKV GEMM (HMMA fp16 2-MMA, 3-stage, 2 CTAs/SM)
    cudaFuncSetAttribute(hgemm<0>,
                         cudaFuncAttributeMaxDynamicSharedMemorySize, SMH);
    hgemm<0><<<dim3(QKV_N / 128, M_ROWS / 128), 256, SMH>>>(b_attn, nullptr, QKV_N);

    // 2) causal flash attention (HMMA fp16 2-MMA, 3-stage cp.async)
    cudaFuncSetAttribute(attn_mma_kernel,
                         cudaFuncAttributeMaxDynamicSharedMemorySize, ATT_SMEM);
    attn_mma_kernel<<<dim3(T_ / 64, B_ * H_), 128, ATT_SMEM>>>();

    // 3) output projection (HMMA fp16 2-MMA)
    cudaFuncSetAttribute(hgemm<1>,
                         cudaFuncAttributeMaxDynamicSharedMemorySize, SMH);
    hgemm<1><<<dim3(C_ / 128, M_ROWS / 128), 256, SMH>>>(b_proj, out, C_);
}

// round 10
// speedup vs baseline: 4.2818x; 1.0533x over previous
#include <cuda_runtime.h>
#include <cuda_fp16.h>
#include <cstdint>
#include <cstddef>

// ---------------------------------------------------------------------------
// MultiHeadAttention: y = proj( causal_attention( x @ W_attn + b_attn ) )
// B=8, T=1024, C=768, H=12, hd=64
// All matmuls on HMMA fp16 2-MMA (activations split hi/lo, weights single).
// hgemm v4: warp tile 32x64, KCH=64, 2-stage cp.async, fragment pipelining.
// ---------------------------------------------------------------------------

#define B_  8
#define T_  1024
#define C_  768
#define H_  12
#define HD_ 64
#define M_ROWS (B_ * T_)          // 8192
#define QKV_N  (3 * C_)           // 2304
#define K_     C_                 // 768

// ---------------- device scratch (no allocation allowed) -------------------
__device__ __half g_qh[B_ * H_ * T_ * HD_], g_ql[B_ * H_ * T_ * HD_];
__device__ __half g_kh[B_ * H_ * T_ * HD_];
__device__ __half g_vh[B_ * H_ * T_ * HD_];

__device__ __half g_xh[M_ROWS * K_], g_xl[M_ROWS * K_];
__device__ __half g_yh[M_ROWS * K_], g_yl[M_ROWS * K_];   // attn out
__device__ __half g_wah[QKV_N * K_];                      // W_attn^T [N,K]
__device__ __half g_wph[C_ * K_];                         // W_proj^T [N,K]

// ---------------- small PTX helpers (sm_80-level only) ---------------------
__device__ __forceinline__ uint32_t smem_to_u32(const void* p) {
    uint32_t a;
    asm("{ .reg .u64 t; cvta.to.shared.u64 t, %1; cvt.u32.u64 %0, t; }"
        : "=r"(a) : "l"(p));
    return a;
}
__device__ __forceinline__ void ldm_x4(uint32_t* r, uint32_t addr) {
    asm volatile("ldmatrix.sync.aligned.m8n8.x4.shared.b16 {%0,%1,%2,%3}, [%4];"
                 : "=r"(r[0]), "=r"(r[1]), "=r"(r[2]), "=r"(r[3]) : "r"(addr));
}
__device__ __forceinline__ void ldm_x4_t(uint32_t* r, uint32_t addr) {
    asm volatile("ldmatrix.sync.aligned.m8n8.x4.trans.shared.b16 {%0,%1,%2,%3}, [%4];"
                 : "=r"(r[0]), "=r"(r[1]), "=r"(r[2]), "=r"(r[3]) : "r"(addr));
}
__device__ __forceinline__ void mma16816(float* d, const uint32_t* a,
                                         uint32_t b0, uint32_t b1) {
    asm volatile(
        "mma.sync.aligned.m16n8k16.row.col.f32.f16.f16.f32 "
        "{%0,%1,%2,%3}, {%4,%5,%6,%7}, {%8,%9}, {%0,%1,%2,%3};"
        : "+f"(d[0]), "+f"(d[1]), "+f"(d[2]), "+f"(d[3])
        : "r"(a[0]), "r"(a[1]), "r"(a[2]), "r"(a[3]), "r"(b0), "r"(b1));
}
__device__ __forceinline__ uint32_t packh(float lo, float hi) {
    __half2 t = __floats2half2_rn(lo, hi);
    return *(uint32_t*)&t;
}
__device__ __forceinline__ void cp16(uint32_t dst, const void* src) {
    asm volatile("cp.async.cg.shared.global [%0], [%1], 16;"
                 :: "r"(dst), "l"(src));
}
#define CP_COMMIT() asm volatile("cp.async.commit_group;" ::: "memory")
#define CP_WAIT1()  asm volatile("cp.async.wait_group 1;" ::: "memory")
#define CP_WAIT0()  asm volatile("cp.async.wait_group 0;" ::: "memory")
#define SWZ(b) ((b) ^ (((b) >> 3) & 0x70))
// 16x16 subtile layout for a tile with KCH=64 halves per row (4 subtiles/row-group)
#define SUBT64(r, u) ((((r) >> 4) * 4 + ((u) >> 1)) * 512 + ((r) & 15) * 32 + ((u) & 1) * 16)

// ---------------------------------------------------------------------------
// Split / conversion kernels
// ---------------------------------------------------------------------------
__global__ void split_x_kernel(const float* __restrict__ s) {
    int i = blockIdx.x * 256 + threadIdx.x;
    float a = s[i];
    __half h = __float2half_rn(a);
    g_xh[i] = h;
    g_xl[i] = __float2half_rn(a - __half2float(h));
}
// transpose [K,N] fp32 -> [N,K] fp16 (weights single precision)
template <int W>
__global__ void split_tr_kernel(const float* __restrict__ s, int Kd, int Nd) {
    __shared__ float t[32][33];
    int nb = blockIdx.x * 32, kb = blockIdx.y * 32;
    int tx = threadIdx.x & 31, ty = threadIdx.x >> 5;   // 32 x 8
    for (int r = ty; r < 32; r += 8)
        t[r][tx] = s[(size_t)(kb + r) * Nd + nb + tx];
    __syncthreads();
    __half* hi = W ? g_wph : g_wah;
    for (int r = ty; r < 32; r += 8) {
        size_t o = (size_t)(nb + r) * Kd + kb + tx;
        hi[o] = __float2half_rn(t[tx][r]);
    }
}

// ---------------------------------------------------------------------------
// HMMA fp16 2-MMA GEMM v4: CTA 128x128, K-chunk 64, 8 warps (4m x 2n),
// warp tile 32x64. 2-stage cp.async (prefetch distance 1, ONE barrier/chunk).
// Fragment double-buffering: next kc's B + A-hi prefetched under current MMAs;
// A-lo latency hidden under the hi pass.
// SMEM stage: Ah 16K | Al 16K | B 16K; 2 stages = 96KB/CTA -> 2 CTAs/SM.
// EPI==0: q hi/lo + k/v single fp16 [B,H,T,hd].  EPI==1: fp32 row-major out.
// ---------------------------------------------------------------------------
#define KCH    64
#define NKCH   (K_ / KCH)          // 12
#define HSTAGE 49152               // 16KB Ah + 16KB Al + 16KB B
#define SMH    (2 * HSTAGE)        // 98304

template <int EPI>
__global__ __launch_bounds__(256, 2)
void hgemm(const float* __restrict__ bias, float* __restrict__ Cout, int N)
{
    extern __shared__ char smem[];
    const uint32_t sb = smem_to_u32(smem);
    const int tid  = threadIdx.x;
    const int lane = tid & 31;
    const int w    = tid >> 5;
    const int mw   = w & 3;        // 4 m-warps (32 rows each)
    const int nw   = w >> 2;       // 2 n-warps (64 cols each)
    const int n0 = blockIdx.x * 128;
    const int m0 = blockIdx.y * 128;

    const __half* Ahi = (EPI == 0) ? g_xh : g_yh;
    const __half* Alo = (EPI == 0) ? g_xl : g_yl;
    const __half* Bs  = (EPI == 0) ? g_wah : g_wph;

    float acc[2][8][4];           // [mt 16-row][j n8][quad] = 64 regs
#pragma unroll
    for (int i = 0; i < 2; i++)
#pragma unroll
        for (int j = 0; j < 8; j++)
#pragma unroll
            for (int q = 0; q < 4; q++) acc[i][j][q] = 0.f;

    auto issue = [&](int stage, int c) {
        const int kk = c * KCH;
        const uint32_t sbase = sb + stage * HSTAGE;
        // A hi/lo: 2 * 128 rows * 8 u = 2048 pieces (8 its)
#pragma unroll
        for (int it = 0; it < 8; it++) {
            int idx = it * 256 + tid;
            int hl = idx >> 10, rem = idx & 1023;
            int r = rem >> 3, u = rem & 7;
            const __half* src = hl ? Alo : Ahi;
            cp16(sbase + hl * 16384 + SUBT64(r, u),
                 src + (size_t)(m0 + r) * K_ + kk + u * 8);
        }
        // B: 128 rows * 8 u = 1024 pieces (4 its)
#pragma unroll
        for (int it = 0; it < 4; it++) {
            int idx = it * 256 + tid;
            int r = idx >> 3, u = idx & 7;
            cp16(sbase + 32768 + SUBT64(r, u),
                 Bs + (size_t)(n0 + r) * K_ + kk + u * 8);
        }
        CP_COMMIT();
    };

    const uint32_t a_in = (lane & 15) * 32 + (lane >> 4) * 16;
    const uint32_t b_in = ((lane & 7) + (lane >> 4) * 8) * 32 + ((lane >> 3) & 1) * 16;

    issue(0, 0);

    for (int c = 0; c < NKCH; c++) {
        CP_WAIT0();
        __syncthreads();
        if (c + 1 < NKCH) issue((c + 1) & 1, c + 1);

        const uint32_t base = sb + (c & 1) * HSTAGE;

        // fragment buffers: B (4 nt16) and A-hi (2 mt) double-buffered
        uint32_t bf[2][16], ah[2][8], al[8];

        auto load_bah = [&](int kc, int buf) {
#pragma unroll
            for (int nt = 0; nt < 4; nt++)
                ldm_x4(&bf[buf][nt * 4],
                       base + 32768 + ((nw * 4 + nt) * 4 + kc) * 512 + b_in);
#pragma unroll
            for (int mt = 0; mt < 2; mt++)
                ldm_x4(&ah[buf][mt * 4],
                       base + ((mw * 2 + mt) * 4 + kc) * 512 + a_in);
        };

        load_bah(0, 0);
#pragma unroll
        for (int kc = 0; kc < 4; kc++) {
            const int cur = kc & 1;
            // A-lo for this kc: issue first, latency hidden under hi pass
#pragma unroll
            for (int mt = 0; mt < 2; mt++)
                ldm_x4(&al[mt * 4],
                       base + 16384 + ((mw * 2 + mt) * 4 + kc) * 512 + a_in);
            // prefetch next kc's B + A-hi under this kc's MMAs
            if (kc < 3) load_bah(kc + 1, cur ^ 1);
            // hi pass (16 MMAs, 16 independent accumulators)
#pragma unroll
            for (int mt = 0; mt < 2; mt++)
#pragma unroll
                for (int nt = 0; nt < 4; nt++)
#pragma unroll
                    for (int sub = 0; sub < 2; sub++)
                        mma16816(acc[mt][nt * 2 + sub], &ah[cur][mt * 4],
                                 bf[cur][nt * 4 + sub * 2],
                                 bf[cur][nt * 4 + sub * 2 + 1]);
            // lo pass
#pragma unroll
            for (int mt = 0; mt < 2; mt++)
#pragma unroll
                for (int nt = 0; nt < 4; nt++)
#pragma unroll
                    for (int sub = 0; sub < 2; sub++)
                        mma16816(acc[mt][nt * 2 + sub], &al[mt * 4],
                                 bf[cur][nt * 4 + sub * 2],
                                 bf[cur][nt * 4 + sub * 2 + 1]);
        }
        // no trailing barrier: next iteration's barrier protects stage reuse
    }

    // epilogue
    const int row_in = lane >> 2;
    const int col_in = (lane & 3) * 2;
#pragma unroll
    for (int mt = 0; mt < 2; mt++) {
#pragma unroll
        for (int j = 0; j < 8; j++) {
            const int c = n0 + nw * 64 + j * 8 + col_in;
            const float b0v = bias[c], b1v = bias[c + 1];
#pragma unroll
            for (int hf = 0; hf < 2; hf++) {
                const int m = m0 + mw * 32 + mt * 16 + row_in + hf * 8;
                float v0 = acc[mt][j][hf * 2 + 0] + b0v;
                float v1 = acc[mt][j][hf * 2 + 1] + b1v;
                if (EPI == 0) {
                    int which = c / C_;
                    int cc = c - which * C_;
                    int h = cc >> 6, d = cc & 63;
                    int b = m >> 10, tt = m & 1023;
                    size_t o = ((size_t)(b * H_ + h) * T_ + tt) * HD_ + d;
                    if (which == 0) {
                        float h0 = __half2float(__float2half_rn(v0));
                        float h1 = __half2float(__float2half_rn(v1));
                        *(uint32_t*)&g_qh[o] = packh(v0, v1);
                        *(uint32_t*)&g_ql[o] = packh(v0 - h0, v1 - h1);
                    } else if (which == 1) {
                        *(uint32_t*)&g_kh[o] = packh(v0, v1);
                    } else {
                        *(uint32_t*)&g_vh[o] = packh(v0, v1);
                    }
                } else {
                    *(float2*)&Cout[(size_t)m * N + c] = make_float2(v0, v1);
                }
            }
        }
    }
}

// ---------------------------------------------------------------------------
// HMMA flash attention, causal. Grid (16 q-tiles, 96 bh), 128 threads (4 warps).
// 3-stage cp.async K/V pipeline (16KB/stage: K 8K | V 8K), ONE barrier per kt.
// Q hi/lo at 48KB. S = (Qh+Ql) K^T, O += (Ph+Pl) V. fp16 single K/V.
// (round-9 proven, unchanged)
// ---------------------------------------------------------------------------
#define ATT_SMEM (3 * 16384 + 16384)   // 65536

__global__ __launch_bounds__(128)
void attn_mma_kernel()
{
    extern __shared__ char smem[];
    const uint32_t sb = smem_to_u32(smem);
    const int tid = threadIdx.x, lane = tid & 31, w = tid >> 5;
    const int qt = blockIdx.x, bh = blockIdx.y;
    const int q0 = qt * 64;
    const size_t base = (size_t)bh * T_ * HD_;

    auto issue_kv = [&](int stage, int kt) {
        const int k0 = kt * 64;
        const uint32_t sbase = sb + stage * 16384;
#pragma unroll
        for (int it = 0; it < 8; it++) {
            int idx = it * 128 + tid;       // 0..1023
            int tile = idx >> 9;            // 0..1
            int rem = idx & 511;
            int r = rem >> 3, u = rem & 7;  // r 0..63, u 0..7
            const __half* src = tile ? g_vh : g_kh;
            cp16(sbase + tile * 8192 + SWZ(r * 128 + u * 16),
                 src + base + (size_t)(k0 + r) * HD_ + u * 8);
        }
        CP_COMMIT();
    };

    issue_kv(0, 0);
    if (qt >= 1) issue_kv(1, 1);

    // ---- load Q tiles (hi/lo) with plain stores, build fragments ----
#pragma unroll
    for (int half = 0; half < 2; half++) {
        const __half* src = half ? g_ql : g_qh;
        uint32_t dstb = 49152 + half * 8192;
#pragma unroll
        for (int it = 0; it < 4; it++) {
            int idx = it * 128 + tid;
            int r = idx >> 3, u = idx & 7;
            uint4 v = *(const uint4*)(src + base + (size_t)(q0 + r) * HD_ + u * 8);
            *(uint4*)(smem + dstb + SWZ(r * 128 + u * 16)) = v;
        }
    }
    __syncthreads();

    uint32_t qh[4][4], ql[4][4];
    {
        uint32_t rowb = (uint32_t)(16 * w + (lane & 7) + ((lane >> 3) & 1) * 8) * 128;
#pragma unroll
        for (int ks = 0; ks < 4; ks++) {
            uint32_t cb = ks * 32 + (lane >> 4) * 16;
            ldm_x4(qh[ks], sb + 49152 + SWZ(rowb + cb));
            ldm_x4(ql[ks], sb + 57344 + SWZ(rowb + cb));
        }
    }

    float oacc[8][4];
#pragma unroll
    for (int i = 0; i < 8; i++)
#pragma unroll
        for (int j = 0; j < 4; j++) oacc[i][j] = 0.f;
    float m_s[2] = {-1e30f, -1e30f};
    float l_s[2] = {0.f, 0.f};

    const int rlo = q0 + 16 * w + (lane >> 2);
    const int rhi = rlo + 8;

    for (int kt = 0; kt <= qt; kt++) {
        const int k0 = kt * 64;
        if (kt < qt) { CP_WAIT1(); } else { CP_WAIT0(); }
        __syncthreads();
        if (kt + 2 <= qt) issue_kv((kt + 2) % 3, kt + 2);
        const uint32_t stg = sb + (kt % 3) * 16384;

        // ---- S = Q K^T (2-MMA hi/lo, split passes) ----
        float sacc[8][4];
#pragma unroll
        for (int i = 0; i < 8; i++)
#pragma unroll
            for (int j = 0; j < 4; j++) sacc[i][j] = 0.f;

#pragma unroll
        for (int kt16 = 0; kt16 < 4; kt16++) {
            uint32_t rowb = (uint32_t)(kt16 * 16 + (lane & 7) + (lane >> 4) * 8) * 128;
            uint32_t kf[4][4];
#pragma unroll
            for (int ks = 0; ks < 4; ks++)
                ldm_x4(kf[ks], stg + SWZ(rowb + ks * 32 + ((lane >> 3) & 1) * 16));
            // qh pass
#pragma unroll
            for (int ks = 0; ks < 4; ks++)
#pragma unroll
                for (int sub = 0; sub < 2; sub++)
                    mma16816(sacc[kt16 * 2 + sub], qh[ks],
                             kf[ks][sub * 2], kf[ks][sub * 2 + 1]);
            // ql pass
#pragma unroll
            for (int ks = 0; ks < 4; ks++)
#pragma unroll
                for (int sub = 0; sub < 2; sub++)
                    mma16816(sacc[kt16 * 2 + sub], ql[ks],
                             kf[ks][sub * 2], kf[ks][sub * 2 + 1]);
        }

        // ---- scale + causal mask ----
#pragma unroll
        for (int nt = 0; nt < 8; nt++) {
            int cb0 = k0 + nt * 8 + (lane & 3) * 2;
#pragma unroll
            for (int j = 0; j < 4; j++) sacc[nt][j] *= 0.125f;
            if (kt == qt) {
                if (cb0 > rlo)     sacc[nt][0] = -1e30f;
                if (cb0 + 1 > rlo) sacc[nt][1] = -1e30f;
                if (cb0 > rhi)     sacc[nt][2] = -1e30f;
                if (cb0 + 1 > rhi) sacc[nt][3] = -1e30f;
            }
        }

        // ---- online softmax (register, quad shfl reductions) ----
        float tmax0 = -1e30f, tmax1 = -1e30f;
#pragma unroll
        for (int nt = 0; nt < 8; nt++) {
            tmax0 = fmaxf(tmax0, fmaxf(sacc[nt][0], sacc[nt][1]));
            tmax1 = fmaxf(tmax1, fmaxf(sacc[nt][2], sacc[nt][3]));
        }
        tmax0 = fmaxf(tmax0, __shfl_xor_sync(0xffffffff, tmax0, 1));
        tmax0 = fmaxf(tmax0, __shfl_xor_sync(0xffffffff, tmax0, 2));
        tmax1 = fmaxf(tmax1, __shfl_xor_sync(0xffffffff, tmax1, 1));
        tmax1 = fmaxf(tmax1, __shfl_xor_sync(0xffffffff, tmax1, 2));
        float nm0 = fmaxf(m_s[0], tmax0), nm1 = fmaxf(m_s[1], tmax1);
        float al0 = __expf(m_s[0] - nm0), al1 = __expf(m_s[1] - nm1);
        m_s[0] = nm0; m_s[1] = nm1;

        float rs0 = 0.f, rs1 = 0.f;
#pragma unroll
        for (int nt = 0; nt < 8; nt++) {
            sacc[nt][0] = __expf(sacc[nt][0] - nm0);
            sacc[nt][1] = __expf(sacc[nt][1] - nm0);
            sacc[nt][2] = __expf(sacc[nt][2] - nm1);
            sacc[nt][3] = __expf(sacc[nt][3] - nm1);
            rs0 += sacc[nt][0] + sacc[nt][1];
            rs1 += sacc[nt][2] + sacc[nt][3];
        }
        rs0 += __shfl_xor_sync(0xffffffff, rs0, 1);
        rs0 += __shfl_xor_sync(0xffffffff, rs0, 2);
        rs1 += __shfl_xor_sync(0xffffffff, rs1, 1);
        rs1 += __shfl_xor_sync(0xffffffff, rs1, 2);
        l_s[0] = l_s[0] * al0 + rs0;
        l_s[1] = l_s[1] * al1 + rs1;

#pragma unroll
        for (int nt = 0; nt < 8; nt++) {
            oacc[nt][0] *= al0; oacc[nt][1] *= al0;
            oacc[nt][2] *= al1; oacc[nt][3] *= al1;
        }

        // ---- P fragments (fp16 hi/lo) ----
        uint32_t ph[4][4], pl[4][4];
#pragma unroll
        for (int ks = 0; ks < 4; ks++) {
            const float* t0 = sacc[2 * ks];
            const float* t1 = sacc[2 * ks + 1];
            float h00 = __half2float(__float2half_rn(t0[0]));
            float h01 = __half2float(__float2half_rn(t0[1]));
            float h02 = __half2float(__float2half_rn(t0[2]));
            float h03 = __half2float(__float2half_rn(t0[3]));
            float h10 = __half2float(__float2half_rn(t1[0]));
            float h11 = __half2float(__float2half_rn(t1[1]));
            float h12 = __half2float(__float2half_rn(t1[2]));
            float h13 = __half2float(__float2half_rn(t1[3]));
            ph[ks][0] = packh(t0[0], t0[1]);
            ph[ks][1] = packh(t0[2], t0[3]);
            ph[ks][2] = packh(t1[0], t1[1]);
            ph[ks][3] = packh(t1[2], t1[3]);
            pl[ks][0] = packh(t0[0] - h00, t0[1] - h01);
            pl[ks][1] = packh(t0[2] - h02, t0[3] - h03);
            pl[ks][2] = packh(t1[0] - h10, t1[1] - h11);
            pl[ks][3] = packh(t1[2] - h12, t1[3] - h13);
        }

        // ---- O += P V (2-MMA hi/lo, split passes; V via ldmatrix.trans) ----
#pragma unroll
        for (int ks = 0; ks < 4; ks++) {
            uint32_t rowb = (uint32_t)(ks * 16 + (lane & 7) + ((lane >> 3) & 1) * 8) * 128;
            uint32_t vf[4][4];
#pragma unroll
            for (int np = 0; np < 4; np++)
                ldm_x4_t(vf[np], stg + 8192 + SWZ(rowb + np * 32 + (lane >> 4) * 16));
            // ph pass (8 independent accumulators)
#pragma unroll
            for (int np = 0; np < 4; np++)
#pragma unroll
                for (int sub = 0; sub < 2; sub++)
                    mma16816(oacc[np * 2 + sub], ph[ks],
                             vf[np][sub * 2], vf[np][sub * 2 + 1]);
            // pl pass
#pragma unroll
            for (int np = 0; np < 4; np++)
#pragma unroll
                for (int sub = 0; sub < 2; sub++)
                    mma16816(oacc[np * 2 + sub], pl[ks],
                             vf[np][sub * 2], vf[np][sub * 2 + 1]);
        }
        // no trailing barrier: next iteration's barrier protects stage reuse
    }

    // ---- epilogue: y (fp16 hi/lo) into [B,T,C], merging heads ----
    float inv0 = 1.f / l_s[0], inv1 = 1.f / l_s[1];
    int b = bh / H_, h = bh - b * H_;
    const int col = h * 64 + (lane & 3) * 2;
#pragma unroll
    for (int nt = 0; nt < 8; nt++) {
        float y0 = oacc[nt][0] * inv0, y1 = oacc[nt][1] * inv0;
        float y2 = oacc[nt][2] * inv1, y3 = oacc[nt][3] * inv1;
        size_t o0 = ((size_t)b * T_ + rlo) * C_ + col + nt * 8;
        size_t o1 = ((size_t)b * T_ + rhi) * C_ + col + nt * 8;
        float h0 = __half2float(__float2half_rn(y0));
        float h1 = __half2float(__float2half_rn(y1));
        float h2 = __half2float(__float2half_rn(y2));
        float h3 = __half2float(__float2half_rn(y3));
        *(uint32_t*)&g_yh[o0] = packh(y0, y1);
        *(uint32_t*)&g_yl[o0] = packh(y0 - h0, y1 - h1);
        *(uint32_t*)&g_yh[o1] = packh(y2, y3);
        *(uint32_t*)&g_yl[o1] = packh(y2 - h2, y3 - h3);
    }
}

// ---------------------------------------------------------------------------
extern "C" void kernel_launch(void* const* d_in, const int* in_sizes, int n_in,
                              void* d_out, int out_size)
{
    (void)in_sizes; (void)n_in; (void)out_size;
    const float* x      = (const float*)d_in[0];
    const float* W_attn = (const float*)d_in[1];
    const float* b_attn = (const float*)d_in[2];
    const float* W_proj = (const float*)d_in[3];
    const float* b_proj = (const float*)d_in[4];
    float* out = (float*)d_out;

    // conversions
    split_x_kernel<<<(M_ROWS * K_) / 256, 256>>>(x);
    split_tr_kernel<0><<<dim3(QKV_N / 32, K_ / 32), 256>>>(W_attn, K_, QKV_N);
    split_tr_kernel<1><<<dim3(C_ / 32, K_ / 32), 256>>>(W_proj, K_, C_);

    // 1) QKV GEMM (HMMA fp16 2-MMA, v4)
    cudaFuncSetAttribute(hgemm<0>,
                         cudaFuncAttributeMaxDynamicSharedMemorySize, SMH);
    hgemm<0><<<dim3(QKV_N / 128, M_ROWS / 128), 256, SMH>>>(b_attn, nullptr, QKV_N);

    // 2) causal flash attention (HMMA fp16 2-MMA, 3-stage cp.async)
    cudaFuncSetAttribute(attn_mma_kernel,
                         cudaFuncAttributeMaxDynamicSharedMemorySize, ATT_SMEM);
    attn_mma_kernel<<<dim3(T_ / 64, B_ * H_), 128, ATT_SMEM>>>();

    // 3) output projection (HMMA fp16 2-MMA, v4)
    cudaFuncSetAttribute(hgemm<1>,
                         cudaFuncAttributeMaxDynamicSharedMemorySize, SMH);
    hgemm<1><<<dim3(C_ / 128, M_ROWS / 128), 256, SMH>>>(b_proj, out, C_);
}

// round 11
// speedup vs baseline: 4.7983x; 1.1206x over previous
#include <cuda_runtime.h>
#include <cuda_fp16.h>
#include <cstdint>
#include <cstddef>

// ---------------------------------------------------------------------------
// MultiHeadAttention: y = proj( causal_attention( x @ W_attn + b_attn ) )
// B=8, T=1024, C=768, H=12, hd=64
// HMMA fp16; precision placement: hi/lo (2-MMA) only where it matters
//   - Q columns of QKV GEMM, S=QK^T (Q hi/lo), y into proj.
//   - K/V columns and P*V use single fp16 (error bounded by fp16 stores).
// ---------------------------------------------------------------------------

#define B_  8
#define T_  1024
#define C_  768
#define H_  12
#define HD_ 64
#define M_ROWS (B_ * T_)          // 8192
#define QKV_N  (3 * C_)           // 2304
#define K_     C_                 // 768

// ---------------- device scratch (no allocation allowed) -------------------
__device__ __half g_qh[B_ * H_ * T_ * HD_], g_ql[B_ * H_ * T_ * HD_];
__device__ __half g_kh[B_ * H_ * T_ * HD_];
__device__ __half g_vh[B_ * H_ * T_ * HD_];

__device__ __half g_xh[M_ROWS * K_], g_xl[M_ROWS * K_];
__device__ __half g_yh[M_ROWS * K_], g_yl[M_ROWS * K_];   // attn out
__device__ __half g_wah[QKV_N * K_];                      // W_attn^T [N,K]
__device__ __half g_wph[C_ * K_];                         // W_proj^T [N,K]

// ---------------- small PTX helpers (sm_80-level only) ---------------------
__device__ __forceinline__ uint32_t smem_to_u32(const void* p) {
    uint32_t a;
    asm("{ .reg .u64 t; cvta.to.shared.u64 t, %1; cvt.u32.u64 %0, t; }"
        : "=r"(a) : "l"(p));
    return a;
}
__device__ __forceinline__ void ldm_x4(uint32_t* r, uint32_t addr) {
    asm volatile("ldmatrix.sync.aligned.m8n8.x4.shared.b16 {%0,%1,%2,%3}, [%4];"
                 : "=r"(r[0]), "=r"(r[1]), "=r"(r[2]), "=r"(r[3]) : "r"(addr));
}
__device__ __forceinline__ void ldm_x4_t(uint32_t* r, uint32_t addr) {
    asm volatile("ldmatrix.sync.aligned.m8n8.x4.trans.shared.b16 {%0,%1,%2,%3}, [%4];"
                 : "=r"(r[0]), "=r"(r[1]), "=r"(r[2]), "=r"(r[3]) : "r"(addr));
}
__device__ __forceinline__ void mma16816(float* d, const uint32_t* a,
                                         uint32_t b0, uint32_t b1) {
    asm volatile(
        "mma.sync.aligned.m16n8k16.row.col.f32.f16.f16.f32 "
        "{%0,%1,%2,%3}, {%4,%5,%6,%7}, {%8,%9}, {%0,%1,%2,%3};"
        : "+f"(d[0]), "+f"(d[1]), "+f"(d[2]), "+f"(d[3])
        : "r"(a[0]), "r"(a[1]), "r"(a[2]), "r"(a[3]), "r"(b0), "r"(b1));
}
__device__ __forceinline__ uint32_t packh(float lo, float hi) {
    __half2 t = __floats2half2_rn(lo, hi);
    return *(uint32_t*)&t;
}
__device__ __forceinline__ void cp16(uint32_t dst, const void* src) {
    asm volatile("cp.async.cg.shared.global [%0], [%1], 16;"
                 :: "r"(dst), "l"(src));
}
#define CP_COMMIT() asm volatile("cp.async.commit_group;" ::: "memory")
#define CP_WAIT1()  asm volatile("cp.async.wait_group 1;" ::: "memory")
#define CP_WAIT0()  asm volatile("cp.async.wait_group 0;" ::: "memory")
#define SWZ(b) ((b) ^ (((b) >> 3) & 0x70))
// 16x16 subtile layout for a tile with KCH=64 halves per row (4 subtiles/row-group)
#define SUBT64(r, u) ((((r) >> 4) * 4 + ((u) >> 1)) * 512 + ((r) & 15) * 32 + ((u) & 1) * 16)

// ---------------------------------------------------------------------------
// Split / conversion kernels
// ---------------------------------------------------------------------------
__global__ void split_x_kernel(const float* __restrict__ s) {
    int i = blockIdx.x * 256 + threadIdx.x;
    float a = s[i];
    __half h = __float2half_rn(a);
    g_xh[i] = h;
    g_xl[i] = __float2half_rn(a - __half2float(h));
}
// transpose [K,N] fp32 -> [N,K] fp16 (weights single precision)
template <int W>
__global__ void split_tr_kernel(const float* __restrict__ s, int Kd, int Nd) {
    __shared__ float t[32][33];
    int nb = blockIdx.x * 32, kb = blockIdx.y * 32;
    int tx = threadIdx.x & 31, ty = threadIdx.x >> 5;   // 32 x 8
    for (int r = ty; r < 32; r += 8)
        t[r][tx] = s[(size_t)(kb + r) * Nd + nb + tx];
    __syncthreads();
    __half* hi = W ? g_wph : g_wah;
    for (int r = ty; r < 32; r += 8) {
        size_t o = (size_t)(nb + r) * Kd + kb + tx;
        hi[o] = __float2half_rn(t[tx][r]);
    }
}

// ---------------------------------------------------------------------------
// HMMA fp16 GEMM v5: CTA 128x128, K-chunk 64, 8 warps (4m x 2n),
// warp tile 32x64. 2-stage cp.async, fragment double-buffering.
// A-lo pass only where needed: EPI==1 (proj: y hi/lo) or Q columns (n0 < C_)
// of the QKV GEMM. K/V columns run single-MMA (they are stored fp16 anyway).
// SMEM stage: Ah 16K | Al 16K | B 16K; 2 stages = 96KB/CTA -> 2 CTAs/SM.
// ---------------------------------------------------------------------------
#define KCH    64
#define NKCH   (K_ / KCH)          // 12
#define HSTAGE 49152               // 16KB Ah + 16KB Al + 16KB B
#define SMH    (2 * HSTAGE)        // 98304

template <int EPI>
__global__ __launch_bounds__(256, 2)
void hgemm(const float* __restrict__ bias, float* __restrict__ Cout, int N)
{
    extern __shared__ char smem[];
    const uint32_t sb = smem_to_u32(smem);
    const int tid  = threadIdx.x;
    const int lane = tid & 31;
    const int w    = tid >> 5;
    const int mw   = w & 3;        // 4 m-warps (32 rows each)
    const int nw   = w >> 2;       // 2 n-warps (64 cols each)
    const int n0 = blockIdx.x * 128;
    const int m0 = blockIdx.y * 128;

    // lo-precision pass needed? (proj always; QKV only for Q columns)
    const bool use_lo = (EPI == 1) || (n0 < C_);

    const __half* Ahi = (EPI == 0) ? g_xh : g_yh;
    const __half* Alo = (EPI == 0) ? g_xl : g_yl;
    const __half* Bs  = (EPI == 0) ? g_wah : g_wph;

    float acc[2][8][4];           // [mt 16-row][j n8][quad] = 64 regs
#pragma unroll
    for (int i = 0; i < 2; i++)
#pragma unroll
        for (int j = 0; j < 8; j++)
#pragma unroll
            for (int q = 0; q < 4; q++) acc[i][j][q] = 0.f;

    auto issue = [&](int stage, int c) {
        const int kk = c * KCH;
        const uint32_t sbase = sb + stage * HSTAGE;
        // A hi (its 0-3) + A lo (its 4-7, only if use_lo)
#pragma unroll
        for (int it = 0; it < 8; it++) {
            if (it >= 4 && !use_lo) break;
            int idx = it * 256 + tid;
            int hl = idx >> 10, rem = idx & 1023;
            int r = rem >> 3, u = rem & 7;
            const __half* src = hl ? Alo : Ahi;
            cp16(sbase + hl * 16384 + SUBT64(r, u),
                 src + (size_t)(m0 + r) * K_ + kk + u * 8);
        }
        // B: 128 rows * 8 u = 1024 pieces (4 its)
#pragma unroll
        for (int it = 0; it < 4; it++) {
            int idx = it * 256 + tid;
            int r = idx >> 3, u = idx & 7;
            cp16(sbase + 32768 + SUBT64(r, u),
                 Bs + (size_t)(n0 + r) * K_ + kk + u * 8);
        }
        CP_COMMIT();
    };

    const uint32_t a_in = (lane & 15) * 32 + (lane >> 4) * 16;
    const uint32_t b_in = ((lane & 7) + (lane >> 4) * 8) * 32 + ((lane >> 3) & 1) * 16;

    issue(0, 0);

    for (int c = 0; c < NKCH; c++) {
        CP_WAIT0();
        __syncthreads();
        if (c + 1 < NKCH) issue((c + 1) & 1, c + 1);

        const uint32_t base = sb + (c & 1) * HSTAGE;

        // fragment buffers: B (4 nt16) and A-hi (2 mt) double-buffered
        uint32_t bf[2][16], ah[2][8], al[8];

        auto load_bah = [&](int kc, int buf) {
#pragma unroll
            for (int nt = 0; nt < 4; nt++)
                ldm_x4(&bf[buf][nt * 4],
                       base + 32768 + ((nw * 4 + nt) * 4 + kc) * 512 + b_in);
#pragma unroll
            for (int mt = 0; mt < 2; mt++)
                ldm_x4(&ah[buf][mt * 4],
                       base + ((mw * 2 + mt) * 4 + kc) * 512 + a_in);
        };

        load_bah(0, 0);
#pragma unroll
        for (int kc = 0; kc < 4; kc++) {
            const int cur = kc & 1;
            // A-lo for this kc: issue first, latency hidden under hi pass
            if (use_lo) {
#pragma unroll
                for (int mt = 0; mt < 2; mt++)
                    ldm_x4(&al[mt * 4],
                           base + 16384 + ((mw * 2 + mt) * 4 + kc) * 512 + a_in);
            }
            // prefetch next kc's B + A-hi under this kc's MMAs
            if (kc < 3) load_bah(kc + 1, cur ^ 1);
            // hi pass (16 MMAs, 16 independent accumulators)
#pragma unroll
            for (int mt = 0; mt < 2; mt++)
#pragma unroll
                for (int nt = 0; nt < 4; nt++)
#pragma unroll
                    for (int sub = 0; sub < 2; sub++)
                        mma16816(acc[mt][nt * 2 + sub], &ah[cur][mt * 4],
                                 bf[cur][nt * 4 + sub * 2],
                                 bf[cur][nt * 4 + sub * 2 + 1]);
            // lo pass (only where precision is consumed downstream)
            if (use_lo) {
#pragma unroll
                for (int mt = 0; mt < 2; mt++)
#pragma unroll
                    for (int nt = 0; nt < 4; nt++)
#pragma unroll
                        for (int sub = 0; sub < 2; sub++)
                            mma16816(acc[mt][nt * 2 + sub], &al[mt * 4],
                                     bf[cur][nt * 4 + sub * 2],
                                     bf[cur][nt * 4 + sub * 2 + 1]);
            }
        }
        // no trailing barrier: next iteration's barrier protects stage reuse
    }

    // epilogue
    const int row_in = lane >> 2;
    const int col_in = (lane & 3) * 2;
#pragma unroll
    for (int mt = 0; mt < 2; mt++) {
#pragma unroll
        for (int j = 0; j < 8; j++) {
            const int c = n0 + nw * 64 + j * 8 + col_in;
            const float b0v = bias[c], b1v = bias[c + 1];
#pragma unroll
            for (int hf = 0; hf < 2; hf++) {
                const int m = m0 + mw * 32 + mt * 16 + row_in + hf * 8;
                float v0 = acc[mt][j][hf * 2 + 0] + b0v;
                float v1 = acc[mt][j][hf * 2 + 1] + b1v;
                if (EPI == 0) {
                    int which = c / C_;
                    int cc = c - which * C_;
                    int h = cc >> 6, d = cc & 63;
                    int b = m >> 10, tt = m & 1023;
                    size_t o = ((size_t)(b * H_ + h) * T_ + tt) * HD_ + d;
                    if (which == 0) {
                        float h0 = __half2float(__float2half_rn(v0));
                        float h1 = __half2float(__float2half_rn(v1));
                        *(uint32_t*)&g_qh[o] = packh(v0, v1);
                        *(uint32_t*)&g_ql[o] = packh(v0 - h0, v1 - h1);
                    } else if (which == 1) {
                        *(uint32_t*)&g_kh[o] = packh(v0, v1);
                    } else {
                        *(uint32_t*)&g_vh[o] = packh(v0, v1);
                    }
                } else {
                    *(float2*)&Cout[(size_t)m * N + c] = make_float2(v0, v1);
                }
            }
        }
    }
}

// ---------------------------------------------------------------------------
// HMMA flash attention, causal. Grid (16 q-tiles, 96 bh), 128 threads (4 warps).
// 3-stage cp.async K/V pipeline (16KB/stage: K 8K | V 8K), ONE barrier per kt.
// Q hi/lo at 48KB. S = (Qh+Ql) K^T (2-MMA); O += P V with SINGLE-fp16 P.
// ---------------------------------------------------------------------------
#define ATT_SMEM (3 * 16384 + 16384)   // 65536

__global__ __launch_bounds__(128)
void attn_mma_kernel()
{
    extern __shared__ char smem[];
    const uint32_t sb = smem_to_u32(smem);
    const int tid = threadIdx.x, lane = tid & 31, w = tid >> 5;
    const int qt = blockIdx.x, bh = blockIdx.y;
    const int q0 = qt * 64;
    const size_t base = (size_t)bh * T_ * HD_;

    auto issue_kv = [&](int stage, int kt) {
        const int k0 = kt * 64;
        const uint32_t sbase = sb + stage * 16384;
#pragma unroll
        for (int it = 0; it < 8; it++) {
            int idx = it * 128 + tid;       // 0..1023
            int tile = idx >> 9;            // 0..1
            int rem = idx & 511;
            int r = rem >> 3, u = rem & 7;  // r 0..63, u 0..7
            const __half* src = tile ? g_vh : g_kh;
            cp16(sbase + tile * 8192 + SWZ(r * 128 + u * 16),
                 src + base + (size_t)(k0 + r) * HD_ + u * 8);
        }
        CP_COMMIT();
    };

    issue_kv(0, 0);
    if (qt >= 1) issue_kv(1, 1);

    // ---- load Q tiles (hi/lo) with plain stores, build fragments ----
#pragma unroll
    for (int half = 0; half < 2; half++) {
        const __half* src = half ? g_ql : g_qh;
        uint32_t dstb = 49152 + half * 8192;
#pragma unroll
        for (int it = 0; it < 4; it++) {
            int idx = it * 128 + tid;
            int r = idx >> 3, u = idx & 7;
            uint4 v = *(const uint4*)(src + base + (size_t)(q0 + r) * HD_ + u * 8);
            *(uint4*)(smem + dstb + SWZ(r * 128 + u * 16)) = v;
        }
    }
    __syncthreads();

    uint32_t qh[4][4], ql[4][4];
    {
        uint32_t rowb = (uint32_t)(16 * w + (lane & 7) + ((lane >> 3) & 1) * 8) * 128;
#pragma unroll
        for (int ks = 0; ks < 4; ks++) {
            uint32_t cb = ks * 32 + (lane >> 4) * 16;
            ldm_x4(qh[ks], sb + 49152 + SWZ(rowb + cb));
            ldm_x4(ql[ks], sb + 57344 + SWZ(rowb + cb));
        }
    }

    float oacc[8][4];
#pragma unroll
    for (int i = 0; i < 8; i++)
#pragma unroll
        for (int j = 0; j < 4; j++) oacc[i][j] = 0.f;
    float m_s[2] = {-1e30f, -1e30f};
    float l_s[2] = {0.f, 0.f};

    const int rlo = q0 + 16 * w + (lane >> 2);
    const int rhi = rlo + 8;

    for (int kt = 0; kt <= qt; kt++) {
        const int k0 = kt * 64;
        if (kt < qt) { CP_WAIT1(); } else { CP_WAIT0(); }
        __syncthreads();
        if (kt + 2 <= qt) issue_kv((kt + 2) % 3, kt + 2);
        const uint32_t stg = sb + (kt % 3) * 16384;

        // ---- S = Q K^T (2-MMA hi/lo, split passes) ----
        float sacc[8][4];
#pragma unroll
        for (int i = 0; i < 8; i++)
#pragma unroll
            for (int j = 0; j < 4; j++) sacc[i][j] = 0.f;

#pragma unroll
        for (int kt16 = 0; kt16 < 4; kt16++) {
            uint32_t rowb = (uint32_t)(kt16 * 16 + (lane & 7) + (lane >> 4) * 8) * 128;
            uint32_t kf[4][4];
#pragma unroll
            for (int ks = 0; ks < 4; ks++)
                ldm_x4(kf[ks], stg + SWZ(rowb + ks * 32 + ((lane >> 3) & 1) * 16));
            // qh pass
#pragma unroll
            for (int ks = 0; ks < 4; ks++)
#pragma unroll
                for (int sub = 0; sub < 2; sub++)
                    mma16816(sacc[kt16 * 2 + sub], qh[ks],
                             kf[ks][sub * 2], kf[ks][sub * 2 + 1]);
            // ql pass
#pragma unroll
            for (int ks = 0; ks < 4; ks++)
#pragma unroll
                for (int sub = 0; sub < 2; sub++)
                    mma16816(sacc[kt16 * 2 + sub], ql[ks],
                             kf[ks][sub * 2], kf[ks][sub * 2 + 1]);
        }

        // ---- scale + causal mask ----
#pragma unroll
        for (int nt = 0; nt < 8; nt++) {
            int cb0 = k0 + nt * 8 + (lane & 3) * 2;
#pragma unroll
            for (int j = 0; j < 4; j++) sacc[nt][j] *= 0.125f;
            if (kt == qt) {
                if (cb0 > rlo)     sacc[nt][0] = -1e30f;
                if (cb0 + 1 > rlo) sacc[nt][1] = -1e30f;
                if (cb0 > rhi)     sacc[nt][2] = -1e30f;
                if (cb0 + 1 > rhi) sacc[nt][3] = -1e30f;
            }
        }

        // ---- online softmax (register, quad shfl reductions) ----
        float tmax0 = -1e30f, tmax1 = -1e30f;
#pragma unroll
        for (int nt = 0; nt < 8; nt++) {
            tmax0 = fmaxf(tmax0, fmaxf(sacc[nt][0], sacc[nt][1]));
            tmax1 = fmaxf(tmax1, fmaxf(sacc[nt][2], sacc[nt][3]));
        }
        tmax0 = fmaxf(tmax0, __shfl_xor_sync(0xffffffff, tmax0, 1));
        tmax0 = fmaxf(tmax0, __shfl_xor_sync(0xffffffff, tmax0, 2));
        tmax1 = fmaxf(tmax1, __shfl_xor_sync(0xffffffff, tmax1, 1));
        tmax1 = fmaxf(tmax1, __shfl_xor_sync(0xffffffff, tmax1, 2));
        float nm0 = fmaxf(m_s[0], tmax0), nm1 = fmaxf(m_s[1], tmax1);
        float al0 = __expf(m_s[0] - nm0), al1 = __expf(m_s[1] - nm1);
        m_s[0] = nm0; m_s[1] = nm1;

        float rs0 = 0.f, rs1 = 0.f;
#pragma unroll
        for (int nt = 0; nt < 8; nt++) {
            sacc[nt][0] = __expf(sacc[nt][0] - nm0);
            sacc[nt][1] = __expf(sacc[nt][1] - nm0);
            sacc[nt][2] = __expf(sacc[nt][2] - nm1);
            sacc[nt][3] = __expf(sacc[nt][3] - nm1);
            rs0 += sacc[nt][0] + sacc[nt][1];
            rs1 += sacc[nt][2] + sacc[nt][3];
        }
        rs0 += __shfl_xor_sync(0xffffffff, rs0, 1);
        rs0 += __shfl_xor_sync(0xffffffff, rs0, 2);
        rs1 += __shfl_xor_sync(0xffffffff, rs1, 1);
        rs1 += __shfl_xor_sync(0xffffffff, rs1, 2);
        l_s[0] = l_s[0] * al0 + rs0;
        l_s[1] = l_s[1] * al1 + rs1;

#pragma unroll
        for (int nt = 0; nt < 8; nt++) {
            oacc[nt][0] *= al0; oacc[nt][1] *= al0;
            oacc[nt][2] *= al1; oacc[nt][3] *= al1;
        }

        // ---- P fragments (single fp16) ----
        uint32_t ph[4][4];
#pragma unroll
        for (int ks = 0; ks < 4; ks++) {
            const float* t0 = sacc[2 * ks];
            const float* t1 = sacc[2 * ks + 1];
            ph[ks][0] = packh(t0[0], t0[1]);
            ph[ks][1] = packh(t0[2], t0[3]);
            ph[ks][2] = packh(t1[0], t1[1]);
            ph[ks][3] = packh(t1[2], t1[3]);
        }

        // ---- O += P V (single-MMA; V via ldmatrix.trans) ----
#pragma unroll
        for (int ks = 0; ks < 4; ks++) {
            uint32_t rowb = (uint32_t)(ks * 16 + (lane & 7) + ((lane >> 3) & 1) * 8) * 128;
            uint32_t vf[4][4];
#pragma unroll
            for (int np = 0; np < 4; np++)
                ldm_x4_t(vf[np], stg + 8192 + SWZ(rowb + np * 32 + (lane >> 4) * 16));
#pragma unroll
            for (int np = 0; np < 4; np++)
#pragma unroll
                for (int sub = 0; sub < 2; sub++)
                    mma16816(oacc[np * 2 + sub], ph[ks],
                             vf[np][sub * 2], vf[np][sub * 2 + 1]);
        }
        // no trailing barrier: next iteration's barrier protects stage reuse
    }

    // ---- epilogue: y (fp16 hi/lo) into [B,T,C], merging heads ----
    float inv0 = 1.f / l_s[0], inv1 = 1.f / l_s[1];
    int b = bh / H_, h = bh - b * H_;
    const int col = h * 64 + (lane & 3) * 2;
#pragma unroll
    for (int nt = 0; nt < 8; nt++) {
        float y0 = oacc[nt][0] * inv0, y1 = oacc[nt][1] * inv0;
        float y2 = oacc[nt][2] * inv1, y3 = oacc[nt][3] * inv1;
        size_t o0 = ((size_t)b * T_ + rlo) * C_ + col + nt * 8;
        size_t o1 = ((size_t)b * T_ + rhi) * C_ + col + nt * 8;
        float h0 = __half2float(__float2half_rn(y0));
        float h1 = __half2float(__float2half_rn(y1));
        float h2 = __half2float(__float2half_rn(y2));
        float h3 = __half2float(__float2half_rn(y3));
        *(uint32_t*)&g_yh[o0] = packh(y0, y1);
        *(uint32_t*)&g_yl[o0] = packh(y0 - h0, y1 - h1);
        *(uint32_t*)&g_yh[o1] = packh(y2, y3);
        *(uint32_t*)&g_yl[o1] = packh(y2 - h2, y3 - h3);
    }
}

// ---------------------------------------------------------------------------
extern "C" void kernel_launch(void* const* d_in, const int* in_sizes, int n_in,
                              void* d_out, int out_size)
{
    (void)in_sizes; (void)n_in; (void)out_size;
    const float* x      = (const float*)d_in[0];
    const float* W_attn = (const float*)d_in[1];
    const float* b_attn = (const float*)d_in[2];
    const float* W_proj = (const float*)d_in[3];
    const float* b_proj = (const float*)d_in[4];
    float* out = (float*)d_out;

    // conversions
    split_x_kernel<<<(M_ROWS * K_) / 256, 256>>>(x);
    split_tr_kernel<0><<<dim3(QKV_N / 32, K_ / 32), 256>>>(W_attn, K_, QKV_N);
    split_tr_kernel<1><<<dim3(C_ / 32, K_ / 32), 256>>>(W_proj, K_, C_);

    // 1) QKV GEMM (HMMA fp16, lo-pass only on Q columns)
    cudaFuncSetAttribute(hgemm<0>,
                         cudaFuncAttributeMaxDynamicSharedMemorySize, SMH);
    hgemm<0><<<dim3(QKV_N / 128, M_ROWS / 128), 256, SMH>>>(b_attn, nullptr, QKV_N);

    // 2) causal flash attention (HMMA fp16; S 2-MMA, PV 1-MMA)
    cudaFuncSetAttribute(attn_mma_kernel,
                         cudaFuncAttributeMaxDynamicSharedMemorySize, ATT_SMEM);
    attn_mma_kernel<<<dim3(T_ / 64, B_ * H_), 128, ATT_SMEM>>>();

    // 3) output projection (HMMA fp16 2-MMA)
    cudaFuncSetAttribute(hgemm<1>,
                         cudaFuncAttributeMaxDynamicSharedMemorySize, SMH);
    hgemm<1><<<dim3(C_ / 128, M_ROWS / 128), 256, SMH>>>(b_proj, out, C_);
}

// round 12
// speedup vs baseline: 4.9128x; 1.0238x over previous
#include <cuda_runtime.h>
#include <cuda_fp16.h>
#include <cstdint>
#include <cstddef>

// ---------------------------------------------------------------------------
// MultiHeadAttention: y = proj( causal_attention( x @ W_attn + b_attn ) )
// B=8, T=1024, C=768, H=12, hd=64
// HMMA fp16; precision placement (calibrated):
//   - x hi/lo into Q columns; Q hi/lo into S=QK^T.
//   - K/V, P, y, W: single fp16 (errors RMS-combine to ~6.3e-4 < 1e-3).
// ---------------------------------------------------------------------------

#define B_  8
#define T_  1024
#define C_  768
#define H_  12
#define HD_ 64
#define M_ROWS (B_ * T_)          // 8192
#define QKV_N  (3 * C_)           // 2304
#define K_     C_                 // 768

// ---------------- device scratch (no allocation allowed) -------------------
__device__ __half g_qh[B_ * H_ * T_ * HD_], g_ql[B_ * H_ * T_ * HD_];
__device__ __half g_kh[B_ * H_ * T_ * HD_];
__device__ __half g_vh[B_ * H_ * T_ * HD_];

__device__ __half g_xh[M_ROWS * K_], g_xl[M_ROWS * K_];
__device__ __half g_yh[M_ROWS * K_];                      // attn out (single fp16)
__device__ __half g_wah[QKV_N * K_];                      // W_attn^T [N,K]
__device__ __half g_wph[C_ * K_];                         // W_proj^T [N,K]

// ---------------- small PTX helpers (sm_80-level only) ---------------------
__device__ __forceinline__ uint32_t smem_to_u32(const void* p) {
    uint32_t a;
    asm("{ .reg .u64 t; cvta.to.shared.u64 t, %1; cvt.u32.u64 %0, t; }"
        : "=r"(a) : "l"(p));
    return a;
}
__device__ __forceinline__ void ldm_x4(uint32_t* r, uint32_t addr) {
    asm volatile("ldmatrix.sync.aligned.m8n8.x4.shared.b16 {%0,%1,%2,%3}, [%4];"
                 : "=r"(r[0]), "=r"(r[1]), "=r"(r[2]), "=r"(r[3]) : "r"(addr));
}
__device__ __forceinline__ void ldm_x4_t(uint32_t* r, uint32_t addr) {
    asm volatile("ldmatrix.sync.aligned.m8n8.x4.trans.shared.b16 {%0,%1,%2,%3}, [%4];"
                 : "=r"(r[0]), "=r"(r[1]), "=r"(r[2]), "=r"(r[3]) : "r"(addr));
}
__device__ __forceinline__ void mma16816(float* d, const uint32_t* a,
                                         uint32_t b0, uint32_t b1) {
    asm volatile(
        "mma.sync.aligned.m16n8k16.row.col.f32.f16.f16.f32 "
        "{%0,%1,%2,%3}, {%4,%5,%6,%7}, {%8,%9}, {%0,%1,%2,%3};"
        : "+f"(d[0]), "+f"(d[1]), "+f"(d[2]), "+f"(d[3])
        : "r"(a[0]), "r"(a[1]), "r"(a[2]), "r"(a[3]), "r"(b0), "r"(b1));
}
__device__ __forceinline__ uint32_t packh(float lo, float hi) {
    __half2 t = __floats2half2_rn(lo, hi);
    return *(uint32_t*)&t;
}
__device__ __forceinline__ void cp16(uint32_t dst, const void* src) {
    asm volatile("cp.async.cg.shared.global [%0], [%1], 16;"
                 :: "r"(dst), "l"(src));
}
#define CP_COMMIT() asm volatile("cp.async.commit_group;" ::: "memory")
#define CP_WAIT1()  asm volatile("cp.async.wait_group 1;" ::: "memory")
#define CP_WAIT0()  asm volatile("cp.async.wait_group 0;" ::: "memory")
#define SWZ(b) ((b) ^ (((b) >> 3) & 0x70))
// 16x16 subtile layout for a tile with KCH=64 halves per row
#define SUBT64(r, u) ((((r) >> 4) * 4 + ((u) >> 1)) * 512 + ((r) & 15) * 32 + ((u) & 1) * 16)

// ---------------------------------------------------------------------------
// Split / conversion kernels
// ---------------------------------------------------------------------------
__global__ void split_x_kernel(const float* __restrict__ s) {
    int i = blockIdx.x * 256 + threadIdx.x;
    float a = s[i];
    __half h = __float2half_rn(a);
    g_xh[i] = h;
    g_xl[i] = __float2half_rn(a - __half2float(h));
}
// transpose [K,N] fp32 -> [N,K] fp16 (weights single precision)
template <int W>
__global__ void split_tr_kernel(const float* __restrict__ s, int Kd, int Nd) {
    __shared__ float t[32][33];
    int nb = blockIdx.x * 32, kb = blockIdx.y * 32;
    int tx = threadIdx.x & 31, ty = threadIdx.x >> 5;   // 32 x 8
    for (int r = ty; r < 32; r += 8)
        t[r][tx] = s[(size_t)(kb + r) * Nd + nb + tx];
    __syncthreads();
    __half* hi = W ? g_wph : g_wah;
    for (int r = ty; r < 32; r += 8) {
        size_t o = (size_t)(nb + r) * Kd + kb + tx;
        hi[o] = __float2half_rn(t[tx][r]);
    }
}

// ---------------------------------------------------------------------------
// HMMA fp16 GEMM: CTA 128x128, K-chunk 64, 8 warps (4m x 2n), warp tile 32x64.
// 2-stage cp.async, fragment double-buffering.
// A-lo pass only on QKV's Q columns (n0 < C_). Proj (EPI==1) is single-pass
// (y is single fp16 now).
// ---------------------------------------------------------------------------
#define KCH    64
#define NKCH   (K_ / KCH)          // 12
#define HSTAGE 49152               // 16KB Ah + 16KB Al + 16KB B
#define SMH    (2 * HSTAGE)        // 98304

template <int EPI>
__global__ __launch_bounds__(256, 2)
void hgemm(const float* __restrict__ bias, float* __restrict__ Cout, int N)
{
    extern __shared__ char smem[];
    const uint32_t sb = smem_to_u32(smem);
    const int tid  = threadIdx.x;
    const int lane = tid & 31;
    const int w    = tid >> 5;
    const int mw   = w & 3;        // 4 m-warps (32 rows each)
    const int nw   = w >> 2;       // 2 n-warps (64 cols each)
    const int n0 = blockIdx.x * 128;
    const int m0 = blockIdx.y * 128;

    // lo-precision pass needed only for QKV's Q columns
    const bool use_lo = (EPI == 0) && (n0 < C_);

    const __half* Ahi = (EPI == 0) ? g_xh : g_yh;
    const __half* Alo = g_xl;                 // only used when EPI==0
    const __half* Bs  = (EPI == 0) ? g_wah : g_wph;

    float acc[2][8][4];           // [mt 16-row][j n8][quad] = 64 regs
#pragma unroll
    for (int i = 0; i < 2; i++)
#pragma unroll
        for (int j = 0; j < 8; j++)
#pragma unroll
            for (int q = 0; q < 4; q++) acc[i][j][q] = 0.f;

    auto issue = [&](int stage, int c) {
        const int kk = c * KCH;
        const uint32_t sbase = sb + stage * HSTAGE;
        // A hi (its 0-3) + A lo (its 4-7, only if use_lo)
#pragma unroll
        for (int it = 0; it < 8; it++) {
            if (it >= 4 && !use_lo) break;
            int idx = it * 256 + tid;
            int hl = idx >> 10, rem = idx & 1023;
            int r = rem >> 3, u = rem & 7;
            const __half* src = hl ? Alo : Ahi;
            cp16(sbase + hl * 16384 + SUBT64(r, u),
                 src + (size_t)(m0 + r) * K_ + kk + u * 8);
        }
        // B: 128 rows * 8 u = 1024 pieces (4 its)
#pragma unroll
        for (int it = 0; it < 4; it++) {
            int idx = it * 256 + tid;
            int r = idx >> 3, u = idx & 7;
            cp16(sbase + 32768 + SUBT64(r, u),
                 Bs + (size_t)(n0 + r) * K_ + kk + u * 8);
        }
        CP_COMMIT();
    };

    const uint32_t a_in = (lane & 15) * 32 + (lane >> 4) * 16;
    const uint32_t b_in = ((lane & 7) + (lane >> 4) * 8) * 32 + ((lane >> 3) & 1) * 16;

    issue(0, 0);

    for (int c = 0; c < NKCH; c++) {
        CP_WAIT0();
        __syncthreads();
        if (c + 1 < NKCH) issue((c + 1) & 1, c + 1);

        const uint32_t base = sb + (c & 1) * HSTAGE;

        uint32_t bf[2][16], ah[2][8], al[8];

        auto load_bah = [&](int kc, int buf) {
#pragma unroll
            for (int nt = 0; nt < 4; nt++)
                ldm_x4(&bf[buf][nt * 4],
                       base + 32768 + ((nw * 4 + nt) * 4 + kc) * 512 + b_in);
#pragma unroll
            for (int mt = 0; mt < 2; mt++)
                ldm_x4(&ah[buf][mt * 4],
                       base + ((mw * 2 + mt) * 4 + kc) * 512 + a_in);
        };

        load_bah(0, 0);
#pragma unroll
        for (int kc = 0; kc < 4; kc++) {
            const int cur = kc & 1;
            if (use_lo) {
#pragma unroll
                for (int mt = 0; mt < 2; mt++)
                    ldm_x4(&al[mt * 4],
                           base + 16384 + ((mw * 2 + mt) * 4 + kc) * 512 + a_in);
            }
            if (kc < 3) load_bah(kc + 1, cur ^ 1);
#pragma unroll
            for (int mt = 0; mt < 2; mt++)
#pragma unroll
                for (int nt = 0; nt < 4; nt++)
#pragma unroll
                    for (int sub = 0; sub < 2; sub++)
                        mma16816(acc[mt][nt * 2 + sub], &ah[cur][mt * 4],
                                 bf[cur][nt * 4 + sub * 2],
                                 bf[cur][nt * 4 + sub * 2 + 1]);
            if (use_lo) {
#pragma unroll
                for (int mt = 0; mt < 2; mt++)
#pragma unroll
                    for (int nt = 0; nt < 4; nt++)
#pragma unroll
                        for (int sub = 0; sub < 2; sub++)
                            mma16816(acc[mt][nt * 2 + sub], &al[mt * 4],
                                     bf[cur][nt * 4 + sub * 2],
                                     bf[cur][nt * 4 + sub * 2 + 1]);
            }
        }
    }

    // epilogue
    const int row_in = lane >> 2;
    const int col_in = (lane & 3) * 2;
#pragma unroll
    for (int mt = 0; mt < 2; mt++) {
#pragma unroll
        for (int j = 0; j < 8; j++) {
            const int c = n0 + nw * 64 + j * 8 + col_in;
            const float b0v = bias[c], b1v = bias[c + 1];
#pragma unroll
            for (int hf = 0; hf < 2; hf++) {
                const int m = m0 + mw * 32 + mt * 16 + row_in + hf * 8;
                float v0 = acc[mt][j][hf * 2 + 0] + b0v;
                float v1 = acc[mt][j][hf * 2 + 1] + b1v;
                if (EPI == 0) {
                    int which = c / C_;
                    int cc = c - which * C_;
                    int h = cc >> 6, d = cc & 63;
                    int b = m >> 10, tt = m & 1023;
                    size_t o = ((size_t)(b * H_ + h) * T_ + tt) * HD_ + d;
                    if (which == 0) {
                        float h0 = __half2float(__float2half_rn(v0));
                        float h1 = __half2float(__float2half_rn(v1));
                        *(uint32_t*)&g_qh[o] = packh(v0, v1);
                        *(uint32_t*)&g_ql[o] = packh(v0 - h0, v1 - h1);
                    } else if (which == 1) {
                        *(uint32_t*)&g_kh[o] = packh(v0, v1);
                    } else {
                        *(uint32_t*)&g_vh[o] = packh(v0, v1);
                    }
                } else {
                    *(float2*)&Cout[(size_t)m * N + c] = make_float2(v0, v1);
                }
            }
        }
    }
}

// ---------------------------------------------------------------------------
// HMMA flash attention, causal. CTA = 128 Q-rows, 8 warps (256 threads).
// Grid (T/128 = 8, 96). 3-stage cp.async K/V pipeline (16KB/stage: K 8K | V 8K),
// ONE barrier per kt (K tiles are 64 rows; nkt = 2*qt+2).
// Q hi/lo at 48K/64K. S = (Qh+Ql) K^T (2-MMA); O += P V single-fp16 P.
// y written single fp16. smem 80KB -> 2 CTAs/SM.
// ---------------------------------------------------------------------------
#define ATT_SMEM (3 * 16384 + 2 * 16384)   // 81920

__global__ __launch_bounds__(256, 2)
void attn_mma_kernel()
{
    extern __shared__ char smem[];
    const uint32_t sb = smem_to_u32(smem);
    const int tid = threadIdx.x, lane = tid & 31, w = tid >> 5;
    const int qt = blockIdx.x, bh = blockIdx.y;
    const int q0 = qt * 128;
    const size_t base = (size_t)bh * T_ * HD_;
    const int nkt = 2 * qt + 2;

    // 2 tiles (K, V), each 64 rows x 128B = 1024 x 16B pieces -> 4 its @256thr
    auto issue_kv = [&](int stage, int kt) {
        const int k0 = kt * 64;
        const uint32_t sbase = sb + stage * 16384;
#pragma unroll
        for (int it = 0; it < 4; it++) {
            int idx = it * 256 + tid;       // 0..1023
            int tile = idx >> 9;            // 0..1
            int rem = idx & 511;
            int r = rem >> 3, u = rem & 7;  // r 0..63, u 0..7
            const __half* src = tile ? g_vh : g_kh;
            cp16(sbase + tile * 8192 + SWZ(r * 128 + u * 16),
                 src + base + (size_t)(k0 + r) * HD_ + u * 8);
        }
        CP_COMMIT();
    };

    issue_kv(0, 0);
    issue_kv(1, 1);   // nkt >= 2 always

    // ---- load Q tiles (hi/lo, 128 rows) with plain stores ----
#pragma unroll
    for (int half = 0; half < 2; half++) {
        const __half* src = half ? g_ql : g_qh;
        uint32_t dstb = 49152 + half * 16384;
#pragma unroll
        for (int it = 0; it < 4; it++) {
            int idx = it * 256 + tid;       // 0..1023
            int r = idx >> 3, u = idx & 7;  // r 0..127
            uint4 v = *(const uint4*)(src + base + (size_t)(q0 + r) * HD_ + u * 8);
            *(uint4*)(smem + dstb + SWZ(r * 128 + u * 16)) = v;
        }
    }
    __syncthreads();

    uint32_t qh[4][4], ql[4][4];
    {
        uint32_t rowb = (uint32_t)(16 * w + (lane & 7) + ((lane >> 3) & 1) * 8) * 128;
#pragma unroll
        for (int ks = 0; ks < 4; ks++) {
            uint32_t cb = ks * 32 + (lane >> 4) * 16;
            ldm_x4(qh[ks], sb + 49152 + SWZ(rowb + cb));
            ldm_x4(ql[ks], sb + 65536 + SWZ(rowb + cb));
        }
    }

    float oacc[8][4];
#pragma unroll
    for (int i = 0; i < 8; i++)
#pragma unroll
        for (int j = 0; j < 4; j++) oacc[i][j] = 0.f;
    float m_s[2] = {-1e30f, -1e30f};
    float l_s[2] = {0.f, 0.f};

    const int rlo = q0 + 16 * w + (lane >> 2);
    const int rhi = rlo + 8;

    for (int kt = 0; kt < nkt; kt++) {
        const int k0 = kt * 64;
        if (kt + 1 < nkt) { CP_WAIT1(); } else { CP_WAIT0(); }
        __syncthreads();
        if (kt + 2 < nkt) issue_kv((kt + 2) % 3, kt + 2);
        const uint32_t stg = sb + (kt % 3) * 16384;

        // ---- S = Q K^T (2-MMA hi/lo, split passes) ----
        float sacc[8][4];
#pragma unroll
        for (int i = 0; i < 8; i++)
#pragma unroll
            for (int j = 0; j < 4; j++) sacc[i][j] = 0.f;

#pragma unroll
        for (int kt16 = 0; kt16 < 4; kt16++) {
            uint32_t rowb = (uint32_t)(kt16 * 16 + (lane & 7) + (lane >> 4) * 8) * 128;
            uint32_t kf[4][4];
#pragma unroll
            for (int ks = 0; ks < 4; ks++)
                ldm_x4(kf[ks], stg + SWZ(rowb + ks * 32 + ((lane >> 3) & 1) * 16));
#pragma unroll
            for (int ks = 0; ks < 4; ks++)
#pragma unroll
                for (int sub = 0; sub < 2; sub++)
                    mma16816(sacc[kt16 * 2 + sub], qh[ks],
                             kf[ks][sub * 2], kf[ks][sub * 2 + 1]);
#pragma unroll
            for (int ks = 0; ks < 4; ks++)
#pragma unroll
                for (int sub = 0; sub < 2; sub++)
                    mma16816(sacc[kt16 * 2 + sub], ql[ks],
                             kf[ks][sub * 2], kf[ks][sub * 2 + 1]);
        }

        // ---- scale + causal mask (per-warp guard) ----
        const bool need_mask = (k0 + 63 > rlo);
#pragma unroll
        for (int nt = 0; nt < 8; nt++) {
            int cb0 = k0 + nt * 8 + (lane & 3) * 2;
#pragma unroll
            for (int j = 0; j < 4; j++) sacc[nt][j] *= 0.125f;
            if (need_mask) {
                if (cb0 > rlo)     sacc[nt][0] = -1e30f;
                if (cb0 + 1 > rlo) sacc[nt][1] = -1e30f;
                if (cb0 > rhi)     sacc[nt][2] = -1e30f;
                if (cb0 + 1 > rhi) sacc[nt][3] = -1e30f;
            }
        }

        // ---- online softmax (register, quad shfl reductions) ----
        float tmax0 = -1e30f, tmax1 = -1e30f;
#pragma unroll
        for (int nt = 0; nt < 8; nt++) {
            tmax0 = fmaxf(tmax0, fmaxf(sacc[nt][0], sacc[nt][1]));
            tmax1 = fmaxf(tmax1, fmaxf(sacc[nt][2], sacc[nt][3]));
        }
        tmax0 = fmaxf(tmax0, __shfl_xor_sync(0xffffffff, tmax0, 1));
        tmax0 = fmaxf(tmax0, __shfl_xor_sync(0xffffffff, tmax0, 2));
        tmax1 = fmaxf(tmax1, __shfl_xor_sync(0xffffffff, tmax1, 1));
        tmax1 = fmaxf(tmax1, __shfl_xor_sync(0xffffffff, tmax1, 2));
        float nm0 = fmaxf(m_s[0], tmax0), nm1 = fmaxf(m_s[1], tmax1);
        float al0 = __expf(m_s[0] - nm0), al1 = __expf(m_s[1] - nm1);
        m_s[0] = nm0; m_s[1] = nm1;

        float rs0 = 0.f, rs1 = 0.f;
#pragma unroll
        for (int nt = 0; nt < 8; nt++) {
            sacc[nt][0] = __expf(sacc[nt][0] - nm0);
            sacc[nt][1] = __expf(sacc[nt][1] - nm0);
            sacc[nt][2] = __expf(sacc[nt][2] - nm1);
            sacc[nt][3] = __expf(sacc[nt][3] - nm1);
            rs0 += sacc[nt][0] + sacc[nt][1];
            rs1 += sacc[nt][2] + sacc[nt][3];
        }
        rs0 += __shfl_xor_sync(0xffffffff, rs0, 1);
        rs0 += __shfl_xor_sync(0xffffffff, rs0, 2);
        rs1 += __shfl_xor_sync(0xffffffff, rs1, 1);
        rs1 += __shfl_xor_sync(0xffffffff, rs1, 2);
        l_s[0] = l_s[0] * al0 + rs0;
        l_s[1] = l_s[1] * al1 + rs1;

#pragma unroll
        for (int nt = 0; nt < 8; nt++) {
            oacc[nt][0] *= al0; oacc[nt][1] *= al0;
            oacc[nt][2] *= al1; oacc[nt][3] *= al1;
        }

        // ---- P fragments (single fp16) ----
        uint32_t ph[4][4];
#pragma unroll
        for (int ks = 0; ks < 4; ks++) {
            const float* t0 = sacc[2 * ks];
            const float* t1 = sacc[2 * ks + 1];
            ph[ks][0] = packh(t0[0], t0[1]);
            ph[ks][1] = packh(t0[2], t0[3]);
            ph[ks][2] = packh(t1[0], t1[1]);
            ph[ks][3] = packh(t1[2], t1[3]);
        }

        // ---- O += P V (single-MMA; V via ldmatrix.trans) ----
#pragma unroll
        for (int ks = 0; ks < 4; ks++) {
            uint32_t rowb = (uint32_t)(ks * 16 + (lane & 7) + ((lane >> 3) & 1) * 8) * 128;
            uint32_t vf[4][4];
#pragma unroll
            for (int np = 0; np < 4; np++)
                ldm_x4_t(vf[np], stg + 8192 + SWZ(rowb + np * 32 + (lane >> 4) * 16));
#pragma unroll
            for (int np = 0; np < 4; np++)
#pragma unroll
                for (int sub = 0; sub < 2; sub++)
                    mma16816(oacc[np * 2 + sub], ph[ks],
                             vf[np][sub * 2], vf[np][sub * 2 + 1]);
        }
        // no trailing barrier: next iteration's barrier protects stage reuse
    }

    // ---- epilogue: y (single fp16) into [B,T,C], merging heads ----
    float inv0 = 1.f / l_s[0], inv1 = 1.f / l_s[1];
    int b = bh / H_, h = bh - b * H_;
    const int col = h * 64 + (lane & 3) * 2;
#pragma unroll
    for (int nt = 0; nt < 8; nt++) {
        float y0 = oacc[nt][0] * inv0, y1 = oacc[nt][1] * inv0;
        float y2 = oacc[nt][2] * inv1, y3 = oacc[nt][3] * inv1;
        size_t o0 = ((size_t)b * T_ + rlo) * C_ + col + nt * 8;
        size_t o1 = ((size_t)b * T_ + rhi) * C_ + col + nt * 8;
        *(uint32_t*)&g_yh[o0] = packh(y0, y1);
        *(uint32_t*)&g_yh[o1] = packh(y2, y3);
    }
}

// ---------------------------------------------------------------------------
extern "C" void kernel_launch(void* const* d_in, const int* in_sizes, int n_in,
                              void* d_out, int out_size)
{
    (void)in_sizes; (void)n_in; (void)out_size;
    const float* x      = (const float*)d_in[0];
    const float* W_attn = (const float*)d_in[1];
    const float* b_attn = (const float*)d_in[2];
    const float* W_proj = (const float*)d_in[3];
    const float* b_proj = (const float*)d_in[4];
    float* out = (float*)d_out;

    // conversions
    split_x_kernel<<<(M_ROWS * K_) / 256, 256>>>(x);
    split_tr_kernel<0><<<dim3(QKV_N / 32, K_ / 32), 256>>>(W_attn, K_, QKV_N);
    split_tr_kernel<1><<<dim3(C_ / 32, K_ / 32), 256>>>(W_proj, K_, C_);

    // 1) QKV GEMM (HMMA fp16, lo-pass only on Q columns)
    cudaFuncSetAttribute(hgemm<0>,
                         cudaFuncAttributeMaxDynamicSharedMemorySize, SMH);
    hgemm<0><<<dim3(QKV_N / 128, M_ROWS / 128), 256, SMH>>>(b_attn, nullptr, QKV_N);

    // 2) causal flash attention (128-row Q tiles, 8 warps)
    cudaFuncSetAttribute(attn_mma_kernel,
                         cudaFuncAttributeMaxDynamicSharedMemorySize, ATT_SMEM);
    attn_mma_kernel<<<dim3(T_ / 128, B_ * H_), 256, ATT_SMEM>>>();

    // 3) output projection (HMMA fp16, single-pass: y is single fp16)
    cudaFuncSetAttribute(hgemm<1>,
                         cudaFuncAttributeMaxDynamicSharedMemorySize, SMH);
    hgemm<1><<<dim3(C_ / 128, M_ROWS / 128), 256, SMH>>>(b_proj, out, C_);
}

// round 13
// speedup vs baseline: 5.0890x; 1.0359x over previous
#include <cuda_runtime.h>
#include <cuda_fp16.h>
#include <cstdint>
#include <cstddef>

// ---------------------------------------------------------------------------
// MultiHeadAttention: y = proj( causal_attention( x @ W_attn + b_attn ) )
// B=8, T=1024, C=768, H=12, hd=64
// HMMA fp16; precision placement (calibrated ~6e-4):
//   - x hi/lo into Q columns; Q hi/lo into S=QK^T.
//   - K/V, P, y, W: single fp16.
// hgemm v6: 4 warps/CTA, warp tile 64x64 (5-11 MMA per LDSM).
// ---------------------------------------------------------------------------

#define B_  8
#define T_  1024
#define C_  768
#define H_  12
#define HD_ 64
#define M_ROWS (B_ * T_)          // 8192
#define QKV_N  (3 * C_)           // 2304
#define K_     C_                 // 768

// ---------------- device scratch (no allocation allowed) -------------------
__device__ __half g_qh[B_ * H_ * T_ * HD_], g_ql[B_ * H_ * T_ * HD_];
__device__ __half g_kh[B_ * H_ * T_ * HD_];
__device__ __half g_vh[B_ * H_ * T_ * HD_];

__device__ __half g_xh[M_ROWS * K_], g_xl[M_ROWS * K_];
__device__ __half g_yh[M_ROWS * K_];                      // attn out (single fp16)
__device__ __half g_wah[QKV_N * K_];                      // W_attn^T [N,K]
__device__ __half g_wph[C_ * K_];                         // W_proj^T [N,K]

// ---------------- small PTX helpers (sm_80-level only) ---------------------
__device__ __forceinline__ uint32_t smem_to_u32(const void* p) {
    uint32_t a;
    asm("{ .reg .u64 t; cvta.to.shared.u64 t, %1; cvt.u32.u64 %0, t; }"
        : "=r"(a) : "l"(p));
    return a;
}
__device__ __forceinline__ void ldm_x4(uint32_t* r, uint32_t addr) {
    asm volatile("ldmatrix.sync.aligned.m8n8.x4.shared.b16 {%0,%1,%2,%3}, [%4];"
                 : "=r"(r[0]), "=r"(r[1]), "=r"(r[2]), "=r"(r[3]) : "r"(addr));
}
__device__ __forceinline__ void ldm_x4_t(uint32_t* r, uint32_t addr) {
    asm volatile("ldmatrix.sync.aligned.m8n8.x4.trans.shared.b16 {%0,%1,%2,%3}, [%4];"
                 : "=r"(r[0]), "=r"(r[1]), "=r"(r[2]), "=r"(r[3]) : "r"(addr));
}
__device__ __forceinline__ void mma16816(float* d, const uint32_t* a,
                                         uint32_t b0, uint32_t b1) {
    asm volatile(
        "mma.sync.aligned.m16n8k16.row.col.f32.f16.f16.f32 "
        "{%0,%1,%2,%3}, {%4,%5,%6,%7}, {%8,%9}, {%0,%1,%2,%3};"
        : "+f"(d[0]), "+f"(d[1]), "+f"(d[2]), "+f"(d[3])
        : "r"(a[0]), "r"(a[1]), "r"(a[2]), "r"(a[3]), "r"(b0), "r"(b1));
}
__device__ __forceinline__ uint32_t packh(float lo, float hi) {
    __half2 t = __floats2half2_rn(lo, hi);
    return *(uint32_t*)&t;
}
__device__ __forceinline__ void cp16(uint32_t dst, const void* src) {
    asm volatile("cp.async.cg.shared.global [%0], [%1], 16;"
                 :: "r"(dst), "l"(src));
}
#define CP_COMMIT() asm volatile("cp.async.commit_group;" ::: "memory")
#define CP_WAIT1()  asm volatile("cp.async.wait_group 1;" ::: "memory")
#define CP_WAIT0()  asm volatile("cp.async.wait_group 0;" ::: "memory")
#define SWZ(b) ((b) ^ (((b) >> 3) & 0x70))
// 16x16 subtile layout for a tile with KCH=64 halves per row
#define SUBT64(r, u) ((((r) >> 4) * 4 + ((u) >> 1)) * 512 + ((r) & 15) * 32 + ((u) & 1) * 16)

// ---------------------------------------------------------------------------
// Split / conversion kernels
// ---------------------------------------------------------------------------
__global__ void split_x_kernel(const float* __restrict__ s) {
    int i = blockIdx.x * 256 + threadIdx.x;
    float a = s[i];
    __half h = __float2half_rn(a);
    g_xh[i] = h;
    g_xl[i] = __float2half_rn(a - __half2float(h));
}
// transpose [K,N] fp32 -> [N,K] fp16 (weights single precision)
template <int W>
__global__ void split_tr_kernel(const float* __restrict__ s, int Kd, int Nd) {
    __shared__ float t[32][33];
    int nb = blockIdx.x * 32, kb = blockIdx.y * 32;
    int tx = threadIdx.x & 31, ty = threadIdx.x >> 5;   // 32 x 8
    for (int r = ty; r < 32; r += 8)
        t[r][tx] = s[(size_t)(kb + r) * Nd + nb + tx];
    __syncthreads();
    __half* hi = W ? g_wph : g_wah;
    for (int r = ty; r < 32; r += 8) {
        size_t o = (size_t)(nb + r) * Kd + kb + tx;
        hi[o] = __float2half_rn(t[tx][r]);
    }
}

// ---------------------------------------------------------------------------
// HMMA fp16 GEMM v6: CTA 128x128, K-chunk 64, 4 warps (2m x 2n, 128 threads),
// warp tile 64x64 (acc=128 regs). 2-stage cp.async.
// A-lo pass only on QKV's Q columns (n0 < C_); proj single-pass.
// SMEM stage: Ah 16K | Al 16K | B 16K; 2 stages = 96KB/CTA -> 2 CTAs/SM.
// ---------------------------------------------------------------------------
#define KCH    64
#define NKCH   (K_ / KCH)          // 12
#define HSTAGE 49152               // 16KB Ah + 16KB Al + 16KB B
#define SMH    (2 * HSTAGE)        // 98304

template <int EPI>
__global__ __launch_bounds__(128, 2)
void hgemm(const float* __restrict__ bias, float* __restrict__ Cout, int N)
{
    extern __shared__ char smem[];
    const uint32_t sb = smem_to_u32(smem);
    const int tid  = threadIdx.x;
    const int lane = tid & 31;
    const int w    = tid >> 5;
    const int mw   = w & 1;        // 2 m-warps (64 rows each)
    const int nw   = w >> 1;       // 2 n-warps (64 cols each)
    const int n0 = blockIdx.x * 128;
    const int m0 = blockIdx.y * 128;

    const bool use_lo = (EPI == 0) && (n0 < C_);

    const __half* Ahi = (EPI == 0) ? g_xh : g_yh;
    const __half* Alo = g_xl;
    const __half* Bs  = (EPI == 0) ? g_wah : g_wph;

    float acc[4][8][4];           // [mt 16-row][j n8][quad] = 128 regs
#pragma unroll
    for (int i = 0; i < 4; i++)
#pragma unroll
        for (int j = 0; j < 8; j++)
#pragma unroll
            for (int q = 0; q < 4; q++) acc[i][j][q] = 0.f;

    auto issue = [&](int stage, int c) {
        const int kk = c * KCH;
        const uint32_t sbase = sb + stage * HSTAGE;
        // A hi (its 0-7) + A lo (its 8-15, only if use_lo); 128 rows * 8 u
#pragma unroll
        for (int it = 0; it < 16; it++) {
            if (it >= 8 && !use_lo) break;
            int idx = it * 128 + tid;
            int hl = idx >> 10, rem = idx & 1023;
            int r = rem >> 3, u = rem & 7;
            const __half* src = hl ? Alo : Ahi;
            cp16(sbase + hl * 16384 + SUBT64(r, u),
                 src + (size_t)(m0 + r) * K_ + kk + u * 8);
        }
        // B: 128 rows * 8 u = 1024 pieces (8 its)
#pragma unroll
        for (int it = 0; it < 8; it++) {
            int idx = it * 128 + tid;
            int r = idx >> 3, u = idx & 7;
            cp16(sbase + 32768 + SUBT64(r, u),
                 Bs + (size_t)(n0 + r) * K_ + kk + u * 8);
        }
        CP_COMMIT();
    };

    const uint32_t a_in = (lane & 15) * 32 + (lane >> 4) * 16;
    const uint32_t b_in = ((lane & 7) + (lane >> 4) * 8) * 32 + ((lane >> 3) & 1) * 16;

    issue(0, 0);

    for (int c = 0; c < NKCH; c++) {
        CP_WAIT0();
        __syncthreads();
        if (c + 1 < NKCH) issue((c + 1) & 1, c + 1);

        const uint32_t base = sb + (c & 1) * HSTAGE;

#pragma unroll
        for (int kc = 0; kc < 4; kc++) {
            uint32_t bf[16], ah[16], al[16];
            // 4 B + 4 A-hi (+4 A-lo) ldmatrix per kc -> 64-128 MMAs
#pragma unroll
            for (int nt = 0; nt < 4; nt++)
                ldm_x4(&bf[nt * 4],
                       base + 32768 + ((nw * 4 + nt) * 4 + kc) * 512 + b_in);
#pragma unroll
            for (int mt = 0; mt < 4; mt++)
                ldm_x4(&ah[mt * 4],
                       base + ((mw * 4 + mt) * 4 + kc) * 512 + a_in);
            if (use_lo) {
#pragma unroll
                for (int mt = 0; mt < 4; mt++)
                    ldm_x4(&al[mt * 4],
                           base + 16384 + ((mw * 4 + mt) * 4 + kc) * 512 + a_in);
            }
            // hi pass (32 MMAs, all independent accumulators)
#pragma unroll
            for (int mt = 0; mt < 4; mt++)
#pragma unroll
                for (int nt = 0; nt < 4; nt++)
#pragma unroll
                    for (int sub = 0; sub < 2; sub++)
                        mma16816(acc[mt][nt * 2 + sub], &ah[mt * 4],
                                 bf[nt * 4 + sub * 2], bf[nt * 4 + sub * 2 + 1]);
            // lo pass
            if (use_lo) {
#pragma unroll
                for (int mt = 0; mt < 4; mt++)
#pragma unroll
                    for (int nt = 0; nt < 4; nt++)
#pragma unroll
                        for (int sub = 0; sub < 2; sub++)
                            mma16816(acc[mt][nt * 2 + sub], &al[mt * 4],
                                     bf[nt * 4 + sub * 2], bf[nt * 4 + sub * 2 + 1]);
            }
        }
    }

    // epilogue
    const int row_in = lane >> 2;
    const int col_in = (lane & 3) * 2;
#pragma unroll
    for (int mt = 0; mt < 4; mt++) {
#pragma unroll
        for (int j = 0; j < 8; j++) {
            const int c = n0 + nw * 64 + j * 8 + col_in;
            const float b0v = bias[c], b1v = bias[c + 1];
#pragma unroll
            for (int hf = 0; hf < 2; hf++) {
                const int m = m0 + mw * 64 + mt * 16 + row_in + hf * 8;
                float v0 = acc[mt][j][hf * 2 + 0] + b0v;
                float v1 = acc[mt][j][hf * 2 + 1] + b1v;
                if (EPI == 0) {
                    int which = c / C_;
                    int cc = c - which * C_;
                    int h = cc >> 6, d = cc & 63;
                    int b = m >> 10, tt = m & 1023;
                    size_t o = ((size_t)(b * H_ + h) * T_ + tt) * HD_ + d;
                    if (which == 0) {
                        float h0 = __half2float(__float2half_rn(v0));
                        float h1 = __half2float(__float2half_rn(v1));
                        *(uint32_t*)&g_qh[o] = packh(v0, v1);
                        *(uint32_t*)&g_ql[o] = packh(v0 - h0, v1 - h1);
                    } else if (which == 1) {
                        *(uint32_t*)&g_kh[o] = packh(v0, v1);
                    } else {
                        *(uint32_t*)&g_vh[o] = packh(v0, v1);
                    }
                } else {
                    *(float2*)&Cout[(size_t)m * N + c] = make_float2(v0, v1);
                }
            }
        }
    }
}

// ---------------------------------------------------------------------------
// HMMA flash attention, causal. CTA = 128 Q-rows, 8 warps (256 threads).
// Grid (T/128 = 8, 96). 3-stage cp.async K/V pipeline (16KB/stage),
// ONE barrier per kt (K tiles 64 rows; nkt = 2*qt+2).
// Q hi/lo at 48K/64K. S = (Qh+Ql) K^T (2-MMA); O += P V single-fp16 P.
// y written single fp16. smem 80KB -> 2 CTAs/SM.  (round-12 proven)
// ---------------------------------------------------------------------------
#define ATT_SMEM (3 * 16384 + 2 * 16384)   // 81920

__global__ __launch_bounds__(256, 2)
void attn_mma_kernel()
{
    extern __shared__ char smem[];
    const uint32_t sb = smem_to_u32(smem);
    const int tid = threadIdx.x, lane = tid & 31, w = tid >> 5;
    const int qt = blockIdx.x, bh = blockIdx.y;
    const int q0 = qt * 128;
    const size_t base = (size_t)bh * T_ * HD_;
    const int nkt = 2 * qt + 2;

    auto issue_kv = [&](int stage, int kt) {
        const int k0 = kt * 64;
        const uint32_t sbase = sb + stage * 16384;
#pragma unroll
        for (int it = 0; it < 4; it++) {
            int idx = it * 256 + tid;       // 0..1023
            int tile = idx >> 9;            // 0..1
            int rem = idx & 511;
            int r = rem >> 3, u = rem & 7;
            const __half* src = tile ? g_vh : g_kh;
            cp16(sbase + tile * 8192 + SWZ(r * 128 + u * 16),
                 src + base + (size_t)(k0 + r) * HD_ + u * 8);
        }
        CP_COMMIT();
    };

    issue_kv(0, 0);
    issue_kv(1, 1);   // nkt >= 2 always

    // ---- load Q tiles (hi/lo, 128 rows) with plain stores ----
#pragma unroll
    for (int half = 0; half < 2; half++) {
        const __half* src = half ? g_ql : g_qh;
        uint32_t dstb = 49152 + half * 16384;
#pragma unroll
        for (int it = 0; it < 4; it++) {
            int idx = it * 256 + tid;
            int r = idx >> 3, u = idx & 7;
            uint4 v = *(const uint4*)(src + base + (size_t)(q0 + r) * HD_ + u * 8);
            *(uint4*)(smem + dstb + SWZ(r * 128 + u * 16)) = v;
        }
    }
    __syncthreads();

    uint32_t qh[4][4], ql[4][4];
    {
        uint32_t rowb = (uint32_t)(16 * w + (lane & 7) + ((lane >> 3) & 1) * 8) * 128;
#pragma unroll
        for (int ks = 0; ks < 4; ks++) {
            uint32_t cb = ks * 32 + (lane >> 4) * 16;
            ldm_x4(qh[ks], sb + 49152 + SWZ(rowb + cb));
            ldm_x4(ql[ks], sb + 65536 + SWZ(rowb + cb));
        }
    }

    float oacc[8][4];
#pragma unroll
    for (int i = 0; i < 8; i++)
#pragma unroll
        for (int j = 0; j < 4; j++) oacc[i][j] = 0.f;
    float m_s[2] = {-1e30f, -1e30f};
    float l_s[2] = {0.f, 0.f};

    const int rlo = q0 + 16 * w + (lane >> 2);
    const int rhi = rlo + 8;

    for (int kt = 0; kt < nkt; kt++) {
        const int k0 = kt * 64;
        if (kt + 1 < nkt) { CP_WAIT1(); } else { CP_WAIT0(); }
        __syncthreads();
        if (kt + 2 < nkt) issue_kv((kt + 2) % 3, kt + 2);
        const uint32_t stg = sb + (kt % 3) * 16384;

        // ---- S = Q K^T (2-MMA hi/lo, split passes) ----
        float sacc[8][4];
#pragma unroll
        for (int i = 0; i < 8; i++)
#pragma unroll
            for (int j = 0; j < 4; j++) sacc[i][j] = 0.f;

#pragma unroll
        for (int kt16 = 0; kt16 < 4; kt16++) {
            uint32_t rowb = (uint32_t)(kt16 * 16 + (lane & 7) + (lane >> 4) * 8) * 128;
            uint32_t kf[4][4];
#pragma unroll
            for (int ks = 0; ks < 4; ks++)
                ldm_x4(kf[ks], stg + SWZ(rowb + ks * 32 + ((lane >> 3) & 1) * 16));
#pragma unroll
            for (int ks = 0; ks < 4; ks++)
#pragma unroll
                for (int sub = 0; sub < 2; sub++)
                    mma16816(sacc[kt16 * 2 + sub], qh[ks],
                             kf[ks][sub * 2], kf[ks][sub * 2 + 1]);
#pragma unroll
            for (int ks = 0; ks < 4; ks++)
#pragma unroll
                for (int sub = 0; sub < 2; sub++)
                    mma16816(sacc[kt16 * 2 + sub], ql[ks],
                             kf[ks][sub * 2], kf[ks][sub * 2 + 1]);
        }

        // ---- scale + causal mask (per-warp guard) ----
        const bool need_mask = (k0 + 63 > rlo);
#pragma unroll
        for (int nt = 0; nt < 8; nt++) {
            int cb0 = k0 + nt * 8 + (lane & 3) * 2;
#pragma unroll
            for (int j = 0; j < 4; j++) sacc[nt][j] *= 0.125f;
            if (need_mask) {
                if (cb0 > rlo)     sacc[nt][0] = -1e30f;
                if (cb0 + 1 > rlo) sacc[nt][1] = -1e30f;
                if (cb0 > rhi)     sacc[nt][2] = -1e30f;
                if (cb0 + 1 > rhi) sacc[nt][3] = -1e30f;
            }
        }

        // ---- online softmax ----
        float tmax0 = -1e30f, tmax1 = -1e30f;
#pragma unroll
        for (int nt = 0; nt < 8; nt++) {
            tmax0 = fmaxf(tmax0, fmaxf(sacc[nt][0], sacc[nt][1]));
            tmax1 = fmaxf(tmax1, fmaxf(sacc[nt][2], sacc[nt][3]));
        }
        tmax0 = fmaxf(tmax0, __shfl_xor_sync(0xffffffff, tmax0, 1));
        tmax0 = fmaxf(tmax0, __shfl_xor_sync(0xffffffff, tmax0, 2));
        tmax1 = fmaxf(tmax1, __shfl_xor_sync(0xffffffff, tmax1, 1));
        tmax1 = fmaxf(tmax1, __shfl_xor_sync(0xffffffff, tmax1, 2));
        float nm0 = fmaxf(m_s[0], tmax0), nm1 = fmaxf(m_s[1], tmax1);
        float al0 = __expf(m_s[0] - nm0), al1 = __expf(m_s[1] - nm1);
        m_s[0] = nm0; m_s[1] = nm1;

        float rs0 = 0.f, rs1 = 0.f;
#pragma unroll
        for (int nt = 0; nt < 8; nt++) {
            sacc[nt][0] = __expf(sacc[nt][0] - nm0);
            sacc[nt][1] = __expf(sacc[nt][1] - nm0);
            sacc[nt][2] = __expf(sacc[nt][2] - nm1);
            sacc[nt][3] = __expf(sacc[nt][3] - nm1);
            rs0 += sacc[nt][0] + sacc[nt][1];
            rs1 += sacc[nt][2] + sacc[nt][3];
        }
        rs0 += __shfl_xor_sync(0xffffffff, rs0, 1);
        rs0 += __shfl_xor_sync(0xffffffff, rs0, 2);
        rs1 += __shfl_xor_sync(0xffffffff, rs1, 1);
        rs1 += __shfl_xor_sync(0xffffffff, rs1, 2);
        l_s[0] = l_s[0] * al0 + rs0;
        l_s[1] = l_s[1] * al1 + rs1;

#pragma unroll
        for (int nt = 0; nt < 8; nt++) {
            oacc[nt][0] *= al0; oacc[nt][1] *= al0;
            oacc[nt][2] *= al1; oacc[nt][3] *= al1;
        }

        // ---- P fragments (single fp16) ----
        uint32_t ph[4][4];
#pragma unroll
        for (int ks = 0; ks < 4; ks++) {
            const float* t0 = sacc[2 * ks];
            const float* t1 = sacc[2 * ks + 1];
            ph[ks][0] = packh(t0[0], t0[1]);
            ph[ks][1] = packh(t0[2], t0[3]);
            ph[ks][2] = packh(t1[0], t1[1]);
            ph[ks][3] = packh(t1[2], t1[3]);
        }

        // ---- O += P V (single-MMA; V via ldmatrix.trans) ----
#pragma unroll
        for (int ks = 0; ks < 4; ks++) {
            uint32_t rowb = (uint32_t)(ks * 16 + (lane & 7) + ((lane >> 3) & 1) * 8) * 128;
            uint32_t vf[4][4];
#pragma unroll
            for (int np = 0; np < 4; np++)
                ldm_x4_t(vf[np], stg + 8192 + SWZ(rowb + np * 32 + (lane >> 4) * 16));
#pragma unroll
            for (int np = 0; np < 4; np++)
#pragma unroll
                for (int sub = 0; sub < 2; sub++)
                    mma16816(oacc[np * 2 + sub], ph[ks],
                             vf[np][sub * 2], vf[np][sub * 2 + 1]);
        }
    }

    // ---- epilogue: y (single fp16) into [B,T,C], merging heads ----
    float inv0 = 1.f / l_s[0], inv1 = 1.f / l_s[1];
    int b = bh / H_, h = bh - b * H_;
    const int col = h * 64 + (lane & 3) * 2;
#pragma unroll
    for (int nt = 0; nt < 8; nt++) {
        float y0 = oacc[nt][0] * inv0, y1 = oacc[nt][1] * inv0;
        float y2 = oacc[nt][2] * inv1, y3 = oacc[nt][3] * inv1;
        size_t o0 = ((size_t)b * T_ + rlo) * C_ + col + nt * 8;
        size_t o1 = ((size_t)b * T_ + rhi) * C_ + col + nt * 8;
        *(uint32_t*)&g_yh[o0] = packh(y0, y1);
        *(uint32_t*)&g_yh[o1] = packh(y2, y3);
    }
}

// ---------------------------------------------------------------------------
extern "C" void kernel_launch(void* const* d_in, const int* in_sizes, int n_in,
                              void* d_out, int out_size)
{
    (void)in_sizes; (void)n_in; (void)out_size;
    const float* x      = (const float*)d_in[0];
    const float* W_attn = (const float*)d_in[1];
    const float* b_attn = (const float*)d_in[2];
    const float* W_proj = (const float*)d_in[3];
    const float* b_proj = (const float*)d_in[4];
    float* out = (float*)d_out;

    // conversions
    split_x_kernel<<<(M_ROWS * K_) / 256, 256>>>(x);
    split_tr_kernel<0><<<dim3(QKV_N / 32, K_ / 32), 256>>>(W_attn, K_, QKV_N);
    split_tr_kernel<1><<<dim3(C_ / 32, K_ / 32), 256>>>(W_proj, K_, C_);

    // 1) QKV GEMM (HMMA fp16 v6, 64x64 warp tiles)
    cudaFuncSetAttribute(hgemm<0>,
                         cudaFuncAttributeMaxDynamicSharedMemorySize, SMH);
    hgemm<0><<<dim3(QKV_N / 128, M_ROWS / 128), 128, SMH>>>(b_attn, nullptr, QKV_N);

    // 2) causal flash attention (128-row Q tiles, 8 warps)
    cudaFuncSetAttribute(attn_mma_kernel,
                         cudaFuncAttributeMaxDynamicSharedMemorySize, ATT_SMEM);
    attn_mma_kernel<<<dim3(T_ / 128, B_ * H_), 256, ATT_SMEM>>>();

    // 3) output projection (HMMA fp16 v6, single-pass)
    cudaFuncSetAttribute(hgemm<1>,
                         cudaFuncAttributeMaxDynamicSharedMemorySize, SMH);
    hgemm<1><<<dim3(C_ / 128, M_ROWS / 128), 128, SMH>>>(b_proj, out, C_);
}

// round 14
// speedup vs baseline: 5.2504x; 1.0317x over previous
#include <cuda_runtime.h>
#include <cuda_fp16.h>
#include <cstdint>
#include <cstddef>

// ---------------------------------------------------------------------------
// MultiHeadAttention: y = proj( causal_attention( x @ W_attn + b_attn ) )
// B=8, T=1024, C=768, H=12, hd=64
// HMMA fp16; precision placement (calibrated ~6e-4):
//   - x hi/lo into Q columns; Q hi/lo into S=QK^T.
//   - K/V, P, y, W: single fp16.
// hgemm v7: 4 warps/CTA, warp tile 64x64, fragment double-buffering.
// ---------------------------------------------------------------------------

#define B_  8
#define T_  1024
#define C_  768
#define H_  12
#define HD_ 64
#define M_ROWS (B_ * T_)          // 8192
#define QKV_N  (3 * C_)           // 2304
#define K_     C_                 // 768

// ---------------- device scratch (no allocation allowed) -------------------
__device__ __half g_qh[B_ * H_ * T_ * HD_], g_ql[B_ * H_ * T_ * HD_];
__device__ __half g_kh[B_ * H_ * T_ * HD_];
__device__ __half g_vh[B_ * H_ * T_ * HD_];

__device__ __half g_xh[M_ROWS * K_], g_xl[M_ROWS * K_];
__device__ __half g_yh[M_ROWS * K_];                      // attn out (single fp16)
__device__ __half g_wah[QKV_N * K_];                      // W_attn^T [N,K]
__device__ __half g_wph[C_ * K_];                         // W_proj^T [N,K]

// ---------------- small PTX helpers (sm_80-level only) ---------------------
__device__ __forceinline__ uint32_t smem_to_u32(const void* p) {
    uint32_t a;
    asm("{ .reg .u64 t; cvta.to.shared.u64 t, %1; cvt.u32.u64 %0, t; }"
        : "=r"(a) : "l"(p));
    return a;
}
__device__ __forceinline__ void ldm_x4(uint32_t* r, uint32_t addr) {
    asm volatile("ldmatrix.sync.aligned.m8n8.x4.shared.b16 {%0,%1,%2,%3}, [%4];"
                 : "=r"(r[0]), "=r"(r[1]), "=r"(r[2]), "=r"(r[3]) : "r"(addr));
}
__device__ __forceinline__ void ldm_x4_t(uint32_t* r, uint32_t addr) {
    asm volatile("ldmatrix.sync.aligned.m8n8.x4.trans.shared.b16 {%0,%1,%2,%3}, [%4];"
                 : "=r"(r[0]), "=r"(r[1]), "=r"(r[2]), "=r"(r[3]) : "r"(addr));
}
__device__ __forceinline__ void mma16816(float* d, const uint32_t* a,
                                         uint32_t b0, uint32_t b1) {
    asm volatile(
        "mma.sync.aligned.m16n8k16.row.col.f32.f16.f16.f32 "
        "{%0,%1,%2,%3}, {%4,%5,%6,%7}, {%8,%9}, {%0,%1,%2,%3};"
        : "+f"(d[0]), "+f"(d[1]), "+f"(d[2]), "+f"(d[3])
        : "r"(a[0]), "r"(a[1]), "r"(a[2]), "r"(a[3]), "r"(b0), "r"(b1));
}
__device__ __forceinline__ uint32_t packh(float lo, float hi) {
    __half2 t = __floats2half2_rn(lo, hi);
    return *(uint32_t*)&t;
}
__device__ __forceinline__ void cp16(uint32_t dst, const void* src) {
    asm volatile("cp.async.cg.shared.global [%0], [%1], 16;"
                 :: "r"(dst), "l"(src));
}
#define CP_COMMIT() asm volatile("cp.async.commit_group;" ::: "memory")
#define CP_WAIT1()  asm volatile("cp.async.wait_group 1;" ::: "memory")
#define CP_WAIT0()  asm volatile("cp.async.wait_group 0;" ::: "memory")
#define SWZ(b) ((b) ^ (((b) >> 3) & 0x70))
// 16x16 subtile layout for a tile with KCH=64 halves per row
#define SUBT64(r, u) ((((r) >> 4) * 4 + ((u) >> 1)) * 512 + ((r) & 15) * 32 + ((u) & 1) * 16)

// ---------------------------------------------------------------------------
// Split / conversion kernels
// ---------------------------------------------------------------------------
__global__ void split_x_kernel(const float* __restrict__ s) {
    int i = blockIdx.x * 256 + threadIdx.x;
    float a = s[i];
    __half h = __float2half_rn(a);
    g_xh[i] = h;
    g_xl[i] = __float2half_rn(a - __half2float(h));
}
// transpose [K,N] fp32 -> [N,K] fp16 (weights single precision)
template <int W>
__global__ void split_tr_kernel(const float* __restrict__ s, int Kd, int Nd) {
    __shared__ float t[32][33];
    int nb = blockIdx.x * 32, kb = blockIdx.y * 32;
    int tx = threadIdx.x & 31, ty = threadIdx.x >> 5;   // 32 x 8
    for (int r = ty; r < 32; r += 8)
        t[r][tx] = s[(size_t)(kb + r) * Nd + nb + tx];
    __syncthreads();
    __half* hi = W ? g_wph : g_wah;
    for (int r = ty; r < 32; r += 8) {
        size_t o = (size_t)(nb + r) * Kd + kb + tx;
        hi[o] = __float2half_rn(t[tx][r]);
    }
}

// ---------------------------------------------------------------------------
// HMMA fp16 GEMM v7: CTA 128x128, K-chunk 64, 4 warps (2m x 2n, 128 threads),
// warp tile 64x64 (acc=128 regs). 2-stage cp.async + fragment double-buffering
// (B, A-hi db'd across kc; A-lo just-in-time, hidden under hi pass).
// A-lo pass only on QKV's Q columns (n0 < C_); proj single-pass.
// SMEM stage: Ah 16K | Al 16K | B 16K; 2 stages = 96KB/CTA -> 2 CTAs/SM.
// ---------------------------------------------------------------------------
#define KCH    64
#define NKCH   (K_ / KCH)          // 12
#define HSTAGE 49152               // 16KB Ah + 16KB Al + 16KB B
#define SMH    (2 * HSTAGE)        // 98304

template <int EPI>
__global__ __launch_bounds__(128)
void hgemm(const float* __restrict__ bias, float* __restrict__ Cout, int N)
{
    extern __shared__ char smem[];
    const uint32_t sb = smem_to_u32(smem);
    const int tid  = threadIdx.x;
    const int lane = tid & 31;
    const int w    = tid >> 5;
    const int mw   = w & 1;        // 2 m-warps (64 rows each)
    const int nw   = w >> 1;       // 2 n-warps (64 cols each)
    const int n0 = blockIdx.x * 128;
    const int m0 = blockIdx.y * 128;

    const bool use_lo = (EPI == 0) && (n0 < C_);

    const __half* Ahi = (EPI == 0) ? g_xh : g_yh;
    const __half* Alo = g_xl;
    const __half* Bs  = (EPI == 0) ? g_wah : g_wph;

    float acc[4][8][4];           // [mt 16-row][j n8][quad] = 128 regs
#pragma unroll
    for (int i = 0; i < 4; i++)
#pragma unroll
        for (int j = 0; j < 8; j++)
#pragma unroll
            for (int q = 0; q < 4; q++) acc[i][j][q] = 0.f;

    auto issue = [&](int stage, int c) {
        const int kk = c * KCH;
        const uint32_t sbase = sb + stage * HSTAGE;
#pragma unroll
        for (int it = 0; it < 16; it++) {
            if (it >= 8 && !use_lo) break;
            int idx = it * 128 + tid;
            int hl = idx >> 10, rem = idx & 1023;
            int r = rem >> 3, u = rem & 7;
            const __half* src = hl ? Alo : Ahi;
            cp16(sbase + hl * 16384 + SUBT64(r, u),
                 src + (size_t)(m0 + r) * K_ + kk + u * 8);
        }
#pragma unroll
        for (int it = 0; it < 8; it++) {
            int idx = it * 128 + tid;
            int r = idx >> 3, u = idx & 7;
            cp16(sbase + 32768 + SUBT64(r, u),
                 Bs + (size_t)(n0 + r) * K_ + kk + u * 8);
        }
        CP_COMMIT();
    };

    const uint32_t a_in = (lane & 15) * 32 + (lane >> 4) * 16;
    const uint32_t b_in = ((lane & 7) + (lane >> 4) * 8) * 32 + ((lane >> 3) & 1) * 16;

    issue(0, 0);

    for (int c = 0; c < NKCH; c++) {
        CP_WAIT0();
        __syncthreads();
        if (c + 1 < NKCH) issue((c + 1) & 1, c + 1);

        const uint32_t base = sb + (c & 1) * HSTAGE;

        // fragment double-buffering across kc: B + A-hi; A-lo just-in-time
        uint32_t bf[2][16], ah[2][16], al[16];

        auto load_bah = [&](int kc, int buf) {
#pragma unroll
            for (int nt = 0; nt < 4; nt++)
                ldm_x4(&bf[buf][nt * 4],
                       base + 32768 + ((nw * 4 + nt) * 4 + kc) * 512 + b_in);
#pragma unroll
            for (int mt = 0; mt < 4; mt++)
                ldm_x4(&ah[buf][mt * 4],
                       base + ((mw * 4 + mt) * 4 + kc) * 512 + a_in);
        };

        load_bah(0, 0);
#pragma unroll
        for (int kc = 0; kc < 4; kc++) {
            const int cur = kc & 1;
            // A-lo for this kc: issue first, latency hidden under hi pass
            if (use_lo) {
#pragma unroll
                for (int mt = 0; mt < 4; mt++)
                    ldm_x4(&al[mt * 4],
                           base + 16384 + ((mw * 4 + mt) * 4 + kc) * 512 + a_in);
            }
            // prefetch next kc's B + A-hi under this kc's MMAs
            if (kc < 3) load_bah(kc + 1, cur ^ 1);
            // hi pass (32 MMAs, all independent accumulators)
#pragma unroll
            for (int mt = 0; mt < 4; mt++)
#pragma unroll
                for (int nt = 0; nt < 4; nt++)
#pragma unroll
                    for (int sub = 0; sub < 2; sub++)
                        mma16816(acc[mt][nt * 2 + sub], &ah[cur][mt * 4],
                                 bf[cur][nt * 4 + sub * 2],
                                 bf[cur][nt * 4 + sub * 2 + 1]);
            // lo pass
            if (use_lo) {
#pragma unroll
                for (int mt = 0; mt < 4; mt++)
#pragma unroll
                    for (int nt = 0; nt < 4; nt++)
#pragma unroll
                        for (int sub = 0; sub < 2; sub++)
                            mma16816(acc[mt][nt * 2 + sub], &al[mt * 4],
                                     bf[cur][nt * 4 + sub * 2],
                                     bf[cur][nt * 4 + sub * 2 + 1]);
            }
        }
    }

    // epilogue
    const int row_in = lane >> 2;
    const int col_in = (lane & 3) * 2;
#pragma unroll
    for (int mt = 0; mt < 4; mt++) {
#pragma unroll
        for (int j = 0; j < 8; j++) {
            const int c = n0 + nw * 64 + j * 8 + col_in;
            const float b0v = bias[c], b1v = bias[c + 1];
#pragma unroll
            for (int hf = 0; hf < 2; hf++) {
                const int m = m0 + mw * 64 + mt * 16 + row_in + hf * 8;
                float v0 = acc[mt][j][hf * 2 + 0] + b0v;
                float v1 = acc[mt][j][hf * 2 + 1] + b1v;
                if (EPI == 0) {
                    int which = c / C_;
                    int cc = c - which * C_;
                    int h = cc >> 6, d = cc & 63;
                    int b = m >> 10, tt = m & 1023;
                    size_t o = ((size_t)(b * H_ + h) * T_ + tt) * HD_ + d;
                    if (which == 0) {
                        float h0 = __half2float(__float2half_rn(v0));
                        float h1 = __half2float(__float2half_rn(v1));
                        *(uint32_t*)&g_qh[o] = packh(v0, v1);
                        *(uint32_t*)&g_ql[o] = packh(v0 - h0, v1 - h1);
                    } else if (which == 1) {
                        *(uint32_t*)&g_kh[o] = packh(v0, v1);
                    } else {
                        *(uint32_t*)&g_vh[o] = packh(v0, v1);
                    }
                } else {
                    *(float2*)&Cout[(size_t)m * N + c] = make_float2(v0, v1);
                }
            }
        }
    }
}

// ---------------------------------------------------------------------------
// HMMA flash attention, causal. CTA = 128 Q-rows, 8 warps (256 threads).
// Grid (T/128 = 8, 96), qt REVERSED (heavy CTAs launch first -> better tail).
// 3-stage cp.async K/V pipeline (16KB/stage), ONE barrier per kt.
// Q hi/lo at 48K/64K. S = (Qh+Ql) K^T (2-MMA); O += P V single-fp16 P.
// ---------------------------------------------------------------------------
#define ATT_SMEM (3 * 16384 + 2 * 16384)   // 81920

__global__ __launch_bounds__(256, 2)
void attn_mma_kernel()
{
    extern __shared__ char smem[];
    const uint32_t sb = smem_to_u32(smem);
    const int tid = threadIdx.x, lane = tid & 31, w = tid >> 5;
    const int qt = gridDim.x - 1 - blockIdx.x;   // heavy tiles first
    const int bh = blockIdx.y;
    const int q0 = qt * 128;
    const size_t base = (size_t)bh * T_ * HD_;
    const int nkt = 2 * qt + 2;

    auto issue_kv = [&](int stage, int kt) {
        const int k0 = kt * 64;
        const uint32_t sbase = sb + stage * 16384;
#pragma unroll
        for (int it = 0; it < 4; it++) {
            int idx = it * 256 + tid;       // 0..1023
            int tile = idx >> 9;            // 0..1
            int rem = idx & 511;
            int r = rem >> 3, u = rem & 7;
            const __half* src = tile ? g_vh : g_kh;
            cp16(sbase + tile * 8192 + SWZ(r * 128 + u * 16),
                 src + base + (size_t)(k0 + r) * HD_ + u * 8);
        }
        CP_COMMIT();
    };

    issue_kv(0, 0);
    issue_kv(1, 1);   // nkt >= 2 always

    // ---- load Q tiles (hi/lo, 128 rows) with plain stores ----
#pragma unroll
    for (int half = 0; half < 2; half++) {
        const __half* src = half ? g_ql : g_qh;
        uint32_t dstb = 49152 + half * 16384;
#pragma unroll
        for (int it = 0; it < 4; it++) {
            int idx = it * 256 + tid;
            int r = idx >> 3, u = idx & 7;
            uint4 v = *(const uint4*)(src + base + (size_t)(q0 + r) * HD_ + u * 8);
            *(uint4*)(smem + dstb + SWZ(r * 128 + u * 16)) = v;
        }
    }
    __syncthreads();

    uint32_t qh[4][4], ql[4][4];
    {
        uint32_t rowb = (uint32_t)(16 * w + (lane & 7) + ((lane >> 3) & 1) * 8) * 128;
#pragma unroll
        for (int ks = 0; ks < 4; ks++) {
            uint32_t cb = ks * 32 + (lane >> 4) * 16;
            ldm_x4(qh[ks], sb + 49152 + SWZ(rowb + cb));
            ldm_x4(ql[ks], sb + 65536 + SWZ(rowb + cb));
        }
    }

    float oacc[8][4];
#pragma unroll
    for (int i = 0; i < 8; i++)
#pragma unroll
        for (int j = 0; j < 4; j++) oacc[i][j] = 0.f;
    float m_s[2] = {-1e30f, -1e30f};
    float l_s[2] = {0.f, 0.f};

    const int rlo = q0 + 16 * w + (lane >> 2);
    const int rhi = rlo + 8;

    for (int kt = 0; kt < nkt; kt++) {
        const int k0 = kt * 64;
        if (kt + 1 < nkt) { CP_WAIT1(); } else { CP_WAIT0(); }
        __syncthreads();
        if (kt + 2 < nkt) issue_kv((kt + 2) % 3, kt + 2);
        const uint32_t stg = sb + (kt % 3) * 16384;

        // ---- S = Q K^T (2-MMA hi/lo, split passes) ----
        float sacc[8][4];
#pragma unroll
        for (int i = 0; i < 8; i++)
#pragma unroll
            for (int j = 0; j < 4; j++) sacc[i][j] = 0.f;

#pragma unroll
        for (int kt16 = 0; kt16 < 4; kt16++) {
            uint32_t rowb = (uint32_t)(kt16 * 16 + (lane & 7) + (lane >> 4) * 8) * 128;
            uint32_t kf[4][4];
#pragma unroll
            for (int ks = 0; ks < 4; ks++)
                ldm_x4(kf[ks], stg + SWZ(rowb + ks * 32 + ((lane >> 3) & 1) * 16));
#pragma unroll
            for (int ks = 0; ks < 4; ks++)
#pragma unroll
                for (int sub = 0; sub < 2; sub++)
                    mma16816(sacc[kt16 * 2 + sub], qh[ks],
                             kf[ks][sub * 2], kf[ks][sub * 2 + 1]);
#pragma unroll
            for (int ks = 0; ks < 4; ks++)
#pragma unroll
                for (int sub = 0; sub < 2; sub++)
                    mma16816(sacc[kt16 * 2 + sub], ql[ks],
                             kf[ks][sub * 2], kf[ks][sub * 2 + 1]);
        }

        // ---- scale + causal mask (per-warp guard) ----
        const bool need_mask = (k0 + 63 > rlo);
#pragma unroll
        for (int nt = 0; nt < 8; nt++) {
            int cb0 = k0 + nt * 8 + (lane & 3) * 2;
#pragma unroll
            for (int j = 0; j < 4; j++) sacc[nt][j] *= 0.125f;
            if (need_mask) {
                if (cb0 > rlo)     sacc[nt][0] = -1e30f;
                if (cb0 + 1 > rlo) sacc[nt][1] = -1e30f;
                if (cb0 > rhi)     sacc[nt][2] = -1e30f;
                if (cb0 + 1 > rhi) sacc[nt][3] = -1e30f;
            }
        }

        // ---- online softmax ----
        float tmax0 = -1e30f, tmax1 = -1e30f;
#pragma unroll
        for (int nt = 0; nt < 8; nt++) {
            tmax0 = fmaxf(tmax0, fmaxf(sacc[nt][0], sacc[nt][1]));
            tmax1 = fmaxf(tmax1, fmaxf(sacc[nt][2], sacc[nt][3]));
        }
        tmax0 = fmaxf(tmax0, __shfl_xor_sync(0xffffffff, tmax0, 1));
        tmax0 = fmaxf(tmax0, __shfl_xor_sync(0xffffffff, tmax0, 2));
        tmax1 = fmaxf(tmax1, __shfl_xor_sync(0xffffffff, tmax1, 1));
        tmax1 = fmaxf(tmax1, __shfl_xor_sync(0xffffffff, tmax1, 2));
        float nm0 = fmaxf(m_s[0], tmax0), nm1 = fmaxf(m_s[1], tmax1);
        float al0 = __expf(m_s[0] - nm0), al1 = __expf(m_s[1] - nm1);
        m_s[0] = nm0; m_s[1] = nm1;

        float rs0 = 0.f, rs1 = 0.f;
#pragma unroll
        for (int nt = 0; nt < 8; nt++) {
            sacc[nt][0] = __expf(sacc[nt][0] - nm0);
            sacc[nt][1] = __expf(sacc[nt][1] - nm0);
            sacc[nt][2] = __expf(sacc[nt][2] - nm1);
            sacc[nt][3] = __expf(sacc[nt][3] - nm1);
            rs0 += sacc[nt][0] + sacc[nt][1];
            rs1 += sacc[nt][2] + sacc[nt][3];
        }
        rs0 += __shfl_xor_sync(0xffffffff, rs0, 1);
        rs0 += __shfl_xor_sync(0xffffffff, rs0, 2);
        rs1 += __shfl_xor_sync(0xffffffff, rs1, 1);
        rs1 += __shfl_xor_sync(0xffffffff, rs1, 2);
        l_s[0] = l_s[0] * al0 + rs0;
        l_s[1] = l_s[1] * al1 + rs1;

#pragma unroll
        for (int nt = 0; nt < 8; nt++) {
            oacc[nt][0] *= al0; oacc[nt][1] *= al0;
            oacc[nt][2] *= al1; oacc[nt][3] *= al1;
        }

        // ---- P fragments (single fp16) ----
        uint32_t ph[4][4];
#pragma unroll
        for (int ks = 0; ks < 4; ks++) {
            const float* t0 = sacc[2 * ks];
            const float* t1 = sacc[2 * ks + 1];
            ph[ks][0] = packh(t0[0], t0[1]);
            ph[ks][1] = packh(t0[2], t0[3]);
            ph[ks][2] = packh(t1[0], t1[1]);
            ph[ks][3] = packh(t1[2], t1[3]);
        }

        // ---- O += P V (single-MMA; V via ldmatrix.trans) ----
#pragma unroll
        for (int ks = 0; ks < 4; ks++) {
            uint32_t rowb = (uint32_t)(ks * 16 + (lane & 7) + ((lane >> 3) & 1) * 8) * 128;
            uint32_t vf[4][4];
#pragma unroll
            for (int np = 0; np < 4; np++)
                ldm_x4_t(vf[np], stg + 8192 + SWZ(rowb + np * 32 + (lane >> 4) * 16));
#pragma unroll
            for (int np = 0; np < 4; np++)
#pragma unroll
                for (int sub = 0; sub < 2; sub++)
                    mma16816(oacc[np * 2 + sub], ph[ks],
                             vf[np][sub * 2], vf[np][sub * 2 + 1]);
        }
    }

    // ---- epilogue: y (single fp16) into [B,T,C], merging heads ----
    float inv0 = 1.f / l_s[0], inv1 = 1.f / l_s[1];
    int b = bh / H_, h = bh - b * H_;
    const int col = h * 64 + (lane & 3) * 2;
#pragma unroll
    for (int nt = 0; nt < 8; nt++) {
        float y0 = oacc[nt][0] * inv0, y1 = oacc[nt][1] * inv0;
        float y2 = oacc[nt][2] * inv1, y3 = oacc[nt][3] * inv1;
        size_t o0 = ((size_t)b * T_ + rlo) * C_ + col + nt * 8;
        size_t o1 = ((size_t)b * T_ + rhi) * C_ + col + nt * 8;
        *(uint32_t*)&g_yh[o0] = packh(y0, y1);
        *(uint32_t*)&g_yh[o1] = packh(y2, y3);
    }
}

// ---------------------------------------------------------------------------
extern "C" void kernel_launch(void* const* d_in, const int* in_sizes, int n_in,
                              void* d_out, int out_size)
{
    (void)in_sizes; (void)n_in; (void)out_size;
    const float* x      = (const float*)d_in[0];
    const float* W_attn = (const float*)d_in[1];
    const float* b_attn = (const float*)d_in[2];
    const float* W_proj = (const float*)d_in[3];
    const float* b_proj = (const float*)d_in[4];
    float* out = (float*)d_out;

    // conversions
    split_x_kernel<<<(M_ROWS * K_) / 256, 256>>>(x);
    split_tr_kernel<0><<<dim3(QKV_N / 32, K_ / 32), 256>>>(W_attn, K_, QKV_N);
    split_tr_kernel<1><<<dim3(C_ / 32, K_ / 32), 256>>>(W_proj, K_, C_);

    // 1) QKV GEMM (HMMA fp16 v7)
    cudaFuncSetAttribute(hgemm<0>,
                         cudaFuncAttributeMaxDynamicSharedMemorySize, SMH);
    hgemm<0><<<dim3(QKV_N / 128, M_ROWS / 128), 128, SMH>>>(b_attn, nullptr, QKV_N);

    // 2) causal flash attention (128-row Q tiles, heavy-first)
    cudaFuncSetAttribute(attn_mma_kernel,
                         cudaFuncAttributeMaxDynamicSharedMemorySize, ATT_SMEM);
    attn_mma_kernel<<<dim3(T_ / 128, B_ * H_), 256, ATT_SMEM>>>();

    // 3) output projection (HMMA fp16 v7, single-pass)
    cudaFuncSetAttribute(hgemm<1>,
                         cudaFuncAttributeMaxDynamicSharedMemorySize, SMH);
    hgemm<1><<<dim3(C_ / 128, M_ROWS / 128), 128, SMH>>>(b_proj, out, C_);
}